// round 1
// baseline (speedup 1.0000x reference)
#include <cuda_runtime.h>
#include <cuda_bf16.h>

// ---------------------------------------------------------------------------
// DeepSeek MLA block, fp32 baseline.
// B=2, T=1024, D=2048, H=16, NOPE=128, ROPE=64, QKD=192,
// QLORA=1536, KVLORA=512, VHD=128, INTER=8192.
// SOFTSCALE = QKD * -0.5 = -96.0 (literal per reference).
// ---------------------------------------------------------------------------

#define CB 2
#define CT 1024
#define CD 2048
#define CH 16
#define CNOPE 128
#define CROPE 64
#define CQKD 192
#define CQLORA 1536
#define CKVLORA 512
#define CVHD 128
#define CINTER 8192
#define CM (CB*CT)   // 2048 rows

// ------------------------- scratch (device globals) ------------------------
__device__ float g_h   [(long long)CM*CD];
__device__ float g_qa  [(long long)CM*CQLORA];
__device__ float g_q   [(long long)CM*CH*CQKD];
__device__ float g_kva [(long long)CM*(CKVLORA+CROPE)];
__device__ float g_kvn [(long long)CM*CKVLORA];
__device__ float g_kv  [(long long)CM*CH*(CNOPE+CVHD)];
__device__ float g_qf  [(long long)CB*CH*CT*CQKD];
__device__ float g_kf  [(long long)CB*CH*CT*CQKD];
__device__ float g_vT  [(long long)CB*CH*CVHD*CT];
__device__ float g_sc  [(long long)CB*CH*CT*CT];      // scores / attn (128 MB)
__device__ float g_y   [(long long)CB*CH*CT*CVHD];
__device__ float g_y2  [(long long)CM*CD];
__device__ float g_x2  [(long long)CM*CD];
__device__ float g_h2  [(long long)CM*CD];
__device__ float g_gate[(long long)CM*CINTER];
__device__ float g_up  [(long long)CM*CINTER];

// ------------------------- generic batched SGEMM ---------------------------
// C[z][m,n] = alpha * sum_k A[z][m,k] * B[z][n,k]  (+ R[z][m,n] if R)
// A: [M,K] row-major (lda), B: [N,K] row-major (ldb). K % 16 == 0, ld % 4 == 0.
__global__ __launch_bounds__(256) void gemm_abt(
    const float* __restrict__ A, int lda, long long sA,
    const float* __restrict__ B, int ldb, long long sB,
    float* __restrict__ C, int ldc, long long sC,
    const float* __restrict__ R, int ldr, long long sR,
    int M, int N, int K, float alpha)
{
    __shared__ float As[16][128];
    __shared__ float Bs[16][128];
    long long z = blockIdx.z;
    A += z * sA; B += z * sB; C += z * sC;
    if (R) R += z * sR;

    const int bm = blockIdx.y * 128;
    const int bn = blockIdx.x * 128;
    const int tid = threadIdx.x;
    const int ty = tid >> 4, tx = tid & 15;
    const int lrow = tid >> 2;           // 0..63
    const int lcol = (tid & 3) << 2;     // 0,4,8,12

    float acc[8][8];
    #pragma unroll
    for (int i = 0; i < 8; i++)
        #pragma unroll
        for (int j = 0; j < 8; j++) acc[i][j] = 0.f;

    for (int k0 = 0; k0 < K; k0 += 16) {
        #pragma unroll
        for (int r = 0; r < 2; r++) {
            int row = lrow + r * 64;
            int gm = bm + row;
            float4 va = make_float4(0.f,0.f,0.f,0.f);
            if (gm < M) va = *(const float4*)(A + (long long)gm * lda + k0 + lcol);
            As[lcol+0][row] = va.x; As[lcol+1][row] = va.y;
            As[lcol+2][row] = va.z; As[lcol+3][row] = va.w;
            int gn = bn + row;
            float4 vb = make_float4(0.f,0.f,0.f,0.f);
            if (gn < N) vb = *(const float4*)(B + (long long)gn * ldb + k0 + lcol);
            Bs[lcol+0][row] = vb.x; Bs[lcol+1][row] = vb.y;
            Bs[lcol+2][row] = vb.z; Bs[lcol+3][row] = vb.w;
        }
        __syncthreads();
        #pragma unroll
        for (int kk = 0; kk < 16; kk++) {
            float a[8], b[8];
            *(float4*)&a[0] = *(const float4*)&As[kk][ty*4];
            *(float4*)&a[4] = *(const float4*)&As[kk][64 + ty*4];
            *(float4*)&b[0] = *(const float4*)&Bs[kk][tx*4];
            *(float4*)&b[4] = *(const float4*)&Bs[kk][64 + tx*4];
            #pragma unroll
            for (int i = 0; i < 8; i++)
                #pragma unroll
                for (int j = 0; j < 8; j++)
                    acc[i][j] += a[i] * b[j];
        }
        __syncthreads();
    }

    #pragma unroll
    for (int i = 0; i < 8; i++) {
        int gm = bm + ((i < 4) ? (ty*4 + i) : (64 + ty*4 + (i - 4)));
        if (gm >= M) continue;
        #pragma unroll
        for (int j = 0; j < 8; j++) {
            int gn = bn + ((j < 4) ? (tx*4 + j) : (64 + tx*4 + (j - 4)));
            if (gn >= N) continue;
            float v = alpha * acc[i][j];
            if (R) v += R[(long long)gm * ldr + gn];
            C[(long long)gm * ldc + gn] = v;
        }
    }
}

// ------------------------------ RMSNorm -------------------------------------
__global__ __launch_bounds__(256) void rmsnorm_k(
    const float* __restrict__ in, int ldin,
    const float* __restrict__ w,
    float* __restrict__ out, int ldout, int K)
{
    long long row = blockIdx.x;
    const float* ip = in + row * ldin;
    float* op = out + row * ldout;
    float s = 0.f;
    for (int i = threadIdx.x; i < K; i += 256) { float v = ip[i]; s += v * v; }
    __shared__ float red[32];
    #pragma unroll
    for (int o = 16; o > 0; o >>= 1) s += __shfl_xor_sync(0xffffffffu, s, o);
    int warp = threadIdx.x >> 5, lane = threadIdx.x & 31;
    if (lane == 0) red[warp] = s;
    __syncthreads();
    if (warp == 0) {
        float s2 = (lane < 8) ? red[lane] : 0.f;
        #pragma unroll
        for (int o = 4; o > 0; o >>= 1) s2 += __shfl_xor_sync(0xffffffffu, s2, o);
        if (lane == 0) red[0] = s2;
    }
    __syncthreads();
    float scale = rsqrtf(red[0] / (float)K + 1e-6f);
    for (int i = threadIdx.x; i < K; i += 256) op[i] = ip[i] * scale * w[i];
}

// ------------------- RoPE + head packing (qf, kf, vT) -----------------------
__global__ __launch_bounds__(256) void rope_pack_k(
    const float* __restrict__ q,    // [M, H*QKD]
    const float* __restrict__ kv,   // [M, H*256]
    const float* __restrict__ kva,  // [M, 576] (cols 512..575 = k_pe raw)
    const float* __restrict__ fcos, // [T, 32]
    const float* __restrict__ fsin, // [T, 32]
    float* __restrict__ qf,         // [B,H,T,192]
    float* __restrict__ kf,         // [B,H,T,192]
    float* __restrict__ vT)         // [B,H,128,T]
{
    int t = blockIdx.x, b = blockIdx.y;
    long long m = (long long)b * CT + t;
    __shared__ float kpe[CROPE];
    __shared__ float cs[32], sn[32];
    int tid = threadIdx.x;
    if (tid < 32) { cs[tid] = fcos[t*32 + tid]; sn[tid] = fsin[t*32 + tid]; }
    __syncthreads();
    if (tid < 32) {
        float x0 = kva[m*576 + 512 + 2*tid];
        float x1 = kva[m*576 + 512 + 2*tid + 1];
        kpe[2*tid]   = x0*cs[tid] - x1*sn[tid];
        kpe[2*tid+1] = x0*sn[tid] + x1*cs[tid];
    }
    __syncthreads();
    for (int idx = tid; idx < CH*CQKD; idx += 256) {
        int h = idx / CQKD, d = idx % CQKD;
        long long o = (((long long)b*CH + h)*CT + t)*CQKD + d;
        float qv, kvv;
        if (d < CNOPE) {
            qv  = q [m*(CH*CQKD) + h*CQKD + d];
            kvv = kv[m*(CH*256)  + h*256  + d];
        } else {
            int j = d - CNOPE;
            int i2 = j >> 1;
            float x0 = q[m*(CH*CQKD) + h*CQKD + CNOPE + 2*i2];
            float x1 = q[m*(CH*CQKD) + h*CQKD + CNOPE + 2*i2 + 1];
            qv  = (j & 1) ? (x0*sn[i2] + x1*cs[i2]) : (x0*cs[i2] - x1*sn[i2]);
            kvv = kpe[j];
        }
        qf[o] = qv; kf[o] = kvv;
    }
    for (int idx = tid; idx < CH*CVHD; idx += 256) {
        int h = idx >> 7, d = idx & 127;
        vT[(((long long)b*CH + h)*CVHD + d)*CT + t] = kv[m*(CH*256) + h*256 + CNOPE + d];
    }
}

// ------------------------------ Softmax -------------------------------------
__global__ __launch_bounds__(256) void softmax_k(float* __restrict__ s)
{
    long long row = blockIdx.x;
    float* p = s + row * (long long)CT;
    int tid = threadIdx.x;
    int warp = tid >> 5, lane = tid & 31;
    __shared__ float red[32];

    float v[4], mx = -1e30f;
    #pragma unroll
    for (int i = 0; i < 4; i++) { v[i] = p[tid + 256*i]; mx = fmaxf(mx, v[i]); }
    #pragma unroll
    for (int o = 16; o > 0; o >>= 1) mx = fmaxf(mx, __shfl_xor_sync(0xffffffffu, mx, o));
    if (lane == 0) red[warp] = mx;
    __syncthreads();
    if (warp == 0) {
        float m2 = (lane < 8) ? red[lane] : -1e30f;
        #pragma unroll
        for (int o = 4; o > 0; o >>= 1) m2 = fmaxf(m2, __shfl_xor_sync(0xffffffffu, m2, o));
        if (lane == 0) red[0] = m2;
    }
    __syncthreads();
    mx = red[0];
    __syncthreads();

    float sum = 0.f;
    #pragma unroll
    for (int i = 0; i < 4; i++) { v[i] = __expf(v[i] - mx); sum += v[i]; }
    #pragma unroll
    for (int o = 16; o > 0; o >>= 1) sum += __shfl_xor_sync(0xffffffffu, sum, o);
    if (lane == 0) red[warp] = sum;
    __syncthreads();
    if (warp == 0) {
        float s2 = (lane < 8) ? red[lane] : 0.f;
        #pragma unroll
        for (int o = 4; o > 0; o >>= 1) s2 += __shfl_xor_sync(0xffffffffu, s2, o);
        if (lane == 0) red[0] = s2;
    }
    __syncthreads();
    float inv = 1.f / red[0];
    #pragma unroll
    for (int i = 0; i < 4; i++) p[tid + 256*i] = v[i] * inv;
}

// ------------------- permute y [B,H,T,VHD] -> [B*T, H*VHD] ------------------
__global__ __launch_bounds__(256) void permute_y_k(
    const float* __restrict__ y, float* __restrict__ y2)
{
    int t = blockIdx.x, b = blockIdx.y;
    for (int idx = threadIdx.x; idx < CH*CVHD; idx += 256) {
        int h = idx >> 7, d = idx & 127;
        y2[((long long)b*CT + t)*(CH*CVHD) + idx] =
            y[(((long long)b*CH + h)*CT + t)*CVHD + d];
    }
}

// --------------------------- SiLU(gate) * up --------------------------------
__global__ __launch_bounds__(256) void silu_mul_k(
    float* __restrict__ g, const float* __restrict__ u, long long n)
{
    long long i = (long long)blockIdx.x * 256 + threadIdx.x;
    if (i < n) {
        float x = g[i];
        float s = x / (1.f + __expf(-x));
        g[i] = s * u[i];
    }
}

// ------------------------------ launch --------------------------------------
static void gemm(const float* A, int lda, long long sA,
                 const float* B, int ldb, long long sB,
                 float* C, int ldc, long long sC,
                 const float* R, int ldr, long long sR,
                 int M, int N, int K, float alpha, int Z)
{
    dim3 grid((N + 127) / 128, (M + 127) / 128, Z);
    gemm_abt<<<grid, 256>>>(A, lda, sA, B, ldb, sB, C, ldc, sC, R, ldr, sR, M, N, K, alpha);
}

extern "C" void kernel_launch(void* const* d_in, const int* in_sizes, int n_in,
                              void* d_out, int out_size)
{
    const float* x     = (const float*)d_in[0];
    const float* mask  = (const float*)d_in[1];
    const float* fcos  = (const float*)d_in[2];
    const float* fsin  = (const float*)d_in[3];
    const float* anw   = (const float*)d_in[4];
    const float* wq_a  = (const float*)d_in[5];
    const float* qnw   = (const float*)d_in[6];
    const float* wq_b  = (const float*)d_in[7];
    const float* wkv_a = (const float*)d_in[8];
    const float* kvnw  = (const float*)d_in[9];
    const float* wkv_b = (const float*)d_in[10];
    const float* wo    = (const float*)d_in[11];
    const float* fnw   = (const float*)d_in[12];
    const float* w1    = (const float*)d_in[13];
    const float* w2    = (const float*)d_in[14];
    const float* w3    = (const float*)d_in[15];
    float* out = (float*)d_out;

    float *p_h, *p_qa, *p_q, *p_kva, *p_kvn, *p_kv, *p_qf, *p_kf, *p_vT,
          *p_sc, *p_y, *p_y2, *p_x2, *p_h2, *p_gate, *p_up;
    cudaGetSymbolAddress((void**)&p_h,   g_h);
    cudaGetSymbolAddress((void**)&p_qa,  g_qa);
    cudaGetSymbolAddress((void**)&p_q,   g_q);
    cudaGetSymbolAddress((void**)&p_kva, g_kva);
    cudaGetSymbolAddress((void**)&p_kvn, g_kvn);
    cudaGetSymbolAddress((void**)&p_kv,  g_kv);
    cudaGetSymbolAddress((void**)&p_qf,  g_qf);
    cudaGetSymbolAddress((void**)&p_kf,  g_kf);
    cudaGetSymbolAddress((void**)&p_vT,  g_vT);
    cudaGetSymbolAddress((void**)&p_sc,  g_sc);
    cudaGetSymbolAddress((void**)&p_y,   g_y);
    cudaGetSymbolAddress((void**)&p_y2,  g_y2);
    cudaGetSymbolAddress((void**)&p_x2,  g_x2);
    cudaGetSymbolAddress((void**)&p_h2,  g_h2);
    cudaGetSymbolAddress((void**)&p_gate,g_gate);
    cudaGetSymbolAddress((void**)&p_up,  g_up);

    // 1) h = rmsnorm(x)
    rmsnorm_k<<<CM, 256>>>(x, CD, anw, p_h, CD, CD);
    // 2) q_a = h @ wq_a^T
    gemm(p_h, CD, 0, wq_a, CD, 0, p_qa, CQLORA, 0, nullptr, 0, 0, CM, CQLORA, CD, 1.f, 1);
    // 3) q_a = rmsnorm(q_a) (in place)
    rmsnorm_k<<<CM, 256>>>(p_qa, CQLORA, qnw, p_qa, CQLORA, CQLORA);
    // 4) q = q_a @ wq_b^T
    gemm(p_qa, CQLORA, 0, wq_b, CQLORA, 0, p_q, CH*CQKD, 0, nullptr, 0, 0, CM, CH*CQKD, CQLORA, 1.f, 1);
    // 5) kv_all = h @ wkv_a^T
    gemm(p_h, CD, 0, wkv_a, CD, 0, p_kva, CKVLORA + CROPE, 0, nullptr, 0, 0, CM, CKVLORA + CROPE, CD, 1.f, 1);
    // 6) kv_norm = rmsnorm(kv_all[:, :512])
    rmsnorm_k<<<CM, 256>>>(p_kva, CKVLORA + CROPE, kvnw, p_kvn, CKVLORA, CKVLORA);
    // 7) kv = kv_norm @ wkv_b^T
    gemm(p_kvn, CKVLORA, 0, wkv_b, CKVLORA, 0, p_kv, CH*256, 0, nullptr, 0, 0, CM, CH*256, CKVLORA, 1.f, 1);
    // 8) build qf, kf (rope), vT
    rope_pack_k<<<dim3(CT, CB), 256>>>(p_q, p_kv, p_kva, fcos, fsin, p_qf, p_kf, p_vT);
    // 9) scores = -96 * qf @ kf^T + mask   (batched over B*H, mask stride 0)
    gemm(p_qf, CQKD, (long long)CT*CQKD,
         p_kf, CQKD, (long long)CT*CQKD,
         p_sc, CT, (long long)CT*CT,
         mask, CT, 0,
         CT, CT, CQKD, -96.f, CB*CH);
    // 10) softmax rows
    softmax_k<<<CB*CH*CT, 256>>>(p_sc);
    // 11) y = attn @ v   (v as vT [d,t], batched over B*H)
    gemm(p_sc, CT, (long long)CT*CT,
         p_vT, CT, (long long)CVHD*CT,
         p_y, CVHD, (long long)CT*CVHD,
         nullptr, 0, 0,
         CT, CVHD, CT, 1.f, CB*CH);
    // 12) y2 = permute to [B*T, H*VHD]
    permute_y_k<<<dim3(CT, CB), 256>>>(p_y, p_y2);
    // 13) x2 = x + y2 @ wo^T
    gemm(p_y2, CH*CVHD, 0, wo, CH*CVHD, 0, p_x2, CD, 0, x, CD, 0, CM, CD, CH*CVHD, 1.f, 1);
    // 14) h2 = rmsnorm(x2)
    rmsnorm_k<<<CM, 256>>>(p_x2, CD, fnw, p_h2, CD, CD);
    // 15) gate = h2 @ w1^T ; 16) up = h2 @ w3^T
    gemm(p_h2, CD, 0, w1, CD, 0, p_gate, CINTER, 0, nullptr, 0, 0, CM, CINTER, CD, 1.f, 1);
    gemm(p_h2, CD, 0, w3, CD, 0, p_up,   CINTER, 0, nullptr, 0, 0, CM, CINTER, CD, 1.f, 1);
    // 17) gate = silu(gate) * up
    {
        long long n = (long long)CM * CINTER;
        silu_mul_k<<<(unsigned)((n + 255) / 256), 256>>>(p_gate, p_up, n);
    }
    // 18) out = x2 + gate @ w2^T
    gemm(p_gate, CINTER, 0, w2, CINTER, 0, out, CD, 0, p_x2, CD, 0, CM, CD, CINTER, 1.f, 1);
}

// round 3
// speedup vs baseline: 2.9164x; 2.9164x over previous
#include <cuda_runtime.h>
#include <cuda_bf16.h>
#include <cstdint>

// ---------------------------------------------------------------------------
// DeepSeek MLA block on GB300 — mma.sync (HMMA) bf16 split-GEMM version.
// tcgen05 is unavailable (harness PTX targets sm_103, not sm_103a), so all
// GEMMs use warp-level mma.sync.m16n8k16 bf16 with fp32 accum and a 3-term
// Dekker split: C = alpha*(Ah@Bh^T + Ah@Bl^T + Al@Bh^T) [+ R].
// ---------------------------------------------------------------------------

#define CB 2
#define CT 1024
#define CD 2048
#define CH 16
#define CNOPE 128
#define CROPE 64
#define CQKD 192
#define CQLORA 1536
#define CKVLORA 512
#define CVHD 128
#define CINTER 8192
#define CM (CB*CT)

// ------------------------------- PTX helpers -------------------------------
__device__ __forceinline__ uint32_t smem_u32(const void* p) {
    uint32_t a;
    asm("{ .reg .u64 t; cvta.to.shared.u64 t, %1; cvt.u32.u64 %0, t; }" : "=r"(a) : "l"(p));
    return a;
}
#define SW128(o) ((o) ^ (((o) >> 3) & 0x70))

__device__ __forceinline__ void cpa16(uint32_t s, const void* g, int sz) {
    asm volatile("cp.async.cg.shared.global [%0], [%1], 16, %2;"
                 :: "r"(s), "l"(g), "r"(sz));
}
__device__ __forceinline__ void cp_commit() {
    asm volatile("cp.async.commit_group;" ::: "memory");
}
template <int N> __device__ __forceinline__ void cp_wait() {
    asm volatile("cp.async.wait_group %0;" :: "n"(N) : "memory");
}

__device__ __forceinline__ void ldsm_x4(uint32_t* r, uint32_t a) {
    asm volatile("ldmatrix.sync.aligned.m8n8.x4.shared.b16 {%0,%1,%2,%3}, [%4];"
        : "=r"(r[0]), "=r"(r[1]), "=r"(r[2]), "=r"(r[3]) : "r"(a));
}
__device__ __forceinline__ void ldsm_x2(uint32_t* r, uint32_t a) {
    asm volatile("ldmatrix.sync.aligned.m8n8.x2.shared.b16 {%0,%1}, [%2];"
        : "=r"(r[0]), "=r"(r[1]) : "r"(a));
}
__device__ __forceinline__ void mma_bf16(float* d, const uint32_t* a, const uint32_t* b) {
    asm volatile(
        "mma.sync.aligned.m16n8k16.row.col.f32.bf16.bf16.f32 "
        "{%0,%1,%2,%3}, {%4,%5,%6,%7}, {%8,%9}, {%0,%1,%2,%3};"
        : "+f"(d[0]), "+f"(d[1]), "+f"(d[2]), "+f"(d[3])
        : "r"(a[0]), "r"(a[1]), "r"(a[2]), "r"(a[3]), "r"(b[0]), "r"(b[1]));
}

// ------------------------- scratch (device globals) ------------------------
__device__ float g_qa  [(long long)CM*CQLORA];
__device__ float g_q   [(long long)CM*CH*CQKD];
__device__ float g_kva [(long long)CM*(CKVLORA+CROPE)];
__device__ float g_kv  [(long long)CM*CH*(CNOPE+CVHD)];
__device__ float g_sc  [(long long)CB*CH*CT*CT];
__device__ float g_y   [(long long)CB*CH*CT*CVHD];
__device__ float g_x2  [(long long)CM*CD];
__device__ float g_gate[(long long)CM*CINTER];
__device__ float g_up  [(long long)CM*CINTER];

// bf16 hi/lo operand buffers
__device__ __nv_bfloat16 b_hH [(long long)CM*CD],        b_hL [(long long)CM*CD];
__device__ __nv_bfloat16 b_qaH[(long long)CM*CQLORA],    b_qaL[(long long)CM*CQLORA];
__device__ __nv_bfloat16 b_kvnH[(long long)CM*CKVLORA],  b_kvnL[(long long)CM*CKVLORA];
__device__ __nv_bfloat16 b_qfH[(long long)CB*CH*CT*CQKD], b_qfL[(long long)CB*CH*CT*CQKD];
__device__ __nv_bfloat16 b_kfH[(long long)CB*CH*CT*CQKD], b_kfL[(long long)CB*CH*CT*CQKD];
__device__ __nv_bfloat16 b_vTH[(long long)CB*CH*CVHD*CT], b_vTL[(long long)CB*CH*CVHD*CT];
__device__ __nv_bfloat16 b_atH[(long long)CB*CH*CT*CT],  b_atL[(long long)CB*CH*CT*CT];
__device__ __nv_bfloat16 b_y2H[(long long)CM*CD],        b_y2L[(long long)CM*CD];
__device__ __nv_bfloat16 b_h2H[(long long)CM*CD],        b_h2L[(long long)CM*CD];
__device__ __nv_bfloat16 b_gsH[(long long)CM*CINTER],    b_gsL[(long long)CM*CINTER];
// weights
__device__ __nv_bfloat16 b_wqaH[(long long)CQLORA*CD],   b_wqaL[(long long)CQLORA*CD];
__device__ __nv_bfloat16 b_wqbH[(long long)CH*CQKD*CQLORA], b_wqbL[(long long)CH*CQKD*CQLORA];
__device__ __nv_bfloat16 b_wkaH[(long long)(CKVLORA+CROPE)*CD], b_wkaL[(long long)(CKVLORA+CROPE)*CD];
__device__ __nv_bfloat16 b_wkbH[(long long)CH*256*CKVLORA], b_wkbL[(long long)CH*256*CKVLORA];
__device__ __nv_bfloat16 b_woH [(long long)CD*CD],        b_woL [(long long)CD*CD];
__device__ __nv_bfloat16 b_w1H [(long long)CINTER*CD],    b_w1L [(long long)CINTER*CD];
__device__ __nv_bfloat16 b_w2H [(long long)CD*CINTER],    b_w2L [(long long)CD*CINTER];
__device__ __nv_bfloat16 b_w3H [(long long)CINTER*CD],    b_w3L [(long long)CINTER*CD];

// ------------------------------- split helpers -----------------------------
__device__ __forceinline__ void split1(float v, __nv_bfloat16& h, __nv_bfloat16& l) {
    h = __float2bfloat16(v);
    l = __float2bfloat16(v - __bfloat162float(h));
}

__global__ __launch_bounds__(256) void split_k(
    const float4* __restrict__ in, __nv_bfloat162* __restrict__ hi,
    __nv_bfloat162* __restrict__ lo, long long n4)
{
    long long i = (long long)blockIdx.x * 256 + threadIdx.x;
    if (i >= n4) return;
    float4 v = in[i];
    __nv_bfloat16 h0, h1, h2, h3, l0, l1, l2, l3;
    split1(v.x, h0, l0); split1(v.y, h1, l1);
    split1(v.z, h2, l2); split1(v.w, h3, l3);
    hi[2*i]   = __halves2bfloat162(h0, h1);
    hi[2*i+1] = __halves2bfloat162(h2, h3);
    lo[2*i]   = __halves2bfloat162(l0, l1);
    lo[2*i+1] = __halves2bfloat162(l2, l3);
}

// ------------------------------ RMSNorm + split -----------------------------
__global__ __launch_bounds__(256) void rmsnorm_split_k(
    const float* __restrict__ in, int ldin, const float* __restrict__ w,
    __nv_bfloat16* __restrict__ hi, __nv_bfloat16* __restrict__ lo, int K)
{
    long long row = blockIdx.x;
    const float* ip = in + row * ldin;
    float s = 0.f;
    for (int i = threadIdx.x; i < K; i += 256) { float v = ip[i]; s += v * v; }
    __shared__ float red[32];
    #pragma unroll
    for (int o = 16; o > 0; o >>= 1) s += __shfl_xor_sync(0xffffffffu, s, o);
    int warp = threadIdx.x >> 5, lane = threadIdx.x & 31;
    if (lane == 0) red[warp] = s;
    __syncthreads();
    if (warp == 0) {
        float s2 = (lane < 8) ? red[lane] : 0.f;
        #pragma unroll
        for (int o = 4; o > 0; o >>= 1) s2 += __shfl_xor_sync(0xffffffffu, s2, o);
        if (lane == 0) red[0] = s2;
    }
    __syncthreads();
    float scale = rsqrtf(red[0] / (float)K + 1e-6f);
    for (int i = threadIdx.x; i < K; i += 256) {
        float v = ip[i] * scale * w[i];
        __nv_bfloat16 h, l; split1(v, h, l);
        hi[row * (long long)K + i] = h;
        lo[row * (long long)K + i] = l;
    }
}

// ------------------- RoPE + head packing (split outputs) --------------------
__global__ __launch_bounds__(256) void rope_pack_split_k(
    const float* __restrict__ q, const float* __restrict__ kv,
    const float* __restrict__ kva,
    const float* __restrict__ fcos, const float* __restrict__ fsin,
    __nv_bfloat16* __restrict__ qfH, __nv_bfloat16* __restrict__ qfL,
    __nv_bfloat16* __restrict__ kfH, __nv_bfloat16* __restrict__ kfL,
    __nv_bfloat16* __restrict__ vTH, __nv_bfloat16* __restrict__ vTL)
{
    int t = blockIdx.x, b = blockIdx.y;
    long long m = (long long)b * CT + t;
    __shared__ float kpe[CROPE], cs[32], sn[32];
    int tid = threadIdx.x;
    if (tid < 32) { cs[tid] = fcos[t*32 + tid]; sn[tid] = fsin[t*32 + tid]; }
    __syncthreads();
    if (tid < 32) {
        float x0 = kva[m*576 + 512 + 2*tid];
        float x1 = kva[m*576 + 512 + 2*tid + 1];
        kpe[2*tid]   = x0*cs[tid] - x1*sn[tid];
        kpe[2*tid+1] = x0*sn[tid] + x1*cs[tid];
    }
    __syncthreads();
    for (int idx = tid; idx < CH*CQKD; idx += 256) {
        int h = idx / CQKD, d = idx % CQKD;
        long long o = (((long long)b*CH + h)*CT + t)*CQKD + d;
        float qv, kvv;
        if (d < CNOPE) {
            qv  = q [m*(CH*CQKD) + h*CQKD + d];
            kvv = kv[m*(CH*256)  + h*256  + d];
        } else {
            int j = d - CNOPE, i2 = j >> 1;
            float x0 = q[m*(CH*CQKD) + h*CQKD + CNOPE + 2*i2];
            float x1 = q[m*(CH*CQKD) + h*CQKD + CNOPE + 2*i2 + 1];
            qv  = (j & 1) ? (x0*sn[i2] + x1*cs[i2]) : (x0*cs[i2] - x1*sn[i2]);
            kvv = kpe[j];
        }
        __nv_bfloat16 hh, ll;
        split1(qv, hh, ll);  qfH[o] = hh; qfL[o] = ll;
        split1(kvv, hh, ll); kfH[o] = hh; kfL[o] = ll;
    }
    for (int idx = tid; idx < CH*CVHD; idx += 256) {
        int h = idx >> 7, d = idx & 127;
        long long o = (((long long)b*CH + h)*CVHD + d)*CT + t;
        float v = kv[m*(CH*256) + h*256 + CNOPE + d];
        __nv_bfloat16 hh, ll; split1(v, hh, ll);
        vTH[o] = hh; vTL[o] = ll;
    }
}

// ------------------------------ Softmax + split -----------------------------
__global__ __launch_bounds__(256) void softmax_split_k(
    const float* __restrict__ s, __nv_bfloat16* __restrict__ hi,
    __nv_bfloat16* __restrict__ lo)
{
    long long row = blockIdx.x;
    const float4* p = (const float4*)(s + row * (long long)CT);
    int tid = threadIdx.x, warp = tid >> 5, lane = tid & 31;
    __shared__ float red[32];

    float4 v = p[tid];
    float mx = fmaxf(fmaxf(v.x, v.y), fmaxf(v.z, v.w));
    #pragma unroll
    for (int o = 16; o > 0; o >>= 1) mx = fmaxf(mx, __shfl_xor_sync(0xffffffffu, mx, o));
    if (lane == 0) red[warp] = mx;
    __syncthreads();
    if (warp == 0) {
        float m2 = (lane < 8) ? red[lane] : -1e30f;
        #pragma unroll
        for (int o = 4; o > 0; o >>= 1) m2 = fmaxf(m2, __shfl_xor_sync(0xffffffffu, m2, o));
        if (lane == 0) red[0] = m2;
    }
    __syncthreads();
    mx = red[0];
    __syncthreads();

    v.x = __expf(v.x - mx); v.y = __expf(v.y - mx);
    v.z = __expf(v.z - mx); v.w = __expf(v.w - mx);
    float sum = v.x + v.y + v.z + v.w;
    #pragma unroll
    for (int o = 16; o > 0; o >>= 1) sum += __shfl_xor_sync(0xffffffffu, sum, o);
    if (lane == 0) red[warp] = sum;
    __syncthreads();
    if (warp == 0) {
        float s2 = (lane < 8) ? red[lane] : 0.f;
        #pragma unroll
        for (int o = 4; o > 0; o >>= 1) s2 += __shfl_xor_sync(0xffffffffu, s2, o);
        if (lane == 0) red[0] = s2;
    }
    __syncthreads();
    float inv = 1.f / red[0];
    v.x *= inv; v.y *= inv; v.z *= inv; v.w *= inv;

    __nv_bfloat16 h0,h1,h2,h3,l0,l1,l2,l3;
    split1(v.x,h0,l0); split1(v.y,h1,l1); split1(v.z,h2,l2); split1(v.w,h3,l3);
    __nv_bfloat162* H = (__nv_bfloat162*)(hi + row * (long long)CT);
    __nv_bfloat162* L = (__nv_bfloat162*)(lo + row * (long long)CT);
    H[2*tid]   = __halves2bfloat162(h0, h1);
    H[2*tid+1] = __halves2bfloat162(h2, h3);
    L[2*tid]   = __halves2bfloat162(l0, l1);
    L[2*tid+1] = __halves2bfloat162(l2, l3);
}

// ------------------- permute y [B,H,T,VHD] -> split [B*T, H*VHD] ------------
__global__ __launch_bounds__(256) void permute_split_k(
    const float* __restrict__ y, __nv_bfloat16* __restrict__ hi,
    __nv_bfloat16* __restrict__ lo)
{
    int t = blockIdx.x, b = blockIdx.y;
    for (int idx = threadIdx.x; idx < CH*CVHD; idx += 256) {
        int h = idx >> 7, d = idx & 127;
        float v = y[(((long long)b*CH + h)*CT + t)*CVHD + d];
        __nv_bfloat16 hh, ll; split1(v, hh, ll);
        long long o = ((long long)b*CT + t)*(CH*CVHD) + idx;
        hi[o] = hh; lo[o] = ll;
    }
}

// --------------------------- SiLU(gate)*up + split ---------------------------
__global__ __launch_bounds__(256) void silu_mul_split_k(
    const float4* __restrict__ g, const float4* __restrict__ u,
    __nv_bfloat162* __restrict__ hi, __nv_bfloat162* __restrict__ lo, long long n4)
{
    long long i = (long long)blockIdx.x * 256 + threadIdx.x;
    if (i >= n4) return;
    float4 gv = g[i], uv = u[i];
    float r0 = gv.x / (1.f + __expf(-gv.x)) * uv.x;
    float r1 = gv.y / (1.f + __expf(-gv.y)) * uv.y;
    float r2 = gv.z / (1.f + __expf(-gv.z)) * uv.z;
    float r3 = gv.w / (1.f + __expf(-gv.w)) * uv.w;
    __nv_bfloat16 h0,h1,h2,h3,l0,l1,l2,l3;
    split1(r0,h0,l0); split1(r1,h1,l1); split1(r2,h2,l2); split1(r3,h3,l3);
    hi[2*i]   = __halves2bfloat162(h0,h1);
    hi[2*i+1] = __halves2bfloat162(h2,h3);
    lo[2*i]   = __halves2bfloat162(l0,l1);
    lo[2*i+1] = __halves2bfloat162(l2,l3);
}

// ----------------------- HMMA split GEMM (mma.sync) -------------------------
// C[z] = alpha*(Ah@Bh^T + Ah@Bl^T + Al@Bh^T) [+ R[z]]
// A: [M,K] bf16 row-major, B: [N,K] bf16 row-major. K % 64 == 0, M % 128 == 0.
// CTA: 256 threads, tile 128x128, warp tile 64x32, BK=64, 2-stage cp.async.
#define STAGE_BYTES 65536
#define GT_SMEM (2*STAGE_BYTES)

__global__ __launch_bounds__(256, 1) void gemm_tc(
    const __nv_bfloat16* __restrict__ Ah, const __nv_bfloat16* __restrict__ Al,
    int lda, long long sA,
    const __nv_bfloat16* __restrict__ Bh, const __nv_bfloat16* __restrict__ Bl,
    int ldb, long long sB,
    float* __restrict__ C, int ldc, long long sC,
    const float* __restrict__ R, int ldr, long long sR,
    int M, int N, int K, float alpha)
{
    extern __shared__ __align__(1024) char smem[];
    const uint32_t sb0 = smem_u32(smem);
    const int tid = threadIdx.x;
    const int wid = tid >> 5, lane = tid & 31;
    long long z = blockIdx.z;
    Ah += z * sA; Al += z * sA; Bh += z * sB; Bl += z * sB; C += z * sC;
    if (R) R += z * sR;
    const int bm = blockIdx.y * 128, bn = blockIdx.x * 128;
    const int wm = (wid >> 2) * 64, wn = (wid & 3) * 32;

    float acc[4][4][4];
    #pragma unroll
    for (int i = 0; i < 4; i++)
        #pragma unroll
        for (int j = 0; j < 4; j++)
            #pragma unroll
            for (int r = 0; r < 4; r++) acc[i][j][r] = 0.f;

    const int nc = K >> 6;

    // issue one 64-wide K chunk (4 tiles of 128x128B) into a stage
    #define ISSUE(stage, k0) do {                                               \
        uint32_t sbase = sb0 + (stage) * STAGE_BYTES;                           \
        _Pragma("unroll")                                                       \
        for (int it = 0; it < 4; it++) {                                        \
            int e = it * 256 + tid;                                             \
            int r = e >> 3, g = e & 7;                                          \
            uint32_t so = SW128(r * 128 + g * 16);                              \
            int ra = bm + r; int pa = (ra < M) ? 16 : 0; if (!pa) ra = 0;       \
            cpa16(sbase + so,         Ah + (size_t)ra * lda + (k0) + g * 8, pa);\
            cpa16(sbase + 16384 + so, Al + (size_t)ra * lda + (k0) + g * 8, pa);\
            int rb = bn + r; int pb = (rb < N) ? 16 : 0; if (!pb) rb = 0;       \
            cpa16(sbase + 32768 + so, Bh + (size_t)rb * ldb + (k0) + g * 8, pb);\
            cpa16(sbase + 49152 + so, Bl + (size_t)rb * ldb + (k0) + g * 8, pb);\
        }                                                                       \
        cp_commit();                                                            \
    } while (0)

    ISSUE(0, 0);

    const int arow = wm + (lane & 15);
    const int acb  = (lane >> 4) << 4;
    const int brow = wn + (lane & 7);
    const int bcb  = ((lane >> 3) & 1) << 4;

    for (int c = 0; c < nc; c++) {
        if (c + 1 < nc) { ISSUE((c + 1) & 1, (c + 1) << 6); cp_wait<1>(); }
        else            { cp_wait<0>(); }
        __syncthreads();

        uint32_t tAh = sb0 + (c & 1) * STAGE_BYTES;
        uint32_t tAl = tAh + 16384, tBh = tAh + 32768, tBl = tAh + 49152;

        #pragma unroll
        for (int ks = 0; ks < 4; ks++) {
            uint32_t ah[4][4], al[4][4], bh[4][2], bl[4][2];
            #pragma unroll
            for (int ms = 0; ms < 4; ms++) {
                uint32_t off = SW128((arow + ms * 16) * 128 + ks * 32 + acb);
                ldsm_x4(ah[ms], tAh + off);
                ldsm_x4(al[ms], tAl + off);
            }
            #pragma unroll
            for (int ns = 0; ns < 4; ns++) {
                uint32_t off = SW128((brow + ns * 8) * 128 + ks * 32 + bcb);
                ldsm_x2(bh[ns], tBh + off);
                ldsm_x2(bl[ns], tBl + off);
            }
            #pragma unroll
            for (int ms = 0; ms < 4; ms++)
                #pragma unroll
                for (int ns = 0; ns < 4; ns++) {
                    mma_bf16(acc[ms][ns], ah[ms], bh[ns]);
                    mma_bf16(acc[ms][ns], ah[ms], bl[ns]);
                    mma_bf16(acc[ms][ns], al[ms], bh[ns]);
                }
        }
        __syncthreads();
    }

    // epilogue: direct stores from fragments
    const int gid = lane >> 2, tc = lane & 3;
    #pragma unroll
    for (int ms = 0; ms < 4; ms++) {
        #pragma unroll
        for (int ns = 0; ns < 4; ns++) {
            int gr0 = bm + wm + ms * 16 + gid;
            int gc  = bn + wn + ns * 8 + tc * 2;
            if (gc < N) {
                float2 v0;
                v0.x = alpha * acc[ms][ns][0];
                v0.y = alpha * acc[ms][ns][1];
                if (R) { v0.x += R[(size_t)gr0 * ldr + gc]; v0.y += R[(size_t)gr0 * ldr + gc + 1]; }
                *(float2*)&C[(size_t)gr0 * ldc + gc] = v0;
                int gr1 = gr0 + 8;
                float2 v1;
                v1.x = alpha * acc[ms][ns][2];
                v1.y = alpha * acc[ms][ns][3];
                if (R) { v1.x += R[(size_t)gr1 * ldr + gc]; v1.y += R[(size_t)gr1 * ldr + gc + 1]; }
                *(float2*)&C[(size_t)gr1 * ldc + gc] = v1;
            }
        }
    }
}

// ------------------------------ host launch ---------------------------------
static void gemm(const __nv_bfloat16* Ah, const __nv_bfloat16* Al, int lda, long long sA,
                 const __nv_bfloat16* Bh, const __nv_bfloat16* Bl, int ldb, long long sB,
                 float* C, int ldc, long long sC,
                 const float* R, int ldr, long long sR,
                 int M, int N, int K, float alpha, int Z)
{
    dim3 grid((N + 127) / 128, M / 128, Z);
    gemm_tc<<<grid, 256, GT_SMEM>>>(Ah, Al, lda, sA, Bh, Bl, ldb, sB,
                                    C, ldc, sC, R, ldr, sR, M, N, K, alpha);
}

static void split(const float* in, __nv_bfloat16* hi, __nv_bfloat16* lo, long long n)
{
    long long n4 = n >> 2;
    split_k<<<(unsigned)((n4 + 255) / 256), 256>>>(
        (const float4*)in, (__nv_bfloat162*)hi, (__nv_bfloat162*)lo, n4);
}

extern "C" void kernel_launch(void* const* d_in, const int* in_sizes, int n_in,
                              void* d_out, int out_size)
{
    const float* x     = (const float*)d_in[0];
    const float* mask  = (const float*)d_in[1];
    const float* fcos  = (const float*)d_in[2];
    const float* fsin  = (const float*)d_in[3];
    const float* anw   = (const float*)d_in[4];
    const float* wq_a  = (const float*)d_in[5];
    const float* qnw   = (const float*)d_in[6];
    const float* wq_b  = (const float*)d_in[7];
    const float* wkv_a = (const float*)d_in[8];
    const float* kvnw  = (const float*)d_in[9];
    const float* wkv_b = (const float*)d_in[10];
    const float* wo    = (const float*)d_in[11];
    const float* fnw   = (const float*)d_in[12];
    const float* w1    = (const float*)d_in[13];
    const float* w2    = (const float*)d_in[14];
    const float* w3    = (const float*)d_in[15];
    float* out = (float*)d_out;

    cudaFuncSetAttribute(gemm_tc, cudaFuncAttributeMaxDynamicSharedMemorySize, GT_SMEM);

    float *p_qa, *p_q, *p_kva, *p_kv, *p_sc, *p_y, *p_x2, *p_gate, *p_up;
    cudaGetSymbolAddress((void**)&p_qa,  g_qa);
    cudaGetSymbolAddress((void**)&p_q,   g_q);
    cudaGetSymbolAddress((void**)&p_kva, g_kva);
    cudaGetSymbolAddress((void**)&p_kv,  g_kv);
    cudaGetSymbolAddress((void**)&p_sc,  g_sc);
    cudaGetSymbolAddress((void**)&p_y,   g_y);
    cudaGetSymbolAddress((void**)&p_x2,  g_x2);
    cudaGetSymbolAddress((void**)&p_gate,g_gate);
    cudaGetSymbolAddress((void**)&p_up,  g_up);

    __nv_bfloat16 *hH,*hL,*qaH,*qaL,*kvnH,*kvnL,*qfH,*qfL,*kfH,*kfL,*vTH,*vTL,
        *atH,*atL,*y2H,*y2L,*h2H,*h2L,*gsH,*gsL,
        *wqaH,*wqaL,*wqbH,*wqbL,*wkaH,*wkaL,*wkbH,*wkbL,
        *woH,*woL,*w1H,*w1L,*w2H,*w2L,*w3H,*w3L;
    cudaGetSymbolAddress((void**)&hH,  b_hH);  cudaGetSymbolAddress((void**)&hL,  b_hL);
    cudaGetSymbolAddress((void**)&qaH, b_qaH); cudaGetSymbolAddress((void**)&qaL, b_qaL);
    cudaGetSymbolAddress((void**)&kvnH,b_kvnH);cudaGetSymbolAddress((void**)&kvnL,b_kvnL);
    cudaGetSymbolAddress((void**)&qfH, b_qfH); cudaGetSymbolAddress((void**)&qfL, b_qfL);
    cudaGetSymbolAddress((void**)&kfH, b_kfH); cudaGetSymbolAddress((void**)&kfL, b_kfL);
    cudaGetSymbolAddress((void**)&vTH, b_vTH); cudaGetSymbolAddress((void**)&vTL, b_vTL);
    cudaGetSymbolAddress((void**)&atH, b_atH); cudaGetSymbolAddress((void**)&atL, b_atL);
    cudaGetSymbolAddress((void**)&y2H, b_y2H); cudaGetSymbolAddress((void**)&y2L, b_y2L);
    cudaGetSymbolAddress((void**)&h2H, b_h2H); cudaGetSymbolAddress((void**)&h2L, b_h2L);
    cudaGetSymbolAddress((void**)&gsH, b_gsH); cudaGetSymbolAddress((void**)&gsL, b_gsL);
    cudaGetSymbolAddress((void**)&wqaH,b_wqaH);cudaGetSymbolAddress((void**)&wqaL,b_wqaL);
    cudaGetSymbolAddress((void**)&wqbH,b_wqbH);cudaGetSymbolAddress((void**)&wqbL,b_wqbL);
    cudaGetSymbolAddress((void**)&wkaH,b_wkaH);cudaGetSymbolAddress((void**)&wkaL,b_wkaL);
    cudaGetSymbolAddress((void**)&wkbH,b_wkbH);cudaGetSymbolAddress((void**)&wkbL,b_wkbL);
    cudaGetSymbolAddress((void**)&woH, b_woH); cudaGetSymbolAddress((void**)&woL, b_woL);
    cudaGetSymbolAddress((void**)&w1H, b_w1H); cudaGetSymbolAddress((void**)&w1L, b_w1L);
    cudaGetSymbolAddress((void**)&w2H, b_w2H); cudaGetSymbolAddress((void**)&w2L, b_w2L);
    cudaGetSymbolAddress((void**)&w3H, b_w3H); cudaGetSymbolAddress((void**)&w3L, b_w3L);

    // weights -> bf16 hi/lo
    split(wq_a,  wqaH, wqaL, (long long)CQLORA*CD);
    split(wq_b,  wqbH, wqbL, (long long)CH*CQKD*CQLORA);
    split(wkv_a, wkaH, wkaL, (long long)(CKVLORA+CROPE)*CD);
    split(wkv_b, wkbH, wkbL, (long long)CH*256*CKVLORA);
    split(wo,    woH,  woL,  (long long)CD*CD);
    split(w1,    w1H,  w1L,  (long long)CINTER*CD);
    split(w2,    w2H,  w2L,  (long long)CD*CINTER);
    split(w3,    w3H,  w3L,  (long long)CINTER*CD);

    // 1) h = rmsnorm(x) -> hi/lo
    rmsnorm_split_k<<<CM, 256>>>(x, CD, anw, hH, hL, CD);
    // 2) qa = h @ wq_a^T
    gemm(hH, hL, CD, 0, wqaH, wqaL, CD, 0, p_qa, CQLORA, 0,
         nullptr, 0, 0, CM, CQLORA, CD, 1.f, 1);
    // 3) qa_norm -> hi/lo
    rmsnorm_split_k<<<CM, 256>>>(p_qa, CQLORA, qnw, qaH, qaL, CQLORA);
    // 4) q = qa_norm @ wq_b^T
    gemm(qaH, qaL, CQLORA, 0, wqbH, wqbL, CQLORA, 0, p_q, CH*CQKD, 0,
         nullptr, 0, 0, CM, CH*CQKD, CQLORA, 1.f, 1);
    // 5) kva = h @ wkv_a^T
    gemm(hH, hL, CD, 0, wkaH, wkaL, CD, 0, p_kva, CKVLORA+CROPE, 0,
         nullptr, 0, 0, CM, CKVLORA+CROPE, CD, 1.f, 1);
    // 6) kv_norm -> hi/lo
    rmsnorm_split_k<<<CM, 256>>>(p_kva, CKVLORA+CROPE, kvnw, kvnH, kvnL, CKVLORA);
    // 7) kv = kv_norm @ wkv_b^T
    gemm(kvnH, kvnL, CKVLORA, 0, wkbH, wkbL, CKVLORA, 0, p_kv, CH*256, 0,
         nullptr, 0, 0, CM, CH*256, CKVLORA, 1.f, 1);
    // 8) rope + pack -> qf/kf/vT hi/lo
    rope_pack_split_k<<<dim3(CT, CB), 256>>>(p_q, p_kv, p_kva, fcos, fsin,
                                             qfH, qfL, kfH, kfL, vTH, vTL);
    // 9) scores = -96 * qf @ kf^T + mask
    gemm(qfH, qfL, CQKD, (long long)CT*CQKD,
         kfH, kfL, CQKD, (long long)CT*CQKD,
         p_sc, CT, (long long)CT*CT,
         mask, CT, 0, CT, CT, CQKD, -96.f, CB*CH);
    // 10) softmax -> attn hi/lo
    softmax_split_k<<<CB*CH*CT, 256>>>(p_sc, atH, atL);
    // 11) y = attn @ vT
    gemm(atH, atL, CT, (long long)CT*CT,
         vTH, vTL, CT, (long long)CVHD*CT,
         p_y, CVHD, (long long)CT*CVHD,
         nullptr, 0, 0, CT, CVHD, CT, 1.f, CB*CH);
    // 12) permute -> y2 hi/lo
    permute_split_k<<<dim3(CT, CB), 256>>>(p_y, y2H, y2L);
    // 13) x2 = x + y2 @ wo^T
    gemm(y2H, y2L, CH*CVHD, 0, woH, woL, CH*CVHD, 0, p_x2, CD, 0,
         x, CD, 0, CM, CD, CH*CVHD, 1.f, 1);
    // 14) h2 = rmsnorm(x2) -> hi/lo
    rmsnorm_split_k<<<CM, 256>>>(p_x2, CD, fnw, h2H, h2L, CD);
    // 15/16) gate/up
    gemm(h2H, h2L, CD, 0, w1H, w1L, CD, 0, p_gate, CINTER, 0,
         nullptr, 0, 0, CM, CINTER, CD, 1.f, 1);
    gemm(h2H, h2L, CD, 0, w3H, w3L, CD, 0, p_up, CINTER, 0,
         nullptr, 0, 0, CM, CINTER, CD, 1.f, 1);
    // 17) gs = silu(gate)*up -> hi/lo
    {
        long long n4 = ((long long)CM * CINTER) >> 2;
        silu_mul_split_k<<<(unsigned)((n4 + 255) / 256), 256>>>(
            (const float4*)p_gate, (const float4*)p_up,
            (__nv_bfloat162*)gsH, (__nv_bfloat162*)gsL, n4);
    }
    // 18) out = x2 + gs @ w2^T
    gemm(gsH, gsL, CINTER, 0, w2H, w2L, CINTER, 0, out, CD, 0,
         p_x2, CD, 0, CM, CD, CINTER, 1.f, 1);
}

// round 4
// speedup vs baseline: 2.9731x; 1.0195x over previous
#include <cuda_runtime.h>
#include <cuda_bf16.h>
#include <cstdint>

// ---------------------------------------------------------------------------
// DeepSeek MLA block on GB300 — mma.sync bf16 split-GEMM, v2.
// 3-term Dekker split: C = alpha*(Ah@Bh^T + Ah@Bl^T + Al@Bh^T) [+ R].
// v2: 128x256 CTA tile / 64x64 warp tile for large-N GEMMs, causal skipping.
// ---------------------------------------------------------------------------

#define CB 2
#define CT 1024
#define CD 2048
#define CH 16
#define CNOPE 128
#define CROPE 64
#define CQKD 192
#define CQLORA 1536
#define CKVLORA 512
#define CVHD 128
#define CINTER 8192
#define CM (CB*CT)

// ------------------------------- PTX helpers -------------------------------
__device__ __forceinline__ uint32_t smem_u32(const void* p) {
    uint32_t a;
    asm("{ .reg .u64 t; cvta.to.shared.u64 t, %1; cvt.u32.u64 %0, t; }" : "=r"(a) : "l"(p));
    return a;
}
#define SW128(o) ((o) ^ (((o) >> 3) & 0x70))

__device__ __forceinline__ void cpa16(uint32_t s, const void* g, int sz) {
    asm volatile("cp.async.cg.shared.global [%0], [%1], 16, %2;"
                 :: "r"(s), "l"(g), "r"(sz));
}
__device__ __forceinline__ void cp_commit() {
    asm volatile("cp.async.commit_group;" ::: "memory");
}
template <int N> __device__ __forceinline__ void cp_wait() {
    asm volatile("cp.async.wait_group %0;" :: "n"(N) : "memory");
}
__device__ __forceinline__ void ldsm_x4(uint32_t* r, uint32_t a) {
    asm volatile("ldmatrix.sync.aligned.m8n8.x4.shared.b16 {%0,%1,%2,%3}, [%4];"
        : "=r"(r[0]), "=r"(r[1]), "=r"(r[2]), "=r"(r[3]) : "r"(a));
}
__device__ __forceinline__ void ldsm_x2(uint32_t* r, uint32_t a) {
    asm volatile("ldmatrix.sync.aligned.m8n8.x2.shared.b16 {%0,%1}, [%2];"
        : "=r"(r[0]), "=r"(r[1]) : "r"(a));
}
__device__ __forceinline__ void mma_bf16(float* d, const uint32_t* a, const uint32_t* b) {
    asm volatile(
        "mma.sync.aligned.m16n8k16.row.col.f32.bf16.bf16.f32 "
        "{%0,%1,%2,%3}, {%4,%5,%6,%7}, {%8,%9}, {%0,%1,%2,%3};"
        : "+f"(d[0]), "+f"(d[1]), "+f"(d[2]), "+f"(d[3])
        : "r"(a[0]), "r"(a[1]), "r"(a[2]), "r"(a[3]), "r"(b[0]), "r"(b[1]));
}

// ------------------------- scratch (device globals) ------------------------
__device__ float g_qa  [(long long)CM*CQLORA];
__device__ float g_q   [(long long)CM*CH*CQKD];
__device__ float g_kva [(long long)CM*(CKVLORA+CROPE)];
__device__ float g_kv  [(long long)CM*CH*(CNOPE+CVHD)];
__device__ float g_sc  [(long long)CB*CH*CT*CT];
__device__ float g_y   [(long long)CB*CH*CT*CVHD];
__device__ float g_x2  [(long long)CM*CD];
__device__ float g_gate[(long long)CM*CINTER];
__device__ float g_up  [(long long)CM*CINTER];

__device__ __nv_bfloat16 b_hH [(long long)CM*CD],        b_hL [(long long)CM*CD];
__device__ __nv_bfloat16 b_qaH[(long long)CM*CQLORA],    b_qaL[(long long)CM*CQLORA];
__device__ __nv_bfloat16 b_kvnH[(long long)CM*CKVLORA],  b_kvnL[(long long)CM*CKVLORA];
__device__ __nv_bfloat16 b_qfH[(long long)CB*CH*CT*CQKD], b_qfL[(long long)CB*CH*CT*CQKD];
__device__ __nv_bfloat16 b_kfH[(long long)CB*CH*CT*CQKD], b_kfL[(long long)CB*CH*CT*CQKD];
__device__ __nv_bfloat16 b_vTH[(long long)CB*CH*CVHD*CT], b_vTL[(long long)CB*CH*CVHD*CT];
__device__ __nv_bfloat16 b_atH[(long long)CB*CH*CT*CT],  b_atL[(long long)CB*CH*CT*CT];
__device__ __nv_bfloat16 b_y2H[(long long)CM*CD],        b_y2L[(long long)CM*CD];
__device__ __nv_bfloat16 b_h2H[(long long)CM*CD],        b_h2L[(long long)CM*CD];
__device__ __nv_bfloat16 b_gsH[(long long)CM*CINTER],    b_gsL[(long long)CM*CINTER];
__device__ __nv_bfloat16 b_wqaH[(long long)CQLORA*CD],   b_wqaL[(long long)CQLORA*CD];
__device__ __nv_bfloat16 b_wqbH[(long long)CH*CQKD*CQLORA], b_wqbL[(long long)CH*CQKD*CQLORA];
__device__ __nv_bfloat16 b_wkaH[(long long)(CKVLORA+CROPE)*CD], b_wkaL[(long long)(CKVLORA+CROPE)*CD];
__device__ __nv_bfloat16 b_wkbH[(long long)CH*256*CKVLORA], b_wkbL[(long long)CH*256*CKVLORA];
__device__ __nv_bfloat16 b_woH [(long long)CD*CD],        b_woL [(long long)CD*CD];
__device__ __nv_bfloat16 b_w1H [(long long)CINTER*CD],    b_w1L [(long long)CINTER*CD];
__device__ __nv_bfloat16 b_w2H [(long long)CD*CINTER],    b_w2L [(long long)CD*CINTER];
__device__ __nv_bfloat16 b_w3H [(long long)CINTER*CD],    b_w3L [(long long)CINTER*CD];

// ------------------------------- split helpers -----------------------------
__device__ __forceinline__ void split1(float v, __nv_bfloat16& h, __nv_bfloat16& l) {
    h = __float2bfloat16(v);
    l = __float2bfloat16(v - __bfloat162float(h));
}

__global__ __launch_bounds__(256) void split_k(
    const float4* __restrict__ in, __nv_bfloat162* __restrict__ hi,
    __nv_bfloat162* __restrict__ lo, long long n4)
{
    long long i = (long long)blockIdx.x * 256 + threadIdx.x;
    if (i >= n4) return;
    float4 v = in[i];
    __nv_bfloat16 h0, h1, h2, h3, l0, l1, l2, l3;
    split1(v.x, h0, l0); split1(v.y, h1, l1);
    split1(v.z, h2, l2); split1(v.w, h3, l3);
    hi[2*i]   = __halves2bfloat162(h0, h1);
    hi[2*i+1] = __halves2bfloat162(h2, h3);
    lo[2*i]   = __halves2bfloat162(l0, l1);
    lo[2*i+1] = __halves2bfloat162(l2, l3);
}

// ------------------------------ RMSNorm + split -----------------------------
__global__ __launch_bounds__(256) void rmsnorm_split_k(
    const float* __restrict__ in, int ldin, const float* __restrict__ w,
    __nv_bfloat16* __restrict__ hi, __nv_bfloat16* __restrict__ lo, int K)
{
    long long row = blockIdx.x;
    const float* ip = in + row * ldin;
    float s = 0.f;
    for (int i = threadIdx.x; i < K; i += 256) { float v = ip[i]; s += v * v; }
    __shared__ float red[32];
    #pragma unroll
    for (int o = 16; o > 0; o >>= 1) s += __shfl_xor_sync(0xffffffffu, s, o);
    int warp = threadIdx.x >> 5, lane = threadIdx.x & 31;
    if (lane == 0) red[warp] = s;
    __syncthreads();
    if (warp == 0) {
        float s2 = (lane < 8) ? red[lane] : 0.f;
        #pragma unroll
        for (int o = 4; o > 0; o >>= 1) s2 += __shfl_xor_sync(0xffffffffu, s2, o);
        if (lane == 0) red[0] = s2;
    }
    __syncthreads();
    float scale = rsqrtf(red[0] / (float)K + 1e-6f);
    for (int i = threadIdx.x; i < K; i += 256) {
        float v = ip[i] * scale * w[i];
        __nv_bfloat16 h, l; split1(v, h, l);
        hi[row * (long long)K + i] = h;
        lo[row * (long long)K + i] = l;
    }
}

// ------------------- RoPE + head packing (split outputs) --------------------
__global__ __launch_bounds__(256) void rope_pack_split_k(
    const float* __restrict__ q, const float* __restrict__ kv,
    const float* __restrict__ kva,
    const float* __restrict__ fcos, const float* __restrict__ fsin,
    __nv_bfloat16* __restrict__ qfH, __nv_bfloat16* __restrict__ qfL,
    __nv_bfloat16* __restrict__ kfH, __nv_bfloat16* __restrict__ kfL,
    __nv_bfloat16* __restrict__ vTH, __nv_bfloat16* __restrict__ vTL)
{
    int t = blockIdx.x, b = blockIdx.y;
    long long m = (long long)b * CT + t;
    __shared__ float kpe[CROPE], cs[32], sn[32];
    int tid = threadIdx.x;
    if (tid < 32) { cs[tid] = fcos[t*32 + tid]; sn[tid] = fsin[t*32 + tid]; }
    __syncthreads();
    if (tid < 32) {
        float x0 = kva[m*576 + 512 + 2*tid];
        float x1 = kva[m*576 + 512 + 2*tid + 1];
        kpe[2*tid]   = x0*cs[tid] - x1*sn[tid];
        kpe[2*tid+1] = x0*sn[tid] + x1*cs[tid];
    }
    __syncthreads();
    for (int idx = tid; idx < CH*CQKD; idx += 256) {
        int h = idx / CQKD, d = idx % CQKD;
        long long o = (((long long)b*CH + h)*CT + t)*CQKD + d;
        float qv, kvv;
        if (d < CNOPE) {
            qv  = q [m*(CH*CQKD) + h*CQKD + d];
            kvv = kv[m*(CH*256)  + h*256  + d];
        } else {
            int j = d - CNOPE, i2 = j >> 1;
            float x0 = q[m*(CH*CQKD) + h*CQKD + CNOPE + 2*i2];
            float x1 = q[m*(CH*CQKD) + h*CQKD + CNOPE + 2*i2 + 1];
            qv  = (j & 1) ? (x0*sn[i2] + x1*cs[i2]) : (x0*cs[i2] - x1*sn[i2]);
            kvv = kpe[j];
        }
        __nv_bfloat16 hh, ll;
        split1(qv, hh, ll);  qfH[o] = hh; qfL[o] = ll;
        split1(kvv, hh, ll); kfH[o] = hh; kfL[o] = ll;
    }
    for (int idx = tid; idx < CH*CVHD; idx += 256) {
        int h = idx >> 7, d = idx & 127;
        long long o = (((long long)b*CH + h)*CVHD + d)*CT + t;
        float v = kv[m*(CH*256) + h*256 + CNOPE + d];
        __nv_bfloat16 hh, ll; split1(v, hh, ll);
        vTH[o] = hh; vTL[o] = ll;
    }
}

// ------------------------------ Softmax + split -----------------------------
__global__ __launch_bounds__(256) void softmax_split_k(
    const float* __restrict__ s, __nv_bfloat16* __restrict__ hi,
    __nv_bfloat16* __restrict__ lo)
{
    long long row = blockIdx.x;
    const float4* p = (const float4*)(s + row * (long long)CT);
    int tid = threadIdx.x, warp = tid >> 5, lane = tid & 31;
    __shared__ float red[32];

    float4 v = p[tid];
    float mx = fmaxf(fmaxf(v.x, v.y), fmaxf(v.z, v.w));
    #pragma unroll
    for (int o = 16; o > 0; o >>= 1) mx = fmaxf(mx, __shfl_xor_sync(0xffffffffu, mx, o));
    if (lane == 0) red[warp] = mx;
    __syncthreads();
    if (warp == 0) {
        float m2 = (lane < 8) ? red[lane] : -1e30f;
        #pragma unroll
        for (int o = 4; o > 0; o >>= 1) m2 = fmaxf(m2, __shfl_xor_sync(0xffffffffu, m2, o));
        if (lane == 0) red[0] = m2;
    }
    __syncthreads();
    mx = red[0];
    __syncthreads();

    v.x = __expf(v.x - mx); v.y = __expf(v.y - mx);
    v.z = __expf(v.z - mx); v.w = __expf(v.w - mx);
    float sum = v.x + v.y + v.z + v.w;
    #pragma unroll
    for (int o = 16; o > 0; o >>= 1) sum += __shfl_xor_sync(0xffffffffu, sum, o);
    if (lane == 0) red[warp] = sum;
    __syncthreads();
    if (warp == 0) {
        float s2 = (lane < 8) ? red[lane] : 0.f;
        #pragma unroll
        for (int o = 4; o > 0; o >>= 1) s2 += __shfl_xor_sync(0xffffffffu, s2, o);
        if (lane == 0) red[0] = s2;
    }
    __syncthreads();
    float inv = 1.f / red[0];
    v.x *= inv; v.y *= inv; v.z *= inv; v.w *= inv;

    __nv_bfloat16 h0,h1,h2,h3,l0,l1,l2,l3;
    split1(v.x,h0,l0); split1(v.y,h1,l1); split1(v.z,h2,l2); split1(v.w,h3,l3);
    __nv_bfloat162* H = (__nv_bfloat162*)(hi + row * (long long)CT);
    __nv_bfloat162* L = (__nv_bfloat162*)(lo + row * (long long)CT);
    H[2*tid]   = __halves2bfloat162(h0, h1);
    H[2*tid+1] = __halves2bfloat162(h2, h3);
    L[2*tid]   = __halves2bfloat162(l0, l1);
    L[2*tid+1] = __halves2bfloat162(l2, l3);
}

// ------------------- permute y [B,H,T,VHD] -> split [B*T, H*VHD] ------------
__global__ __launch_bounds__(256) void permute_split_k(
    const float* __restrict__ y, __nv_bfloat16* __restrict__ hi,
    __nv_bfloat16* __restrict__ lo)
{
    int t = blockIdx.x, b = blockIdx.y;
    for (int idx = threadIdx.x; idx < CH*CVHD; idx += 256) {
        int h = idx >> 7, d = idx & 127;
        float v = y[(((long long)b*CH + h)*CT + t)*CVHD + d];
        __nv_bfloat16 hh, ll; split1(v, hh, ll);
        long long o = ((long long)b*CT + t)*(CH*CVHD) + idx;
        hi[o] = hh; lo[o] = ll;
    }
}

// --------------------------- SiLU(gate)*up + split ---------------------------
__global__ __launch_bounds__(256) void silu_mul_split_k(
    const float4* __restrict__ g, const float4* __restrict__ u,
    __nv_bfloat162* __restrict__ hi, __nv_bfloat162* __restrict__ lo, long long n4)
{
    long long i = (long long)blockIdx.x * 256 + threadIdx.x;
    if (i >= n4) return;
    float4 gv = g[i], uv = u[i];
    float r0 = gv.x / (1.f + __expf(-gv.x)) * uv.x;
    float r1 = gv.y / (1.f + __expf(-gv.y)) * uv.y;
    float r2 = gv.z / (1.f + __expf(-gv.z)) * uv.z;
    float r3 = gv.w / (1.f + __expf(-gv.w)) * uv.w;
    __nv_bfloat16 h0,h1,h2,h3,l0,l1,l2,l3;
    split1(r0,h0,l0); split1(r1,h1,l1); split1(r2,h2,l2); split1(r3,h3,l3);
    hi[2*i]   = __halves2bfloat162(h0,h1);
    hi[2*i+1] = __halves2bfloat162(h2,h3);
    lo[2*i]   = __halves2bfloat162(l0,l1);
    lo[2*i+1] = __halves2bfloat162(l2,l3);
}

// ==================== GEMM v1: 128x128 tile, warp 64x32 =====================
// causal: 0=none, 2=truncate K at bm+128 (A has zero cols beyond row index)
#define STAGE1 65536
#define GT1_SMEM (2*STAGE1)

__global__ __launch_bounds__(256, 1) void gemm_tc128(
    const __nv_bfloat16* __restrict__ Ah, const __nv_bfloat16* __restrict__ Al,
    int lda, long long sA,
    const __nv_bfloat16* __restrict__ Bh, const __nv_bfloat16* __restrict__ Bl,
    int ldb, long long sB,
    float* __restrict__ C, int ldc, long long sC,
    const float* __restrict__ R, int ldr, long long sR,
    int M, int N, int K, float alpha, int causal)
{
    extern __shared__ __align__(1024) char smem[];
    const uint32_t sb0 = smem_u32(smem);
    const int tid = threadIdx.x;
    const int wid = tid >> 5, lane = tid & 31;
    long long z = blockIdx.z;
    Ah += z * sA; Al += z * sA; Bh += z * sB; Bl += z * sB; C += z * sC;
    if (R) R += z * sR;
    const int bm = blockIdx.y * 128, bn = blockIdx.x * 128;
    const int wm = (wid >> 2) * 64, wn = (wid & 3) * 32;

    float acc[4][4][4];
    #pragma unroll
    for (int i = 0; i < 4; i++)
        #pragma unroll
        for (int j = 0; j < 4; j++)
            #pragma unroll
            for (int r = 0; r < 4; r++) acc[i][j][r] = 0.f;

    int nc = K >> 6;
    if (causal == 2) { int lim = (bm + 128 + 63) >> 6; if (lim < nc) nc = lim; }

    #define ISSUE1(stage, k0) do {                                              \
        uint32_t sbase = sb0 + (stage) * STAGE1;                                \
        _Pragma("unroll")                                                       \
        for (int it = 0; it < 4; it++) {                                        \
            int e = it * 256 + tid;                                             \
            int r = e >> 3, g = e & 7;                                          \
            uint32_t so = SW128(r * 128 + g * 16);                              \
            int ra = bm + r; int pa = (ra < M) ? 16 : 0; if (!pa) ra = 0;       \
            cpa16(sbase + so,         Ah + (size_t)ra * lda + (k0) + g * 8, pa);\
            cpa16(sbase + 16384 + so, Al + (size_t)ra * lda + (k0) + g * 8, pa);\
            int rb = bn + r; int pb = (rb < N) ? 16 : 0; if (!pb) rb = 0;       \
            cpa16(sbase + 32768 + so, Bh + (size_t)rb * ldb + (k0) + g * 8, pb);\
            cpa16(sbase + 49152 + so, Bl + (size_t)rb * ldb + (k0) + g * 8, pb);\
        }                                                                       \
        cp_commit();                                                            \
    } while (0)

    ISSUE1(0, 0);

    const int arow = wm + (lane & 15);
    const int acb  = (lane >> 4) << 4;
    const int brow = wn + (lane & 7);
    const int bcb  = ((lane >> 3) & 1) << 4;

    for (int c = 0; c < nc; c++) {
        if (c + 1 < nc) { ISSUE1((c + 1) & 1, (c + 1) << 6); cp_wait<1>(); }
        else            { cp_wait<0>(); }
        __syncthreads();

        uint32_t tAh = sb0 + (c & 1) * STAGE1;
        uint32_t tAl = tAh + 16384, tBh = tAh + 32768, tBl = tAh + 49152;

        #pragma unroll
        for (int ks = 0; ks < 4; ks++) {
            uint32_t ah[4][4], al[4][4], bh[4][2], bl[4][2];
            #pragma unroll
            for (int ms = 0; ms < 4; ms++) {
                uint32_t off = SW128((arow + ms * 16) * 128 + ks * 32 + acb);
                ldsm_x4(ah[ms], tAh + off);
                ldsm_x4(al[ms], tAl + off);
            }
            #pragma unroll
            for (int ns = 0; ns < 4; ns++) {
                uint32_t off = SW128((brow + ns * 8) * 128 + ks * 32 + bcb);
                ldsm_x2(bh[ns], tBh + off);
                ldsm_x2(bl[ns], tBl + off);
            }
            #pragma unroll
            for (int ms = 0; ms < 4; ms++)
                #pragma unroll
                for (int ns = 0; ns < 4; ns++) {
                    mma_bf16(acc[ms][ns], ah[ms], bh[ns]);
                    mma_bf16(acc[ms][ns], ah[ms], bl[ns]);
                    mma_bf16(acc[ms][ns], al[ms], bh[ns]);
                }
        }
        __syncthreads();
    }

    const int gid = lane >> 2, tc = lane & 3;
    #pragma unroll
    for (int ms = 0; ms < 4; ms++) {
        #pragma unroll
        for (int ns = 0; ns < 4; ns++) {
            int gr0 = bm + wm + ms * 16 + gid;
            int gc  = bn + wn + ns * 8 + tc * 2;
            if (gc < N) {
                float2 v0;
                v0.x = alpha * acc[ms][ns][0];
                v0.y = alpha * acc[ms][ns][1];
                if (R) { v0.x += R[(size_t)gr0 * ldr + gc]; v0.y += R[(size_t)gr0 * ldr + gc + 1]; }
                *(float2*)&C[(size_t)gr0 * ldc + gc] = v0;
                int gr1 = gr0 + 8;
                float2 v1;
                v1.x = alpha * acc[ms][ns][2];
                v1.y = alpha * acc[ms][ns][3];
                if (R) { v1.x += R[(size_t)gr1 * ldr + gc]; v1.y += R[(size_t)gr1 * ldr + gc + 1]; }
                *(float2*)&C[(size_t)gr1 * ldc + gc] = v1;
            }
        }
    }
}

// ==================== GEMM v2: 128x256 tile, warp 64x64 =====================
// N % 256 == 0 required. causal: 1 = write R and skip when fully masked.
#define STAGE2 98304
#define GT2_SMEM (2*STAGE2)

__global__ __launch_bounds__(256, 1) void gemm_tc256(
    const __nv_bfloat16* __restrict__ Ah, const __nv_bfloat16* __restrict__ Al,
    int lda, long long sA,
    const __nv_bfloat16* __restrict__ Bh, const __nv_bfloat16* __restrict__ Bl,
    int ldb, long long sB,
    float* __restrict__ C, int ldc, long long sC,
    const float* __restrict__ R, int ldr, long long sR,
    int M, int N, int K, float alpha, int causal)
{
    extern __shared__ __align__(1024) char smem[];
    const uint32_t sb0 = smem_u32(smem);
    const int tid = threadIdx.x;
    const int wid = tid >> 5, lane = tid & 31;
    long long z = blockIdx.z;
    Ah += z * sA; Al += z * sA; Bh += z * sB; Bl += z * sB; C += z * sC;
    if (R) R += z * sR;
    const int bm = blockIdx.y * 128, bn = blockIdx.x * 256;
    const int wm = (wid >> 2) * 64, wn = (wid & 3) * 64;

    if (causal == 1 && bn > bm + 127) {
        // fully masked tile: C = R (mask); softmax maps these to exp(-1e9)=0
        for (int idx = tid; idx < 128 * 64; idx += 256) {
            int r = idx >> 6, cg = (idx & 63) << 2;
            int gm = bm + r, gn = bn + cg;
            *(float4*)&C[(size_t)gm * ldc + gn] = *(const float4*)&R[(size_t)gm * ldr + gn];
        }
        return;
    }

    float acc[4][8][4];
    #pragma unroll
    for (int i = 0; i < 4; i++)
        #pragma unroll
        for (int j = 0; j < 8; j++)
            #pragma unroll
            for (int r = 0; r < 4; r++) acc[i][j][r] = 0.f;

    int nc = K >> 6;
    if (causal == 2) { int lim = (bm + 128 + 63) >> 6; if (lim < nc) nc = lim; }

    // stage layout: Ah 16K | Al 16K | Bh 32K | Bl 32K
    #define ISSUE2(stage, k0) do {                                              \
        uint32_t sbase = sb0 + (stage) * STAGE2;                                \
        _Pragma("unroll")                                                       \
        for (int it = 0; it < 4; it++) {                                        \
            int e = it * 256 + tid;                                             \
            int r = e >> 3, g = e & 7;                                          \
            uint32_t so = SW128(r * 128 + g * 16);                              \
            int ra = bm + r; int pa = (ra < M) ? 16 : 0; if (!pa) ra = 0;       \
            cpa16(sbase + so,         Ah + (size_t)ra * lda + (k0) + g * 8, pa);\
            cpa16(sbase + 16384 + so, Al + (size_t)ra * lda + (k0) + g * 8, pa);\
        }                                                                       \
        _Pragma("unroll")                                                       \
        for (int it = 0; it < 8; it++) {                                        \
            int e = it * 256 + tid;                                             \
            int r = e >> 3, g = e & 7;                                          \
            uint32_t so = SW128(r * 128 + g * 16);                              \
            int rb = bn + r; int pb = (rb < N) ? 16 : 0; if (!pb) rb = 0;       \
            cpa16(sbase + 32768 + so, Bh + (size_t)rb * ldb + (k0) + g * 8, pb);\
            cpa16(sbase + 65536 + so, Bl + (size_t)rb * ldb + (k0) + g * 8, pb);\
        }                                                                       \
        cp_commit();                                                            \
    } while (0)

    ISSUE2(0, 0);

    const int arow = wm + (lane & 15);
    const int acb  = (lane >> 4) << 4;
    // B x4: row = wn + ng4*16 + ((lane>>4)<<3) + (lane&7), col = ks*32 + ((lane>>3)&1)*16
    const int brow4 = wn + ((lane >> 4) << 3) + (lane & 7);
    const int bcb4  = ((lane >> 3) & 1) << 4;

    for (int c = 0; c < nc; c++) {
        if (c + 1 < nc) { ISSUE2((c + 1) & 1, (c + 1) << 6); cp_wait<1>(); }
        else            { cp_wait<0>(); }
        __syncthreads();

        uint32_t tAh = sb0 + (c & 1) * STAGE2;
        uint32_t tAl = tAh + 16384, tBh = tAh + 32768, tBl = tAh + 65536;

        #pragma unroll
        for (int ks = 0; ks < 4; ks++) {
            uint32_t ah[4][4], al[4][4];
            #pragma unroll
            for (int ms = 0; ms < 4; ms++) {
                uint32_t off = SW128((arow + ms * 16) * 128 + ks * 32 + acb);
                ldsm_x4(ah[ms], tAh + off);
                ldsm_x4(al[ms], tAl + off);
            }
            #pragma unroll
            for (int ng4 = 0; ng4 < 4; ng4++) {
                uint32_t bh4[4], bl4[4];
                uint32_t off = SW128((brow4 + ng4 * 16) * 128 + ks * 32 + bcb4);
                ldsm_x4(bh4, tBh + off);
                ldsm_x4(bl4, tBl + off);
                #pragma unroll
                for (int ms = 0; ms < 4; ms++) {
                    mma_bf16(acc[ms][2*ng4],   ah[ms], bh4);
                    mma_bf16(acc[ms][2*ng4],   ah[ms], bl4);
                    mma_bf16(acc[ms][2*ng4],   al[ms], bh4);
                    mma_bf16(acc[ms][2*ng4+1], ah[ms], bh4 + 2);
                    mma_bf16(acc[ms][2*ng4+1], ah[ms], bl4 + 2);
                    mma_bf16(acc[ms][2*ng4+1], al[ms], bh4 + 2);
                }
            }
        }
        __syncthreads();
    }

    const int gid = lane >> 2, tc = lane & 3;
    #pragma unroll
    for (int ms = 0; ms < 4; ms++) {
        #pragma unroll
        for (int ns = 0; ns < 8; ns++) {
            int gr0 = bm + wm + ms * 16 + gid;
            int gc  = bn + wn + ns * 8 + tc * 2;
            float2 v0;
            v0.x = alpha * acc[ms][ns][0];
            v0.y = alpha * acc[ms][ns][1];
            if (R) { v0.x += R[(size_t)gr0 * ldr + gc]; v0.y += R[(size_t)gr0 * ldr + gc + 1]; }
            *(float2*)&C[(size_t)gr0 * ldc + gc] = v0;
            int gr1 = gr0 + 8;
            float2 v1;
            v1.x = alpha * acc[ms][ns][2];
            v1.y = alpha * acc[ms][ns][3];
            if (R) { v1.x += R[(size_t)gr1 * ldr + gc]; v1.y += R[(size_t)gr1 * ldr + gc + 1]; }
            *(float2*)&C[(size_t)gr1 * ldc + gc] = v1;
        }
    }
}

// ------------------------------ host launch ---------------------------------
static void gemm(const __nv_bfloat16* Ah, const __nv_bfloat16* Al, int lda, long long sA,
                 const __nv_bfloat16* Bh, const __nv_bfloat16* Bl, int ldb, long long sB,
                 float* C, int ldc, long long sC,
                 const float* R, int ldr, long long sR,
                 int M, int N, int K, float alpha, int Z, int causal = 0)
{
    if (N % 256 == 0) {
        dim3 grid(N / 256, M / 128, Z);
        gemm_tc256<<<grid, 256, GT2_SMEM>>>(Ah, Al, lda, sA, Bh, Bl, ldb, sB,
                                            C, ldc, sC, R, ldr, sR, M, N, K, alpha, causal);
    } else {
        dim3 grid((N + 127) / 128, M / 128, Z);
        gemm_tc128<<<grid, 256, GT1_SMEM>>>(Ah, Al, lda, sA, Bh, Bl, ldb, sB,
                                            C, ldc, sC, R, ldr, sR, M, N, K, alpha, causal);
    }
}

static void split(const float* in, __nv_bfloat16* hi, __nv_bfloat16* lo, long long n)
{
    long long n4 = n >> 2;
    split_k<<<(unsigned)((n4 + 255) / 256), 256>>>(
        (const float4*)in, (__nv_bfloat162*)hi, (__nv_bfloat162*)lo, n4);
}

extern "C" void kernel_launch(void* const* d_in, const int* in_sizes, int n_in,
                              void* d_out, int out_size)
{
    const float* x     = (const float*)d_in[0];
    const float* mask  = (const float*)d_in[1];
    const float* fcos  = (const float*)d_in[2];
    const float* fsin  = (const float*)d_in[3];
    const float* anw   = (const float*)d_in[4];
    const float* wq_a  = (const float*)d_in[5];
    const float* qnw   = (const float*)d_in[6];
    const float* wq_b  = (const float*)d_in[7];
    const float* wkv_a = (const float*)d_in[8];
    const float* kvnw  = (const float*)d_in[9];
    const float* wkv_b = (const float*)d_in[10];
    const float* wo    = (const float*)d_in[11];
    const float* fnw   = (const float*)d_in[12];
    const float* w1    = (const float*)d_in[13];
    const float* w2    = (const float*)d_in[14];
    const float* w3    = (const float*)d_in[15];
    float* out = (float*)d_out;

    cudaFuncSetAttribute(gemm_tc128, cudaFuncAttributeMaxDynamicSharedMemorySize, GT1_SMEM);
    cudaFuncSetAttribute(gemm_tc256, cudaFuncAttributeMaxDynamicSharedMemorySize, GT2_SMEM);

    float *p_qa, *p_q, *p_kva, *p_kv, *p_sc, *p_y, *p_x2, *p_gate, *p_up;
    cudaGetSymbolAddress((void**)&p_qa,  g_qa);
    cudaGetSymbolAddress((void**)&p_q,   g_q);
    cudaGetSymbolAddress((void**)&p_kva, g_kva);
    cudaGetSymbolAddress((void**)&p_kv,  g_kv);
    cudaGetSymbolAddress((void**)&p_sc,  g_sc);
    cudaGetSymbolAddress((void**)&p_y,   g_y);
    cudaGetSymbolAddress((void**)&p_x2,  g_x2);
    cudaGetSymbolAddress((void**)&p_gate,g_gate);
    cudaGetSymbolAddress((void**)&p_up,  g_up);

    __nv_bfloat16 *hH,*hL,*qaH,*qaL,*kvnH,*kvnL,*qfH,*qfL,*kfH,*kfL,*vTH,*vTL,
        *atH,*atL,*y2H,*y2L,*h2H,*h2L,*gsH,*gsL,
        *wqaH,*wqaL,*wqbH,*wqbL,*wkaH,*wkaL,*wkbH,*wkbL,
        *woH,*woL,*w1H,*w1L,*w2H,*w2L,*w3H,*w3L;
    cudaGetSymbolAddress((void**)&hH,  b_hH);  cudaGetSymbolAddress((void**)&hL,  b_hL);
    cudaGetSymbolAddress((void**)&qaH, b_qaH); cudaGetSymbolAddress((void**)&qaL, b_qaL);
    cudaGetSymbolAddress((void**)&kvnH,b_kvnH);cudaGetSymbolAddress((void**)&kvnL,b_kvnL);
    cudaGetSymbolAddress((void**)&qfH, b_qfH); cudaGetSymbolAddress((void**)&qfL, b_qfL);
    cudaGetSymbolAddress((void**)&kfH, b_kfH); cudaGetSymbolAddress((void**)&kfL, b_kfL);
    cudaGetSymbolAddress((void**)&vTH, b_vTH); cudaGetSymbolAddress((void**)&vTL, b_vTL);
    cudaGetSymbolAddress((void**)&atH, b_atH); cudaGetSymbolAddress((void**)&atL, b_atL);
    cudaGetSymbolAddress((void**)&y2H, b_y2H); cudaGetSymbolAddress((void**)&y2L, b_y2L);
    cudaGetSymbolAddress((void**)&h2H, b_h2H); cudaGetSymbolAddress((void**)&h2L, b_h2L);
    cudaGetSymbolAddress((void**)&gsH, b_gsH); cudaGetSymbolAddress((void**)&gsL, b_gsL);
    cudaGetSymbolAddress((void**)&wqaH,b_wqaH);cudaGetSymbolAddress((void**)&wqaL,b_wqaL);
    cudaGetSymbolAddress((void**)&wqbH,b_wqbH);cudaGetSymbolAddress((void**)&wqbL,b_wqbL);
    cudaGetSymbolAddress((void**)&wkaH,b_wkaH);cudaGetSymbolAddress((void**)&wkaL,b_wkaL);
    cudaGetSymbolAddress((void**)&wkbH,b_wkbH);cudaGetSymbolAddress((void**)&wkbL,b_wkbL);
    cudaGetSymbolAddress((void**)&woH, b_woH); cudaGetSymbolAddress((void**)&woL, b_woL);
    cudaGetSymbolAddress((void**)&w1H, b_w1H); cudaGetSymbolAddress((void**)&w1L, b_w1L);
    cudaGetSymbolAddress((void**)&w2H, b_w2H); cudaGetSymbolAddress((void**)&w2L, b_w2L);
    cudaGetSymbolAddress((void**)&w3H, b_w3H); cudaGetSymbolAddress((void**)&w3L, b_w3L);

    // weights -> bf16 hi/lo
    split(wq_a,  wqaH, wqaL, (long long)CQLORA*CD);
    split(wq_b,  wqbH, wqbL, (long long)CH*CQKD*CQLORA);
    split(wkv_a, wkaH, wkaL, (long long)(CKVLORA+CROPE)*CD);
    split(wkv_b, wkbH, wkbL, (long long)CH*256*CKVLORA);
    split(wo,    woH,  woL,  (long long)CD*CD);
    split(w1,    w1H,  w1L,  (long long)CINTER*CD);
    split(w2,    w2H,  w2L,  (long long)CD*CINTER);
    split(w3,    w3H,  w3L,  (long long)CINTER*CD);

    // 1) h = rmsnorm(x) -> hi/lo
    rmsnorm_split_k<<<CM, 256>>>(x, CD, anw, hH, hL, CD);
    // 2) qa = h @ wq_a^T
    gemm(hH, hL, CD, 0, wqaH, wqaL, CD, 0, p_qa, CQLORA, 0,
         nullptr, 0, 0, CM, CQLORA, CD, 1.f, 1);
    // 3) qa_norm -> hi/lo
    rmsnorm_split_k<<<CM, 256>>>(p_qa, CQLORA, qnw, qaH, qaL, CQLORA);
    // 4) q = qa_norm @ wq_b^T
    gemm(qaH, qaL, CQLORA, 0, wqbH, wqbL, CQLORA, 0, p_q, CH*CQKD, 0,
         nullptr, 0, 0, CM, CH*CQKD, CQLORA, 1.f, 1);
    // 5) kva = h @ wkv_a^T
    gemm(hH, hL, CD, 0, wkaH, wkaL, CD, 0, p_kva, CKVLORA+CROPE, 0,
         nullptr, 0, 0, CM, CKVLORA+CROPE, CD, 1.f, 1);
    // 6) kv_norm -> hi/lo
    rmsnorm_split_k<<<CM, 256>>>(p_kva, CKVLORA+CROPE, kvnw, kvnH, kvnL, CKVLORA);
    // 7) kv = kv_norm @ wkv_b^T
    gemm(kvnH, kvnL, CKVLORA, 0, wkbH, wkbL, CKVLORA, 0, p_kv, CH*256, 0,
         nullptr, 0, 0, CM, CH*256, CKVLORA, 1.f, 1);
    // 8) rope + pack -> qf/kf/vT hi/lo
    rope_pack_split_k<<<dim3(CT, CB), 256>>>(p_q, p_kv, p_kva, fcos, fsin,
                                             qfH, qfL, kfH, kfL, vTH, vTL);
    // 9) scores = -96 * qf @ kf^T + mask   (causal=1: skip fully-masked tiles)
    gemm(qfH, qfL, CQKD, (long long)CT*CQKD,
         kfH, kfL, CQKD, (long long)CT*CQKD,
         p_sc, CT, (long long)CT*CT,
         mask, CT, 0, CT, CT, CQKD, -96.f, CB*CH, 1);
    // 10) softmax -> attn hi/lo
    softmax_split_k<<<CB*CH*CT, 256>>>(p_sc, atH, atL);
    // 11) y = attn @ vT  (causal=2: truncate K at diagonal — attn is 0 above)
    gemm(atH, atL, CT, (long long)CT*CT,
         vTH, vTL, CT, (long long)CVHD*CT,
         p_y, CVHD, (long long)CT*CVHD,
         nullptr, 0, 0, CT, CVHD, CT, 1.f, CB*CH, 2);
    // 12) permute -> y2 hi/lo
    permute_split_k<<<dim3(CT, CB), 256>>>(p_y, y2H, y2L);
    // 13) x2 = x + y2 @ wo^T
    gemm(y2H, y2L, CH*CVHD, 0, woH, woL, CH*CVHD, 0, p_x2, CD, 0,
         x, CD, 0, CM, CD, CH*CVHD, 1.f, 1);
    // 14) h2 = rmsnorm(x2) -> hi/lo
    rmsnorm_split_k<<<CM, 256>>>(p_x2, CD, fnw, h2H, h2L, CD);
    // 15/16) gate/up
    gemm(h2H, h2L, CD, 0, w1H, w1L, CD, 0, p_gate, CINTER, 0,
         nullptr, 0, 0, CM, CINTER, CD, 1.f, 1);
    gemm(h2H, h2L, CD, 0, w3H, w3L, CD, 0, p_up, CINTER, 0,
         nullptr, 0, 0, CM, CINTER, CD, 1.f, 1);
    // 17) gs = silu(gate)*up -> hi/lo
    {
        long long n4 = ((long long)CM * CINTER) >> 2;
        silu_mul_split_k<<<(unsigned)((n4 + 255) / 256), 256>>>(
            (const float4*)p_gate, (const float4*)p_up,
            (__nv_bfloat162*)gsH, (__nv_bfloat162*)gsL, n4);
    }
    // 18) out = x2 + gs @ w2^T
    gemm(gsH, gsL, CINTER, 0, w2H, w2L, CINTER, 0, out, CD, 0,
         p_x2, CD, 0, CM, CD, CINTER, 1.f, 1);
}

// round 5
// speedup vs baseline: 3.6888x; 1.2407x over previous
#include <cuda_runtime.h>
#include <cuda_bf16.h>
#include <cuda_fp16.h>
#include <cstdint>

// ---------------------------------------------------------------------------
// DeepSeek MLA block on GB300 — mma.sync split-GEMM v3.
// Attention path: bf16 3-term Dekker split (Ah@Bh + Ah@Bl + Al@Bh).
// FFN path: fp16 activations (hi+lo pair) x single-fp16 weights, 2 MMA terms.
// ---------------------------------------------------------------------------

#define CB 2
#define CT 1024
#define CD 2048
#define CH 16
#define CNOPE 128
#define CROPE 64
#define CQKD 192
#define CQLORA 1536
#define CKVLORA 512
#define CVHD 128
#define CINTER 8192
#define CM (CB*CT)

// ------------------------------- PTX helpers -------------------------------
__device__ __forceinline__ uint32_t smem_u32(const void* p) {
    uint32_t a;
    asm("{ .reg .u64 t; cvta.to.shared.u64 t, %1; cvt.u32.u64 %0, t; }" : "=r"(a) : "l"(p));
    return a;
}
#define SW128(o) ((o) ^ (((o) >> 3) & 0x70))

__device__ __forceinline__ void cpa16(uint32_t s, const void* g, int sz) {
    asm volatile("cp.async.cg.shared.global [%0], [%1], 16, %2;"
                 :: "r"(s), "l"(g), "r"(sz));
}
__device__ __forceinline__ void cp_commit() {
    asm volatile("cp.async.commit_group;" ::: "memory");
}
template <int N> __device__ __forceinline__ void cp_wait() {
    asm volatile("cp.async.wait_group %0;" :: "n"(N) : "memory");
}
__device__ __forceinline__ void ldsm_x4(uint32_t* r, uint32_t a) {
    asm volatile("ldmatrix.sync.aligned.m8n8.x4.shared.b16 {%0,%1,%2,%3}, [%4];"
        : "=r"(r[0]), "=r"(r[1]), "=r"(r[2]), "=r"(r[3]) : "r"(a));
}
__device__ __forceinline__ void ldsm_x2(uint32_t* r, uint32_t a) {
    asm volatile("ldmatrix.sync.aligned.m8n8.x2.shared.b16 {%0,%1}, [%2];"
        : "=r"(r[0]), "=r"(r[1]) : "r"(a));
}
__device__ __forceinline__ void mma_bf16(float* d, const uint32_t* a, const uint32_t* b) {
    asm volatile(
        "mma.sync.aligned.m16n8k16.row.col.f32.bf16.bf16.f32 "
        "{%0,%1,%2,%3}, {%4,%5,%6,%7}, {%8,%9}, {%0,%1,%2,%3};"
        : "+f"(d[0]), "+f"(d[1]), "+f"(d[2]), "+f"(d[3])
        : "r"(a[0]), "r"(a[1]), "r"(a[2]), "r"(a[3]), "r"(b[0]), "r"(b[1]));
}
__device__ __forceinline__ void mma_f16(float* d, const uint32_t* a, const uint32_t* b) {
    asm volatile(
        "mma.sync.aligned.m16n8k16.row.col.f32.f16.f16.f32 "
        "{%0,%1,%2,%3}, {%4,%5,%6,%7}, {%8,%9}, {%0,%1,%2,%3};"
        : "+f"(d[0]), "+f"(d[1]), "+f"(d[2]), "+f"(d[3])
        : "r"(a[0]), "r"(a[1]), "r"(a[2]), "r"(a[3]), "r"(b[0]), "r"(b[1]));
}

// ------------------------- scratch (device globals) ------------------------
__device__ float g_qa  [(long long)CM*CQLORA];
__device__ float g_q   [(long long)CM*CH*CQKD];
__device__ float g_kva [(long long)CM*(CKVLORA+CROPE)];
__device__ float g_kv  [(long long)CM*CH*(CNOPE+CVHD)];
__device__ float g_sc  [(long long)CB*CH*CT*CT];
__device__ float g_y   [(long long)CB*CH*CT*CVHD];
__device__ float g_x2  [(long long)CM*CD];
__device__ float g_gate[(long long)CM*CINTER];
__device__ float g_up  [(long long)CM*CINTER];

__device__ __nv_bfloat16 b_hH [(long long)CM*CD],        b_hL [(long long)CM*CD];
__device__ __nv_bfloat16 b_qaH[(long long)CM*CQLORA],    b_qaL[(long long)CM*CQLORA];
__device__ __nv_bfloat16 b_kvnH[(long long)CM*CKVLORA],  b_kvnL[(long long)CM*CKVLORA];
__device__ __nv_bfloat16 b_qfH[(long long)CB*CH*CT*CQKD], b_qfL[(long long)CB*CH*CT*CQKD];
__device__ __nv_bfloat16 b_kfH[(long long)CB*CH*CT*CQKD], b_kfL[(long long)CB*CH*CT*CQKD];
__device__ __nv_bfloat16 b_vTH[(long long)CB*CH*CVHD*CT], b_vTL[(long long)CB*CH*CVHD*CT];
__device__ __nv_bfloat16 b_atH[(long long)CB*CH*CT*CT],  b_atL[(long long)CB*CH*CT*CT];
__device__ __nv_bfloat16 b_y2H[(long long)CM*CD],        b_y2L[(long long)CM*CD];
__device__ __nv_bfloat16 b_wqaH[(long long)CQLORA*CD],   b_wqaL[(long long)CQLORA*CD];
__device__ __nv_bfloat16 b_wqbH[(long long)CH*CQKD*CQLORA], b_wqbL[(long long)CH*CQKD*CQLORA];
__device__ __nv_bfloat16 b_wkaH[(long long)(CKVLORA+CROPE)*CD], b_wkaL[(long long)(CKVLORA+CROPE)*CD];
__device__ __nv_bfloat16 b_wkbH[(long long)CH*256*CKVLORA], b_wkbL[(long long)CH*256*CKVLORA];
__device__ __nv_bfloat16 b_woH [(long long)CD*CD],        b_woL [(long long)CD*CD];
// fp16 FFN buffers
__device__ __half h_w1 [(long long)CINTER*CD];
__device__ __half h_w2 [(long long)CD*CINTER];
__device__ __half h_w3 [(long long)CINTER*CD];
__device__ __half h_h2H[(long long)CM*CD],     h_h2L[(long long)CM*CD];
__device__ __half h_gsH[(long long)CM*CINTER], h_gsL[(long long)CM*CINTER];

// ------------------------------- split helpers -----------------------------
__device__ __forceinline__ void split1(float v, __nv_bfloat16& h, __nv_bfloat16& l) {
    h = __float2bfloat16(v);
    l = __float2bfloat16(v - __bfloat162float(h));
}
__device__ __forceinline__ void split1h(float v, __half& h, __half& l) {
    h = __float2half_rn(v);
    l = __float2half_rn(v - __half2float(h));
}

__global__ __launch_bounds__(256) void split_k(
    const float4* __restrict__ in, __nv_bfloat162* __restrict__ hi,
    __nv_bfloat162* __restrict__ lo, long long n4)
{
    long long i = (long long)blockIdx.x * 256 + threadIdx.x;
    if (i >= n4) return;
    float4 v = in[i];
    __nv_bfloat16 h0, h1, h2, h3, l0, l1, l2, l3;
    split1(v.x, h0, l0); split1(v.y, h1, l1);
    split1(v.z, h2, l2); split1(v.w, h3, l3);
    hi[2*i]   = __halves2bfloat162(h0, h1);
    hi[2*i+1] = __halves2bfloat162(h2, h3);
    lo[2*i]   = __halves2bfloat162(l0, l1);
    lo[2*i+1] = __halves2bfloat162(l2, l3);
}

// fused fp16 conversion of w1, w2, w3 (all the same element count)
__global__ __launch_bounds__(256) void conv3_h_k(
    const float4* __restrict__ s0, const float4* __restrict__ s1,
    const float4* __restrict__ s2,
    __half2* __restrict__ d0, __half2* __restrict__ d1, __half2* __restrict__ d2,
    long long n4)
{
    long long i = (long long)blockIdx.x * 256 + threadIdx.x;
    if (i >= n4) return;
    const float4* s = (blockIdx.y == 0) ? s0 : (blockIdx.y == 1) ? s1 : s2;
    __half2* d = (blockIdx.y == 0) ? d0 : (blockIdx.y == 1) ? d1 : d2;
    float4 v = s[i];
    d[2*i]   = __floats2half2_rn(v.x, v.y);
    d[2*i+1] = __floats2half2_rn(v.z, v.w);
}

// ------------------------------ RMSNorm + split -----------------------------
__global__ __launch_bounds__(256) void rmsnorm_split_k(
    const float* __restrict__ in, int ldin, const float* __restrict__ w,
    __nv_bfloat16* __restrict__ hi, __nv_bfloat16* __restrict__ lo, int K)
{
    long long row = blockIdx.x;
    const float* ip = in + row * ldin;
    float s = 0.f;
    for (int i = threadIdx.x; i < K; i += 256) { float v = ip[i]; s += v * v; }
    __shared__ float red[32];
    #pragma unroll
    for (int o = 16; o > 0; o >>= 1) s += __shfl_xor_sync(0xffffffffu, s, o);
    int warp = threadIdx.x >> 5, lane = threadIdx.x & 31;
    if (lane == 0) red[warp] = s;
    __syncthreads();
    if (warp == 0) {
        float s2 = (lane < 8) ? red[lane] : 0.f;
        #pragma unroll
        for (int o = 4; o > 0; o >>= 1) s2 += __shfl_xor_sync(0xffffffffu, s2, o);
        if (lane == 0) red[0] = s2;
    }
    __syncthreads();
    float scale = rsqrtf(red[0] / (float)K + 1e-6f);
    for (int i = threadIdx.x; i < K; i += 256) {
        float v = ip[i] * scale * w[i];
        __nv_bfloat16 h, l; split1(v, h, l);
        hi[row * (long long)K + i] = h;
        lo[row * (long long)K + i] = l;
    }
}

// fp16-pair output variant (for h2 feeding the FFN)
__global__ __launch_bounds__(256) void rmsnorm_split_h_k(
    const float* __restrict__ in, int ldin, const float* __restrict__ w,
    __half* __restrict__ hi, __half* __restrict__ lo, int K)
{
    long long row = blockIdx.x;
    const float* ip = in + row * ldin;
    float s = 0.f;
    for (int i = threadIdx.x; i < K; i += 256) { float v = ip[i]; s += v * v; }
    __shared__ float red[32];
    #pragma unroll
    for (int o = 16; o > 0; o >>= 1) s += __shfl_xor_sync(0xffffffffu, s, o);
    int warp = threadIdx.x >> 5, lane = threadIdx.x & 31;
    if (lane == 0) red[warp] = s;
    __syncthreads();
    if (warp == 0) {
        float s2 = (lane < 8) ? red[lane] : 0.f;
        #pragma unroll
        for (int o = 4; o > 0; o >>= 1) s2 += __shfl_xor_sync(0xffffffffu, s2, o);
        if (lane == 0) red[0] = s2;
    }
    __syncthreads();
    float scale = rsqrtf(red[0] / (float)K + 1e-6f);
    for (int i = threadIdx.x; i < K; i += 256) {
        float v = ip[i] * scale * w[i];
        __half h, l; split1h(v, h, l);
        hi[row * (long long)K + i] = h;
        lo[row * (long long)K + i] = l;
    }
}

// ------------------- RoPE + head packing (split outputs) --------------------
__global__ __launch_bounds__(256) void rope_pack_split_k(
    const float* __restrict__ q, const float* __restrict__ kv,
    const float* __restrict__ kva,
    const float* __restrict__ fcos, const float* __restrict__ fsin,
    __nv_bfloat16* __restrict__ qfH, __nv_bfloat16* __restrict__ qfL,
    __nv_bfloat16* __restrict__ kfH, __nv_bfloat16* __restrict__ kfL,
    __nv_bfloat16* __restrict__ vTH, __nv_bfloat16* __restrict__ vTL)
{
    int t = blockIdx.x, b = blockIdx.y;
    long long m = (long long)b * CT + t;
    __shared__ float kpe[CROPE], cs[32], sn[32];
    int tid = threadIdx.x;
    if (tid < 32) { cs[tid] = fcos[t*32 + tid]; sn[tid] = fsin[t*32 + tid]; }
    __syncthreads();
    if (tid < 32) {
        float x0 = kva[m*576 + 512 + 2*tid];
        float x1 = kva[m*576 + 512 + 2*tid + 1];
        kpe[2*tid]   = x0*cs[tid] - x1*sn[tid];
        kpe[2*tid+1] = x0*sn[tid] + x1*cs[tid];
    }
    __syncthreads();
    for (int idx = tid; idx < CH*CQKD; idx += 256) {
        int h = idx / CQKD, d = idx % CQKD;
        long long o = (((long long)b*CH + h)*CT + t)*CQKD + d;
        float qv, kvv;
        if (d < CNOPE) {
            qv  = q [m*(CH*CQKD) + h*CQKD + d];
            kvv = kv[m*(CH*256)  + h*256  + d];
        } else {
            int j = d - CNOPE, i2 = j >> 1;
            float x0 = q[m*(CH*CQKD) + h*CQKD + CNOPE + 2*i2];
            float x1 = q[m*(CH*CQKD) + h*CQKD + CNOPE + 2*i2 + 1];
            qv  = (j & 1) ? (x0*sn[i2] + x1*cs[i2]) : (x0*cs[i2] - x1*sn[i2]);
            kvv = kpe[j];
        }
        __nv_bfloat16 hh, ll;
        split1(qv, hh, ll);  qfH[o] = hh; qfL[o] = ll;
        split1(kvv, hh, ll); kfH[o] = hh; kfL[o] = ll;
    }
    for (int idx = tid; idx < CH*CVHD; idx += 256) {
        int h = idx >> 7, d = idx & 127;
        long long o = (((long long)b*CH + h)*CVHD + d)*CT + t;
        float v = kv[m*(CH*256) + h*256 + CNOPE + d];
        __nv_bfloat16 hh, ll; split1(v, hh, ll);
        vTH[o] = hh; vTL[o] = ll;
    }
}

// ------------------------------ Softmax + split -----------------------------
__global__ __launch_bounds__(256) void softmax_split_k(
    const float* __restrict__ s, __nv_bfloat16* __restrict__ hi,
    __nv_bfloat16* __restrict__ lo)
{
    long long row = blockIdx.x;
    const float4* p = (const float4*)(s + row * (long long)CT);
    int tid = threadIdx.x, warp = tid >> 5, lane = tid & 31;
    __shared__ float red[32];

    float4 v = p[tid];
    float mx = fmaxf(fmaxf(v.x, v.y), fmaxf(v.z, v.w));
    #pragma unroll
    for (int o = 16; o > 0; o >>= 1) mx = fmaxf(mx, __shfl_xor_sync(0xffffffffu, mx, o));
    if (lane == 0) red[warp] = mx;
    __syncthreads();
    if (warp == 0) {
        float m2 = (lane < 8) ? red[lane] : -1e30f;
        #pragma unroll
        for (int o = 4; o > 0; o >>= 1) m2 = fmaxf(m2, __shfl_xor_sync(0xffffffffu, m2, o));
        if (lane == 0) red[0] = m2;
    }
    __syncthreads();
    mx = red[0];
    __syncthreads();

    v.x = __expf(v.x - mx); v.y = __expf(v.y - mx);
    v.z = __expf(v.z - mx); v.w = __expf(v.w - mx);
    float sum = v.x + v.y + v.z + v.w;
    #pragma unroll
    for (int o = 16; o > 0; o >>= 1) sum += __shfl_xor_sync(0xffffffffu, sum, o);
    if (lane == 0) red[warp] = sum;
    __syncthreads();
    if (warp == 0) {
        float s2 = (lane < 8) ? red[lane] : 0.f;
        #pragma unroll
        for (int o = 4; o > 0; o >>= 1) s2 += __shfl_xor_sync(0xffffffffu, s2, o);
        if (lane == 0) red[0] = s2;
    }
    __syncthreads();
    float inv = 1.f / red[0];
    v.x *= inv; v.y *= inv; v.z *= inv; v.w *= inv;

    __nv_bfloat16 h0,h1,h2,h3,l0,l1,l2,l3;
    split1(v.x,h0,l0); split1(v.y,h1,l1); split1(v.z,h2,l2); split1(v.w,h3,l3);
    __nv_bfloat162* H = (__nv_bfloat162*)(hi + row * (long long)CT);
    __nv_bfloat162* L = (__nv_bfloat162*)(lo + row * (long long)CT);
    H[2*tid]   = __halves2bfloat162(h0, h1);
    H[2*tid+1] = __halves2bfloat162(h2, h3);
    L[2*tid]   = __halves2bfloat162(l0, l1);
    L[2*tid+1] = __halves2bfloat162(l2, l3);
}

// ------------------- permute y [B,H,T,VHD] -> split [B*T, H*VHD] ------------
__global__ __launch_bounds__(256) void permute_split_k(
    const float* __restrict__ y, __nv_bfloat16* __restrict__ hi,
    __nv_bfloat16* __restrict__ lo)
{
    int t = blockIdx.x, b = blockIdx.y;
    for (int idx = threadIdx.x; idx < CH*CVHD; idx += 256) {
        int h = idx >> 7, d = idx & 127;
        float v = y[(((long long)b*CH + h)*CT + t)*CVHD + d];
        __nv_bfloat16 hh, ll; split1(v, hh, ll);
        long long o = ((long long)b*CT + t)*(CH*CVHD) + idx;
        hi[o] = hh; lo[o] = ll;
    }
}

// -------------------- SiLU(gate)*up + fp16-pair split ------------------------
__global__ __launch_bounds__(256) void silu_mul_split_h_k(
    const float4* __restrict__ g, const float4* __restrict__ u,
    __half2* __restrict__ hi, __half2* __restrict__ lo, long long n4)
{
    long long i = (long long)blockIdx.x * 256 + threadIdx.x;
    if (i >= n4) return;
    float4 gv = g[i], uv = u[i];
    float r0 = gv.x / (1.f + __expf(-gv.x)) * uv.x;
    float r1 = gv.y / (1.f + __expf(-gv.y)) * uv.y;
    float r2 = gv.z / (1.f + __expf(-gv.z)) * uv.z;
    float r3 = gv.w / (1.f + __expf(-gv.w)) * uv.w;
    __half h0,h1,h2,h3,l0,l1,l2,l3;
    split1h(r0,h0,l0); split1h(r1,h1,l1); split1h(r2,h2,l2); split1h(r3,h3,l3);
    hi[2*i]   = __halves2half2(h0,h1);
    hi[2*i+1] = __halves2half2(h2,h3);
    lo[2*i]   = __halves2half2(l0,l1);
    lo[2*i+1] = __halves2half2(l2,l3);
}

// ==================== GEMM v1: 128x128 tile, warp 64x32 (bf16) ==============
#define STAGE1 65536
#define GT1_SMEM (2*STAGE1)

__global__ __launch_bounds__(256, 1) void gemm_tc128(
    const __nv_bfloat16* __restrict__ Ah, const __nv_bfloat16* __restrict__ Al,
    int lda, long long sA,
    const __nv_bfloat16* __restrict__ Bh, const __nv_bfloat16* __restrict__ Bl,
    int ldb, long long sB,
    float* __restrict__ C, int ldc, long long sC,
    const float* __restrict__ R, int ldr, long long sR,
    int M, int N, int K, float alpha, int causal)
{
    extern __shared__ __align__(1024) char smem[];
    const uint32_t sb0 = smem_u32(smem);
    const int tid = threadIdx.x;
    const int wid = tid >> 5, lane = tid & 31;
    long long z = blockIdx.z;
    Ah += z * sA; Al += z * sA; Bh += z * sB; Bl += z * sB; C += z * sC;
    if (R) R += z * sR;
    const int bm = blockIdx.y * 128, bn = blockIdx.x * 128;
    const int wm = (wid >> 2) * 64, wn = (wid & 3) * 32;

    float acc[4][4][4];
    #pragma unroll
    for (int i = 0; i < 4; i++)
        #pragma unroll
        for (int j = 0; j < 4; j++)
            #pragma unroll
            for (int r = 0; r < 4; r++) acc[i][j][r] = 0.f;

    int nc = K >> 6;
    if (causal == 2) { int lim = (bm + 128 + 63) >> 6; if (lim < nc) nc = lim; }

    #define ISSUE1(stage, k0) do {                                              \
        uint32_t sbase = sb0 + (stage) * STAGE1;                                \
        _Pragma("unroll")                                                       \
        for (int it = 0; it < 4; it++) {                                        \
            int e = it * 256 + tid;                                             \
            int r = e >> 3, g = e & 7;                                          \
            uint32_t so = SW128(r * 128 + g * 16);                              \
            int ra = bm + r; int pa = (ra < M) ? 16 : 0; if (!pa) ra = 0;       \
            cpa16(sbase + so,         Ah + (size_t)ra * lda + (k0) + g * 8, pa);\
            cpa16(sbase + 16384 + so, Al + (size_t)ra * lda + (k0) + g * 8, pa);\
            int rb = bn + r; int pb = (rb < N) ? 16 : 0; if (!pb) rb = 0;       \
            cpa16(sbase + 32768 + so, Bh + (size_t)rb * ldb + (k0) + g * 8, pb);\
            cpa16(sbase + 49152 + so, Bl + (size_t)rb * ldb + (k0) + g * 8, pb);\
        }                                                                       \
        cp_commit();                                                            \
    } while (0)

    ISSUE1(0, 0);

    const int arow = wm + (lane & 15);
    const int acb  = (lane >> 4) << 4;
    const int brow = wn + (lane & 7);
    const int bcb  = ((lane >> 3) & 1) << 4;

    for (int c = 0; c < nc; c++) {
        if (c + 1 < nc) { ISSUE1((c + 1) & 1, (c + 1) << 6); cp_wait<1>(); }
        else            { cp_wait<0>(); }
        __syncthreads();

        uint32_t tAh = sb0 + (c & 1) * STAGE1;
        uint32_t tAl = tAh + 16384, tBh = tAh + 32768, tBl = tAh + 49152;

        #pragma unroll
        for (int ks = 0; ks < 4; ks++) {
            uint32_t ah[4][4], al[4][4], bh[4][2], bl[4][2];
            #pragma unroll
            for (int ms = 0; ms < 4; ms++) {
                uint32_t off = SW128((arow + ms * 16) * 128 + ks * 32 + acb);
                ldsm_x4(ah[ms], tAh + off);
                ldsm_x4(al[ms], tAl + off);
            }
            #pragma unroll
            for (int ns = 0; ns < 4; ns++) {
                uint32_t off = SW128((brow + ns * 8) * 128 + ks * 32 + bcb);
                ldsm_x2(bh[ns], tBh + off);
                ldsm_x2(bl[ns], tBl + off);
            }
            #pragma unroll
            for (int ms = 0; ms < 4; ms++)
                #pragma unroll
                for (int ns = 0; ns < 4; ns++) {
                    mma_bf16(acc[ms][ns], ah[ms], bh[ns]);
                    mma_bf16(acc[ms][ns], ah[ms], bl[ns]);
                    mma_bf16(acc[ms][ns], al[ms], bh[ns]);
                }
        }
        __syncthreads();
    }

    const int gid = lane >> 2, tc = lane & 3;
    #pragma unroll
    for (int ms = 0; ms < 4; ms++) {
        #pragma unroll
        for (int ns = 0; ns < 4; ns++) {
            int gr0 = bm + wm + ms * 16 + gid;
            int gc  = bn + wn + ns * 8 + tc * 2;
            if (gc < N) {
                float2 v0;
                v0.x = alpha * acc[ms][ns][0];
                v0.y = alpha * acc[ms][ns][1];
                if (R) { v0.x += R[(size_t)gr0 * ldr + gc]; v0.y += R[(size_t)gr0 * ldr + gc + 1]; }
                *(float2*)&C[(size_t)gr0 * ldc + gc] = v0;
                int gr1 = gr0 + 8;
                float2 v1;
                v1.x = alpha * acc[ms][ns][2];
                v1.y = alpha * acc[ms][ns][3];
                if (R) { v1.x += R[(size_t)gr1 * ldr + gc]; v1.y += R[(size_t)gr1 * ldr + gc + 1]; }
                *(float2*)&C[(size_t)gr1 * ldc + gc] = v1;
            }
        }
    }
}

// ==================== GEMM v2: 128x256 tile, warp 64x64 (bf16) ==============
#define STAGE2 98304
#define GT2_SMEM (2*STAGE2)

__global__ __launch_bounds__(256, 1) void gemm_tc256(
    const __nv_bfloat16* __restrict__ Ah, const __nv_bfloat16* __restrict__ Al,
    int lda, long long sA,
    const __nv_bfloat16* __restrict__ Bh, const __nv_bfloat16* __restrict__ Bl,
    int ldb, long long sB,
    float* __restrict__ C, int ldc, long long sC,
    const float* __restrict__ R, int ldr, long long sR,
    int M, int N, int K, float alpha, int causal)
{
    extern __shared__ __align__(1024) char smem[];
    const uint32_t sb0 = smem_u32(smem);
    const int tid = threadIdx.x;
    const int wid = tid >> 5, lane = tid & 31;
    long long z = blockIdx.z;
    Ah += z * sA; Al += z * sA; Bh += z * sB; Bl += z * sB; C += z * sC;
    if (R) R += z * sR;
    const int bm = blockIdx.y * 128, bn = blockIdx.x * 256;
    const int wm = (wid >> 2) * 64, wn = (wid & 3) * 64;

    if (causal == 1 && bn > bm + 127) {
        for (int idx = tid; idx < 128 * 64; idx += 256) {
            int r = idx >> 6, cg = (idx & 63) << 2;
            int gm = bm + r, gn = bn + cg;
            *(float4*)&C[(size_t)gm * ldc + gn] = *(const float4*)&R[(size_t)gm * ldr + gn];
        }
        return;
    }

    float acc[4][8][4];
    #pragma unroll
    for (int i = 0; i < 4; i++)
        #pragma unroll
        for (int j = 0; j < 8; j++)
            #pragma unroll
            for (int r = 0; r < 4; r++) acc[i][j][r] = 0.f;

    int nc = K >> 6;
    if (causal == 2) { int lim = (bm + 128 + 63) >> 6; if (lim < nc) nc = lim; }

    #define ISSUE2(stage, k0) do {                                              \
        uint32_t sbase = sb0 + (stage) * STAGE2;                                \
        _Pragma("unroll")                                                       \
        for (int it = 0; it < 4; it++) {                                        \
            int e = it * 256 + tid;                                             \
            int r = e >> 3, g = e & 7;                                          \
            uint32_t so = SW128(r * 128 + g * 16);                              \
            int ra = bm + r; int pa = (ra < M) ? 16 : 0; if (!pa) ra = 0;       \
            cpa16(sbase + so,         Ah + (size_t)ra * lda + (k0) + g * 8, pa);\
            cpa16(sbase + 16384 + so, Al + (size_t)ra * lda + (k0) + g * 8, pa);\
        }                                                                       \
        _Pragma("unroll")                                                       \
        for (int it = 0; it < 8; it++) {                                        \
            int e = it * 256 + tid;                                             \
            int r = e >> 3, g = e & 7;                                          \
            uint32_t so = SW128(r * 128 + g * 16);                              \
            int rb = bn + r; int pb = (rb < N) ? 16 : 0; if (!pb) rb = 0;       \
            cpa16(sbase + 32768 + so, Bh + (size_t)rb * ldb + (k0) + g * 8, pb);\
            cpa16(sbase + 65536 + so, Bl + (size_t)rb * ldb + (k0) + g * 8, pb);\
        }                                                                       \
        cp_commit();                                                            \
    } while (0)

    ISSUE2(0, 0);

    const int arow = wm + (lane & 15);
    const int acb  = (lane >> 4) << 4;
    const int brow4 = wn + ((lane >> 4) << 3) + (lane & 7);
    const int bcb4  = ((lane >> 3) & 1) << 4;

    for (int c = 0; c < nc; c++) {
        if (c + 1 < nc) { ISSUE2((c + 1) & 1, (c + 1) << 6); cp_wait<1>(); }
        else            { cp_wait<0>(); }
        __syncthreads();

        uint32_t tAh = sb0 + (c & 1) * STAGE2;
        uint32_t tAl = tAh + 16384, tBh = tAh + 32768, tBl = tAh + 65536;

        #pragma unroll
        for (int ks = 0; ks < 4; ks++) {
            uint32_t ah[4][4], al[4][4];
            #pragma unroll
            for (int ms = 0; ms < 4; ms++) {
                uint32_t off = SW128((arow + ms * 16) * 128 + ks * 32 + acb);
                ldsm_x4(ah[ms], tAh + off);
                ldsm_x4(al[ms], tAl + off);
            }
            #pragma unroll
            for (int ng4 = 0; ng4 < 4; ng4++) {
                uint32_t bh4[4], bl4[4];
                uint32_t off = SW128((brow4 + ng4 * 16) * 128 + ks * 32 + bcb4);
                ldsm_x4(bh4, tBh + off);
                ldsm_x4(bl4, tBl + off);
                #pragma unroll
                for (int ms = 0; ms < 4; ms++) {
                    mma_bf16(acc[ms][2*ng4],   ah[ms], bh4);
                    mma_bf16(acc[ms][2*ng4],   ah[ms], bl4);
                    mma_bf16(acc[ms][2*ng4],   al[ms], bh4);
                    mma_bf16(acc[ms][2*ng4+1], ah[ms], bh4 + 2);
                    mma_bf16(acc[ms][2*ng4+1], ah[ms], bl4 + 2);
                    mma_bf16(acc[ms][2*ng4+1], al[ms], bh4 + 2);
                }
            }
        }
        __syncthreads();
    }

    const int gid = lane >> 2, tc = lane & 3;
    #pragma unroll
    for (int ms = 0; ms < 4; ms++) {
        #pragma unroll
        for (int ns = 0; ns < 8; ns++) {
            int gr0 = bm + wm + ms * 16 + gid;
            int gc  = bn + wn + ns * 8 + tc * 2;
            float2 v0;
            v0.x = alpha * acc[ms][ns][0];
            v0.y = alpha * acc[ms][ns][1];
            if (R) { v0.x += R[(size_t)gr0 * ldr + gc]; v0.y += R[(size_t)gr0 * ldr + gc + 1]; }
            *(float2*)&C[(size_t)gr0 * ldc + gc] = v0;
            int gr1 = gr0 + 8;
            float2 v1;
            v1.x = alpha * acc[ms][ns][2];
            v1.y = alpha * acc[ms][ns][3];
            if (R) { v1.x += R[(size_t)gr1 * ldr + gc]; v1.y += R[(size_t)gr1 * ldr + gc + 1]; }
            *(float2*)&C[(size_t)gr1 * ldc + gc] = v1;
        }
    }
}

// ============ FFN GEMM: fp16, 2 terms, 128x256 tile, 3-stage pipe ============
// C = (Ah+Al)@Bh^T [+ R], A fp16 pair, B single fp16 (weights).
// M%128==0, N%256==0, K%64==0. Stage: Ah 16K | Al 16K | Bh 32K = 64KB.
#define STAGEF 65536
#define GTF_SMEM (3*STAGEF)

__global__ __launch_bounds__(256, 1) void gemm_ffn256(
    const __half* __restrict__ Ah, const __half* __restrict__ Al, int lda,
    const __half* __restrict__ Bh, int ldb,
    float* __restrict__ C, int ldc,
    const float* __restrict__ R, int ldr,
    int M, int N, int K, float alpha)
{
    extern __shared__ __align__(1024) char smem[];
    const uint32_t sb0 = smem_u32(smem);
    const int tid = threadIdx.x;
    const int wid = tid >> 5, lane = tid & 31;
    const int bm = blockIdx.y * 128, bn = blockIdx.x * 256;
    const int wm = (wid >> 2) * 64, wn = (wid & 3) * 64;

    float acc[4][8][4];
    #pragma unroll
    for (int i = 0; i < 4; i++)
        #pragma unroll
        for (int j = 0; j < 8; j++)
            #pragma unroll
            for (int r = 0; r < 4; r++) acc[i][j][r] = 0.f;

    const int nc = K >> 6;

    #define ISSUEF(stage, k0) do {                                              \
        uint32_t sbase = sb0 + (stage) * STAGEF;                                \
        _Pragma("unroll")                                                       \
        for (int it = 0; it < 4; it++) {                                        \
            int e = it * 256 + tid;                                             \
            int r = e >> 3, g = e & 7;                                          \
            uint32_t so = SW128(r * 128 + g * 16);                              \
            cpa16(sbase + so,         Ah + (size_t)(bm + r) * lda + (k0) + g * 8, 16);\
            cpa16(sbase + 16384 + so, Al + (size_t)(bm + r) * lda + (k0) + g * 8, 16);\
        }                                                                       \
        _Pragma("unroll")                                                       \
        for (int it = 0; it < 8; it++) {                                        \
            int e = it * 256 + tid;                                             \
            int r = e >> 3, g = e & 7;                                          \
            uint32_t so = SW128(r * 128 + g * 16);                              \
            cpa16(sbase + 32768 + so, Bh + (size_t)(bn + r) * ldb + (k0) + g * 8, 16);\
        }                                                                       \
        cp_commit();                                                            \
    } while (0)

    ISSUEF(0, 0);
    if (nc > 1) ISSUEF(1, 64); else cp_commit();

    const int arow = wm + (lane & 15);
    const int acb  = (lane >> 4) << 4;
    const int brow4 = wn + ((lane >> 4) << 3) + (lane & 7);
    const int bcb4  = ((lane >> 3) & 1) << 4;

    for (int c = 0; c < nc; c++) {
        if (c + 2 < nc) ISSUEF((c + 2) % 3, (c + 2) << 6);
        int after = nc - 1 - c; if (after > 2) after = 2;
        if (after == 2)      cp_wait<2>();
        else if (after == 1) cp_wait<1>();
        else                 cp_wait<0>();
        __syncthreads();

        uint32_t tAh = sb0 + (c % 3) * STAGEF;
        uint32_t tAl = tAh + 16384, tBh = tAh + 32768;

        #pragma unroll
        for (int ks = 0; ks < 4; ks++) {
            uint32_t ah[4][4], al[4][4], bh4[4][4];
            #pragma unroll
            for (int ms = 0; ms < 4; ms++) {
                uint32_t off = SW128((arow + ms * 16) * 128 + ks * 32 + acb);
                ldsm_x4(ah[ms], tAh + off);
                ldsm_x4(al[ms], tAl + off);
            }
            #pragma unroll
            for (int ng4 = 0; ng4 < 4; ng4++) {
                uint32_t off = SW128((brow4 + ng4 * 16) * 128 + ks * 32 + bcb4);
                ldsm_x4(bh4[ng4], tBh + off);
            }
            #pragma unroll
            for (int ng4 = 0; ng4 < 4; ng4++)
                #pragma unroll
                for (int ms = 0; ms < 4; ms++) {
                    mma_f16(acc[ms][2*ng4],   ah[ms], bh4[ng4]);
                    mma_f16(acc[ms][2*ng4],   al[ms], bh4[ng4]);
                    mma_f16(acc[ms][2*ng4+1], ah[ms], bh4[ng4] + 2);
                    mma_f16(acc[ms][2*ng4+1], al[ms], bh4[ng4] + 2);
                }
        }
        __syncthreads();
    }

    const int gid = lane >> 2, tc = lane & 3;
    #pragma unroll
    for (int ms = 0; ms < 4; ms++) {
        #pragma unroll
        for (int ns = 0; ns < 8; ns++) {
            int gr0 = bm + wm + ms * 16 + gid;
            int gc  = bn + wn + ns * 8 + tc * 2;
            float2 v0;
            v0.x = alpha * acc[ms][ns][0];
            v0.y = alpha * acc[ms][ns][1];
            if (R) { v0.x += R[(size_t)gr0 * ldr + gc]; v0.y += R[(size_t)gr0 * ldr + gc + 1]; }
            *(float2*)&C[(size_t)gr0 * ldc + gc] = v0;
            int gr1 = gr0 + 8;
            float2 v1;
            v1.x = alpha * acc[ms][ns][2];
            v1.y = alpha * acc[ms][ns][3];
            if (R) { v1.x += R[(size_t)gr1 * ldr + gc]; v1.y += R[(size_t)gr1 * ldr + gc + 1]; }
            *(float2*)&C[(size_t)gr1 * ldc + gc] = v1;
        }
    }
}

// ------------------------------ host launch ---------------------------------
static void gemm(const __nv_bfloat16* Ah, const __nv_bfloat16* Al, int lda, long long sA,
                 const __nv_bfloat16* Bh, const __nv_bfloat16* Bl, int ldb, long long sB,
                 float* C, int ldc, long long sC,
                 const float* R, int ldr, long long sR,
                 int M, int N, int K, float alpha, int Z, int causal = 0)
{
    if (N % 256 == 0) {
        dim3 grid(N / 256, M / 128, Z);
        gemm_tc256<<<grid, 256, GT2_SMEM>>>(Ah, Al, lda, sA, Bh, Bl, ldb, sB,
                                            C, ldc, sC, R, ldr, sR, M, N, K, alpha, causal);
    } else {
        dim3 grid((N + 127) / 128, M / 128, Z);
        gemm_tc128<<<grid, 256, GT1_SMEM>>>(Ah, Al, lda, sA, Bh, Bl, ldb, sB,
                                            C, ldc, sC, R, ldr, sR, M, N, K, alpha, causal);
    }
}

static void split(const float* in, __nv_bfloat16* hi, __nv_bfloat16* lo, long long n)
{
    long long n4 = n >> 2;
    split_k<<<(unsigned)((n4 + 255) / 256), 256>>>(
        (const float4*)in, (__nv_bfloat162*)hi, (__nv_bfloat162*)lo, n4);
}

extern "C" void kernel_launch(void* const* d_in, const int* in_sizes, int n_in,
                              void* d_out, int out_size)
{
    const float* x     = (const float*)d_in[0];
    const float* mask  = (const float*)d_in[1];
    const float* fcos  = (const float*)d_in[2];
    const float* fsin  = (const float*)d_in[3];
    const float* anw   = (const float*)d_in[4];
    const float* wq_a  = (const float*)d_in[5];
    const float* qnw   = (const float*)d_in[6];
    const float* wq_b  = (const float*)d_in[7];
    const float* wkv_a = (const float*)d_in[8];
    const float* kvnw  = (const float*)d_in[9];
    const float* wkv_b = (const float*)d_in[10];
    const float* wo    = (const float*)d_in[11];
    const float* fnw   = (const float*)d_in[12];
    const float* w1    = (const float*)d_in[13];
    const float* w2    = (const float*)d_in[14];
    const float* w3    = (const float*)d_in[15];
    float* out = (float*)d_out;

    cudaFuncSetAttribute(gemm_tc128, cudaFuncAttributeMaxDynamicSharedMemorySize, GT1_SMEM);
    cudaFuncSetAttribute(gemm_tc256, cudaFuncAttributeMaxDynamicSharedMemorySize, GT2_SMEM);
    cudaFuncSetAttribute(gemm_ffn256, cudaFuncAttributeMaxDynamicSharedMemorySize, GTF_SMEM);

    float *p_qa, *p_q, *p_kva, *p_kv, *p_sc, *p_y, *p_x2, *p_gate, *p_up;
    cudaGetSymbolAddress((void**)&p_qa,  g_qa);
    cudaGetSymbolAddress((void**)&p_q,   g_q);
    cudaGetSymbolAddress((void**)&p_kva, g_kva);
    cudaGetSymbolAddress((void**)&p_kv,  g_kv);
    cudaGetSymbolAddress((void**)&p_sc,  g_sc);
    cudaGetSymbolAddress((void**)&p_y,   g_y);
    cudaGetSymbolAddress((void**)&p_x2,  g_x2);
    cudaGetSymbolAddress((void**)&p_gate,g_gate);
    cudaGetSymbolAddress((void**)&p_up,  g_up);

    __nv_bfloat16 *hH,*hL,*qaH,*qaL,*kvnH,*kvnL,*qfH,*qfL,*kfH,*kfL,*vTH,*vTL,
        *atH,*atL,*y2H,*y2L,
        *wqaH,*wqaL,*wqbH,*wqbL,*wkaH,*wkaL,*wkbH,*wkbL,*woH,*woL;
    __half *w1h,*w2h,*w3h,*h2H,*h2L,*gsH,*gsL;
    cudaGetSymbolAddress((void**)&hH,  b_hH);  cudaGetSymbolAddress((void**)&hL,  b_hL);
    cudaGetSymbolAddress((void**)&qaH, b_qaH); cudaGetSymbolAddress((void**)&qaL, b_qaL);
    cudaGetSymbolAddress((void**)&kvnH,b_kvnH);cudaGetSymbolAddress((void**)&kvnL,b_kvnL);
    cudaGetSymbolAddress((void**)&qfH, b_qfH); cudaGetSymbolAddress((void**)&qfL, b_qfL);
    cudaGetSymbolAddress((void**)&kfH, b_kfH); cudaGetSymbolAddress((void**)&kfL, b_kfL);
    cudaGetSymbolAddress((void**)&vTH, b_vTH); cudaGetSymbolAddress((void**)&vTL, b_vTL);
    cudaGetSymbolAddress((void**)&atH, b_atH); cudaGetSymbolAddress((void**)&atL, b_atL);
    cudaGetSymbolAddress((void**)&y2H, b_y2H); cudaGetSymbolAddress((void**)&y2L, b_y2L);
    cudaGetSymbolAddress((void**)&wqaH,b_wqaH);cudaGetSymbolAddress((void**)&wqaL,b_wqaL);
    cudaGetSymbolAddress((void**)&wqbH,b_wqbH);cudaGetSymbolAddress((void**)&wqbL,b_wqbL);
    cudaGetSymbolAddress((void**)&wkaH,b_wkaH);cudaGetSymbolAddress((void**)&wkaL,b_wkaL);
    cudaGetSymbolAddress((void**)&wkbH,b_wkbH);cudaGetSymbolAddress((void**)&wkbL,b_wkbL);
    cudaGetSymbolAddress((void**)&woH, b_woH); cudaGetSymbolAddress((void**)&woL, b_woL);
    cudaGetSymbolAddress((void**)&w1h, h_w1);  cudaGetSymbolAddress((void**)&w2h, h_w2);
    cudaGetSymbolAddress((void**)&w3h, h_w3);
    cudaGetSymbolAddress((void**)&h2H, h_h2H); cudaGetSymbolAddress((void**)&h2L, h_h2L);
    cudaGetSymbolAddress((void**)&gsH, h_gsH); cudaGetSymbolAddress((void**)&gsL, h_gsL);

    // ---- attention path (splits interleaved with consumers) ----
    // 1) h = rmsnorm(x)
    rmsnorm_split_k<<<CM, 256>>>(x, CD, anw, hH, hL, CD);
    split(wq_a, wqaH, wqaL, (long long)CQLORA*CD);
    // 2) qa = h @ wq_a^T
    gemm(hH, hL, CD, 0, wqaH, wqaL, CD, 0, p_qa, CQLORA, 0,
         nullptr, 0, 0, CM, CQLORA, CD, 1.f, 1);
    // 3) qa_norm
    rmsnorm_split_k<<<CM, 256>>>(p_qa, CQLORA, qnw, qaH, qaL, CQLORA);
    split(wq_b, wqbH, wqbL, (long long)CH*CQKD*CQLORA);
    // 4) q = qa_norm @ wq_b^T
    gemm(qaH, qaL, CQLORA, 0, wqbH, wqbL, CQLORA, 0, p_q, CH*CQKD, 0,
         nullptr, 0, 0, CM, CH*CQKD, CQLORA, 1.f, 1);
    split(wkv_a, wkaH, wkaL, (long long)(CKVLORA+CROPE)*CD);
    // 5) kva = h @ wkv_a^T
    gemm(hH, hL, CD, 0, wkaH, wkaL, CD, 0, p_kva, CKVLORA+CROPE, 0,
         nullptr, 0, 0, CM, CKVLORA+CROPE, CD, 1.f, 1);
    // 6) kv_norm
    rmsnorm_split_k<<<CM, 256>>>(p_kva, CKVLORA+CROPE, kvnw, kvnH, kvnL, CKVLORA);
    split(wkv_b, wkbH, wkbL, (long long)CH*256*CKVLORA);
    // 7) kv = kv_norm @ wkv_b^T
    gemm(kvnH, kvnL, CKVLORA, 0, wkbH, wkbL, CKVLORA, 0, p_kv, CH*256, 0,
         nullptr, 0, 0, CM, CH*256, CKVLORA, 1.f, 1);
    // 8) rope + pack
    rope_pack_split_k<<<dim3(CT, CB), 256>>>(p_q, p_kv, p_kva, fcos, fsin,
                                             qfH, qfL, kfH, kfL, vTH, vTL);
    // 9) scores = -96 * qf @ kf^T + mask (skip fully-masked tiles)
    gemm(qfH, qfL, CQKD, (long long)CT*CQKD,
         kfH, kfL, CQKD, (long long)CT*CQKD,
         p_sc, CT, (long long)CT*CT,
         mask, CT, 0, CT, CT, CQKD, -96.f, CB*CH, 1);
    // 10) softmax
    softmax_split_k<<<CB*CH*CT, 256>>>(p_sc, atH, atL);
    // 11) y = attn @ vT (truncate K at diagonal)
    gemm(atH, atL, CT, (long long)CT*CT,
         vTH, vTL, CT, (long long)CVHD*CT,
         p_y, CVHD, (long long)CT*CVHD,
         nullptr, 0, 0, CT, CVHD, CT, 1.f, CB*CH, 2);
    // 12) permute
    permute_split_k<<<dim3(CT, CB), 256>>>(p_y, y2H, y2L);
    split(wo, woH, woL, (long long)CD*CD);
    // 13) x2 = x + y2 @ wo^T
    gemm(y2H, y2L, CH*CVHD, 0, woH, woL, CH*CVHD, 0, p_x2, CD, 0,
         x, CD, 0, CM, CD, CH*CVHD, 1.f, 1);

    // ---- FFN path (fp16) ----
    // weights -> single fp16 (one fused launch)
    {
        long long n4 = ((long long)CINTER * CD) >> 2;
        dim3 grid((unsigned)((n4 + 255) / 256), 3);
        conv3_h_k<<<grid, 256>>>((const float4*)w1, (const float4*)w2, (const float4*)w3,
                                 (__half2*)w1h, (__half2*)w2h, (__half2*)w3h, n4);
    }
    // 14) h2 = rmsnorm(x2) -> fp16 pair
    rmsnorm_split_h_k<<<CM, 256>>>(p_x2, CD, fnw, h2H, h2L, CD);
    // 15/16) gate = h2 @ w1^T ; up = h2 @ w3^T
    {
        dim3 grid(CINTER / 256, CM / 128);
        gemm_ffn256<<<grid, 256, GTF_SMEM>>>(h2H, h2L, CD, w1h, CD,
                                             p_gate, CINTER, nullptr, 0,
                                             CM, CINTER, CD, 1.f);
        gemm_ffn256<<<grid, 256, GTF_SMEM>>>(h2H, h2L, CD, w3h, CD,
                                             p_up, CINTER, nullptr, 0,
                                             CM, CINTER, CD, 1.f);
    }
    // 17) gs = silu(gate)*up -> fp16 pair
    {
        long long n4 = ((long long)CM * CINTER) >> 2;
        silu_mul_split_h_k<<<(unsigned)((n4 + 255) / 256), 256>>>(
            (const float4*)p_gate, (const float4*)p_up,
            (__half2*)gsH, (__half2*)gsL, n4);
    }
    // 18) out = x2 + gs @ w2^T
    {
        dim3 grid(CD / 256, CM / 128);
        gemm_ffn256<<<grid, 256, GTF_SMEM>>>(gsH, gsL, CINTER, w2h, CINTER,
                                             out, CD, p_x2, CD,
                                             CM, CD, CINTER, 1.f);
    }
}

// round 6
// speedup vs baseline: 5.0003x; 1.3556x over previous
#include <cuda_runtime.h>
#include <cuda_fp16.h>
#include <cstdint>

// ---------------------------------------------------------------------------
// DeepSeek MLA block on GB300 — mma.sync fp16 GEMMs, v4.
// q/k path (qa, q, kva, kv, scores): fp16-pair 3-term split (≈fp32 accurate).
// Additive paths (attn@V, wo, FFN): plain fp16 1-term (diluted rounding).
// ---------------------------------------------------------------------------

#define CB 2
#define CT 1024
#define CD 2048
#define CH 16
#define CNOPE 128
#define CROPE 64
#define CQKD 192
#define CQLORA 1536
#define CKVLORA 512
#define CVHD 128
#define CINTER 8192
#define CM (CB*CT)

// ------------------------------- PTX helpers -------------------------------
__device__ __forceinline__ uint32_t smem_u32(const void* p) {
    uint32_t a;
    asm("{ .reg .u64 t; cvta.to.shared.u64 t, %1; cvt.u32.u64 %0, t; }" : "=r"(a) : "l"(p));
    return a;
}
#define SW128(o) ((o) ^ (((o) >> 3) & 0x70))

__device__ __forceinline__ void cpa16(uint32_t s, const void* g, int sz) {
    asm volatile("cp.async.cg.shared.global [%0], [%1], 16, %2;"
                 :: "r"(s), "l"(g), "r"(sz));
}
__device__ __forceinline__ void cp_commit() {
    asm volatile("cp.async.commit_group;" ::: "memory");
}
template <int N> __device__ __forceinline__ void cp_wait() {
    asm volatile("cp.async.wait_group %0;" :: "n"(N) : "memory");
}
__device__ __forceinline__ void ldsm_x4(uint32_t* r, uint32_t a) {
    asm volatile("ldmatrix.sync.aligned.m8n8.x4.shared.b16 {%0,%1,%2,%3}, [%4];"
        : "=r"(r[0]), "=r"(r[1]), "=r"(r[2]), "=r"(r[3]) : "r"(a));
}
__device__ __forceinline__ void mma_f16(float* d, const uint32_t* a, const uint32_t* b) {
    asm volatile(
        "mma.sync.aligned.m16n8k16.row.col.f32.f16.f16.f32 "
        "{%0,%1,%2,%3}, {%4,%5,%6,%7}, {%8,%9}, {%0,%1,%2,%3};"
        : "+f"(d[0]), "+f"(d[1]), "+f"(d[2]), "+f"(d[3])
        : "r"(a[0]), "r"(a[1]), "r"(a[2]), "r"(a[3]), "r"(b[0]), "r"(b[1]));
}

// ------------------------- scratch (device globals) ------------------------
__device__ float g_qa  [(long long)CM*CQLORA];
__device__ float g_q   [(long long)CM*CH*CQKD];
__device__ float g_kva [(long long)CM*(CKVLORA+CROPE)];
__device__ float g_kv  [(long long)CM*CH*(CNOPE+CVHD)];
__device__ float g_sc  [(long long)CB*CH*CT*CT];
__device__ float g_y   [(long long)CB*CH*CT*CVHD];
__device__ float g_x2  [(long long)CM*CD];
__device__ float g_gate[(long long)CM*CINTER];
__device__ float g_up  [(long long)CM*CINTER];

// fp16 operand buffers (pairs where 3-term, single otherwise)
__device__ __half f_hH [(long long)CM*CD],        f_hL [(long long)CM*CD];
__device__ __half f_qaH[(long long)CM*CQLORA],    f_qaL[(long long)CM*CQLORA];
__device__ __half f_kvnH[(long long)CM*CKVLORA],  f_kvnL[(long long)CM*CKVLORA];
__device__ __half f_qfH[(long long)CB*CH*CT*CQKD], f_qfL[(long long)CB*CH*CT*CQKD];
__device__ __half f_kfH[(long long)CB*CH*CT*CQKD], f_kfL[(long long)CB*CH*CT*CQKD];
__device__ __half f_vT [(long long)CB*CH*CVHD*CT];
__device__ __half f_at [(long long)CB*CH*CT*CT];
__device__ __half f_y2 [(long long)CM*CD];
__device__ __half f_h2 [(long long)CM*CD];
__device__ __half f_gs [(long long)CM*CINTER];
// weights
__device__ __half f_wqaH[(long long)CQLORA*CD],   f_wqaL[(long long)CQLORA*CD];
__device__ __half f_wqbH[(long long)CH*CQKD*CQLORA], f_wqbL[(long long)CH*CQKD*CQLORA];
__device__ __half f_wkaH[(long long)(CKVLORA+CROPE)*CD], f_wkaL[(long long)(CKVLORA+CROPE)*CD];
__device__ __half f_wkbH[(long long)CH*256*CKVLORA], f_wkbL[(long long)CH*256*CKVLORA];
__device__ __half f_wo [(long long)CD*CD];
__device__ __half f_w1 [(long long)CINTER*CD];
__device__ __half f_w2 [(long long)CD*CINTER];
__device__ __half f_w3 [(long long)CINTER*CD];

// ------------------------------- split helpers -----------------------------
__device__ __forceinline__ void split1h(float v, __half& h, __half& l) {
    h = __float2half_rn(v);
    l = __float2half_rn(v - __half2float(h));
}

__global__ __launch_bounds__(256) void split_h_k(
    const float4* __restrict__ in, __half2* __restrict__ hi,
    __half2* __restrict__ lo, long long n4)
{
    long long i = (long long)blockIdx.x * 256 + threadIdx.x;
    if (i >= n4) return;
    float4 v = in[i];
    __half h0,h1,h2,h3,l0,l1,l2,l3;
    split1h(v.x,h0,l0); split1h(v.y,h1,l1); split1h(v.z,h2,l2); split1h(v.w,h3,l3);
    hi[2*i]   = __halves2half2(h0,h1);
    hi[2*i+1] = __halves2half2(h2,h3);
    lo[2*i]   = __halves2half2(l0,l1);
    lo[2*i+1] = __halves2half2(l2,l3);
}

__global__ __launch_bounds__(256) void conv_h_k(
    const float4* __restrict__ in, __half2* __restrict__ out, long long n4)
{
    long long i = (long long)blockIdx.x * 256 + threadIdx.x;
    if (i >= n4) return;
    float4 v = in[i];
    out[2*i]   = __floats2half2_rn(v.x, v.y);
    out[2*i+1] = __floats2half2_rn(v.z, v.w);
}

// fused fp16 conversion of w1, w2, w3 (same element counts)
__global__ __launch_bounds__(256) void conv3_h_k(
    const float4* __restrict__ s0, const float4* __restrict__ s1,
    const float4* __restrict__ s2,
    __half2* __restrict__ d0, __half2* __restrict__ d1, __half2* __restrict__ d2,
    long long n4)
{
    long long i = (long long)blockIdx.x * 256 + threadIdx.x;
    if (i >= n4) return;
    const float4* s = (blockIdx.y == 0) ? s0 : (blockIdx.y == 1) ? s1 : s2;
    __half2* d = (blockIdx.y == 0) ? d0 : (blockIdx.y == 1) ? d1 : d2;
    float4 v = s[i];
    d[2*i]   = __floats2half2_rn(v.x, v.y);
    d[2*i+1] = __floats2half2_rn(v.z, v.w);
}

// ------------------------------ RMSNorm variants ----------------------------
__device__ __forceinline__ float rms_scale(const float* ip, int K, int tid) {
    float s = 0.f;
    for (int i = tid; i < K; i += 256) { float v = ip[i]; s += v * v; }
    __shared__ float red[32];
    #pragma unroll
    for (int o = 16; o > 0; o >>= 1) s += __shfl_xor_sync(0xffffffffu, s, o);
    int warp = tid >> 5, lane = tid & 31;
    if (lane == 0) red[warp] = s;
    __syncthreads();
    if (warp == 0) {
        float s2 = (lane < 8) ? red[lane] : 0.f;
        #pragma unroll
        for (int o = 4; o > 0; o >>= 1) s2 += __shfl_xor_sync(0xffffffffu, s2, o);
        if (lane == 0) red[0] = s2;
    }
    __syncthreads();
    return rsqrtf(red[0] / (float)K + 1e-6f);
}

__global__ __launch_bounds__(256) void rmsnorm_split_h_k(
    const float* __restrict__ in, int ldin, const float* __restrict__ w,
    __half* __restrict__ hi, __half* __restrict__ lo, int K)
{
    long long row = blockIdx.x;
    const float* ip = in + row * ldin;
    float scale = rms_scale(ip, K, threadIdx.x);
    for (int i = threadIdx.x; i < K; i += 256) {
        float v = ip[i] * scale * w[i];
        __half h, l; split1h(v, h, l);
        hi[row * (long long)K + i] = h;
        lo[row * (long long)K + i] = l;
    }
}

__global__ __launch_bounds__(256) void rmsnorm_h_k(
    const float* __restrict__ in, int ldin, const float* __restrict__ w,
    __half* __restrict__ out, int K)
{
    long long row = blockIdx.x;
    const float* ip = in + row * ldin;
    float scale = rms_scale(ip, K, threadIdx.x);
    for (int i = threadIdx.x; i < K; i += 256)
        out[row * (long long)K + i] = __float2half_rn(ip[i] * scale * w[i]);
}

// ------------------- RoPE + head packing (qf/kf pairs, vT single) -----------
__global__ __launch_bounds__(256) void rope_pack_h_k(
    const float* __restrict__ q, const float* __restrict__ kv,
    const float* __restrict__ kva,
    const float* __restrict__ fcos, const float* __restrict__ fsin,
    __half* __restrict__ qfH, __half* __restrict__ qfL,
    __half* __restrict__ kfH, __half* __restrict__ kfL,
    __half* __restrict__ vT)
{
    int t = blockIdx.x, b = blockIdx.y;
    long long m = (long long)b * CT + t;
    __shared__ float kpe[CROPE], cs[32], sn[32];
    int tid = threadIdx.x;
    if (tid < 32) { cs[tid] = fcos[t*32 + tid]; sn[tid] = fsin[t*32 + tid]; }
    __syncthreads();
    if (tid < 32) {
        float x0 = kva[m*576 + 512 + 2*tid];
        float x1 = kva[m*576 + 512 + 2*tid + 1];
        kpe[2*tid]   = x0*cs[tid] - x1*sn[tid];
        kpe[2*tid+1] = x0*sn[tid] + x1*cs[tid];
    }
    __syncthreads();
    for (int idx = tid; idx < CH*CQKD; idx += 256) {
        int h = idx / CQKD, d = idx % CQKD;
        long long o = (((long long)b*CH + h)*CT + t)*CQKD + d;
        float qv, kvv;
        if (d < CNOPE) {
            qv  = q [m*(CH*CQKD) + h*CQKD + d];
            kvv = kv[m*(CH*256)  + h*256  + d];
        } else {
            int j = d - CNOPE, i2 = j >> 1;
            float x0 = q[m*(CH*CQKD) + h*CQKD + CNOPE + 2*i2];
            float x1 = q[m*(CH*CQKD) + h*CQKD + CNOPE + 2*i2 + 1];
            qv  = (j & 1) ? (x0*sn[i2] + x1*cs[i2]) : (x0*cs[i2] - x1*sn[i2]);
            kvv = kpe[j];
        }
        __half hh, ll;
        split1h(qv, hh, ll);  qfH[o] = hh; qfL[o] = ll;
        split1h(kvv, hh, ll); kfH[o] = hh; kfL[o] = ll;
    }
    for (int idx = tid; idx < CH*CVHD; idx += 256) {
        int h = idx >> 7, d = idx & 127;
        vT[(((long long)b*CH + h)*CVHD + d)*CT + t] =
            __float2half_rn(kv[m*(CH*256) + h*256 + CNOPE + d]);
    }
}

// ------------------------------ Softmax (fp16 out) --------------------------
__global__ __launch_bounds__(256) void softmax_h_k(
    const float* __restrict__ s, __half* __restrict__ at)
{
    long long row = blockIdx.x;
    const float4* p = (const float4*)(s + row * (long long)CT);
    int tid = threadIdx.x, warp = tid >> 5, lane = tid & 31;
    __shared__ float red[32];

    float4 v = p[tid];
    float mx = fmaxf(fmaxf(v.x, v.y), fmaxf(v.z, v.w));
    #pragma unroll
    for (int o = 16; o > 0; o >>= 1) mx = fmaxf(mx, __shfl_xor_sync(0xffffffffu, mx, o));
    if (lane == 0) red[warp] = mx;
    __syncthreads();
    if (warp == 0) {
        float m2 = (lane < 8) ? red[lane] : -1e30f;
        #pragma unroll
        for (int o = 4; o > 0; o >>= 1) m2 = fmaxf(m2, __shfl_xor_sync(0xffffffffu, m2, o));
        if (lane == 0) red[0] = m2;
    }
    __syncthreads();
    mx = red[0];
    __syncthreads();

    v.x = __expf(v.x - mx); v.y = __expf(v.y - mx);
    v.z = __expf(v.z - mx); v.w = __expf(v.w - mx);
    float sum = v.x + v.y + v.z + v.w;
    #pragma unroll
    for (int o = 16; o > 0; o >>= 1) sum += __shfl_xor_sync(0xffffffffu, sum, o);
    if (lane == 0) red[warp] = sum;
    __syncthreads();
    if (warp == 0) {
        float s2 = (lane < 8) ? red[lane] : 0.f;
        #pragma unroll
        for (int o = 4; o > 0; o >>= 1) s2 += __shfl_xor_sync(0xffffffffu, s2, o);
        if (lane == 0) red[0] = s2;
    }
    __syncthreads();
    float inv = 1.f / red[0];
    __half2* H = (__half2*)(at + row * (long long)CT);
    H[2*tid]   = __floats2half2_rn(v.x * inv, v.y * inv);
    H[2*tid+1] = __floats2half2_rn(v.z * inv, v.w * inv);
}

// ------------------- permute y [B,H,T,VHD] -> fp16 [B*T, H*VHD] -------------
__global__ __launch_bounds__(256) void permute_h_k(
    const float* __restrict__ y, __half* __restrict__ y2)
{
    int t = blockIdx.x, b = blockIdx.y;
    for (int idx = threadIdx.x; idx < CH*CVHD; idx += 256) {
        int h = idx >> 7, d = idx & 127;
        y2[((long long)b*CT + t)*(CH*CVHD) + idx] =
            __float2half_rn(y[(((long long)b*CH + h)*CT + t)*CVHD + d]);
    }
}

// --------------------------- SiLU(gate)*up (fp16 out) ------------------------
__global__ __launch_bounds__(256) void silu_mul_h_k(
    const float4* __restrict__ g, const float4* __restrict__ u,
    __half2* __restrict__ gs, long long n4)
{
    long long i = (long long)blockIdx.x * 256 + threadIdx.x;
    if (i >= n4) return;
    float4 gv = g[i], uv = u[i];
    float r0 = gv.x / (1.f + __expf(-gv.x)) * uv.x;
    float r1 = gv.y / (1.f + __expf(-gv.y)) * uv.y;
    float r2 = gv.z / (1.f + __expf(-gv.z)) * uv.z;
    float r3 = gv.w / (1.f + __expf(-gv.w)) * uv.w;
    gs[2*i]   = __floats2half2_rn(r0, r1);
    gs[2*i+1] = __floats2half2_rn(r2, r3);
}

// ======================= templated fp16 HMMA GEMM ===========================
// TERMS=3: C = alpha*(Ah@Bh + Ah@Bl + Al@Bh) [+R]  (A,B fp16 pairs)
// TERMS=1: C = alpha*(Ah@Bh) [+R]                  (A,B single fp16)
// A: [M,K] row-major, B: [N,K] row-major. K%64==0, M%128==0.
// CTA 256 threads, tile 128xBN, warp tile 64x(BN/4).
// causal: 1 = write R & skip when bn > bm+127;  2 = truncate K at bm+128.

template<int TERMS, int BN>
__device__ __forceinline__ void issue_h(
    uint32_t sbase, const __half* Ah, const __half* Al,
    const __half* Bh, const __half* Bl,
    int lda, int ldb, int bm, int bn, int M, int N, int k0, int tid)
{
    constexpr int OPS = (TERMS == 3) ? 2 : 1;
    constexpr int ABYTES = 16384 * OPS;
    constexpr int NBT = BN / 128;
    #pragma unroll
    for (int it = 0; it < 4; it++) {
        int e = it * 256 + tid;
        int r = e >> 3, g = e & 7;
        uint32_t so = SW128(r * 128 + g * 16);
        int ra = bm + r; int pa = (ra < M) ? 16 : 0; if (!pa) ra = 0;
        cpa16(sbase + so, Ah + (size_t)ra * lda + k0 + g * 8, pa);
        if constexpr (TERMS == 3)
            cpa16(sbase + 16384 + so, Al + (size_t)ra * lda + k0 + g * 8, pa);
    }
    #pragma unroll
    for (int it = 0; it < 4 * NBT; it++) {
        int e = it * 256 + tid;
        int r = e >> 3, g = e & 7;
        uint32_t so = SW128(r * 128 + g * 16);
        int rb = bn + r; int pb = (rb < N) ? 16 : 0; if (!pb) rb = 0;
        cpa16(sbase + ABYTES + so, Bh + (size_t)rb * ldb + k0 + g * 8, pb);
        if constexpr (TERMS == 3)
            cpa16(sbase + ABYTES + NBT * 16384 + so, Bl + (size_t)rb * ldb + k0 + g * 8, pb);
    }
    cp_commit();
}

template<int TERMS, int BN>
__global__ __launch_bounds__(256, 1) void gemm_h(
    const __half* __restrict__ Ah, const __half* __restrict__ Al,
    int lda, long long sA,
    const __half* __restrict__ Bh, const __half* __restrict__ Bl,
    int ldb, long long sB,
    float* __restrict__ C, int ldc, long long sC,
    const float* __restrict__ R, int ldr, long long sR,
    int M, int N, int K, float alpha, int causal)
{
    constexpr int OPS = (TERMS == 3) ? 2 : 1;
    constexpr int ABYTES = 16384 * OPS;
    constexpr int NBT = BN / 128;
    constexpr int STAGE = ABYTES + NBT * 16384 * OPS;
    constexpr int NST = (TERMS == 1) ? 4 : ((BN == 128) ? 3 : 2);
    constexpr int NG4 = BN / 64;   // 16-col B groups per warp
    constexpr int NS  = BN / 32;   // 8-col accum groups per warp

    extern __shared__ __align__(1024) char smem[];
    const uint32_t sb0 = smem_u32(smem);
    const int tid = threadIdx.x;
    const int wid = tid >> 5, lane = tid & 31;
    long long z = blockIdx.z;
    Ah += z * sA;
    if constexpr (TERMS == 3) Al += z * sA;
    Bh += z * sB;
    if constexpr (TERMS == 3) Bl += z * sB;
    C += z * sC;
    if (R) R += z * sR;
    const int bm = blockIdx.y * 128, bn = blockIdx.x * BN;
    const int wm = (wid >> 2) * 64, wn = (wid & 3) * (BN / 4);

    if (causal == 1 && bn > bm + 127) {
        for (int idx = tid; idx < 128 * (BN / 4); idx += 256) {
            int r = idx / (BN / 4), cg = (idx % (BN / 4)) * 4;
            int gm = bm + r, gn = bn + cg;
            *(float4*)&C[(size_t)gm * ldc + gn] = *(const float4*)&R[(size_t)gm * ldr + gn];
        }
        return;
    }

    float acc[4][NS][4];
    #pragma unroll
    for (int i = 0; i < 4; i++)
        #pragma unroll
        for (int j = 0; j < NS; j++)
            #pragma unroll
            for (int r = 0; r < 4; r++) acc[i][j][r] = 0.f;

    int nc = K >> 6;
    if (causal == 2) { int lim = (bm + 191) >> 6; if (lim < nc) nc = lim; }

    #pragma unroll
    for (int s = 0; s < NST - 1; s++) {
        if (s < nc)
            issue_h<TERMS, BN>(sb0 + s * STAGE, Ah, Al, Bh, Bl, lda, ldb, bm, bn, M, N, s << 6, tid);
        else
            cp_commit();
    }

    const int arow = wm + (lane & 15);
    const int acb  = (lane >> 4) << 4;
    const int brow4 = wn + ((lane >> 4) << 3) + (lane & 7);
    const int bcb4  = ((lane >> 3) & 1) << 4;

    for (int c = 0; c < nc; c++) {
        if (c + NST - 1 < nc)
            issue_h<TERMS, BN>(sb0 + ((c + NST - 1) % NST) * STAGE, Ah, Al, Bh, Bl,
                               lda, ldb, bm, bn, M, N, (c + NST - 1) << 6, tid);
        int after = nc - 1 - c; if (after > NST - 1) after = NST - 1;
        if (after == 0)      cp_wait<0>();
        else if (after == 1) cp_wait<1>();
        else if (after == 2) cp_wait<2>();
        else                 cp_wait<3>();
        __syncthreads();

        uint32_t tA  = sb0 + (c % NST) * STAGE;
        uint32_t tAl = tA + 16384;
        uint32_t tB  = tA + ABYTES;
        uint32_t tBl = tB + NBT * 16384;

        #pragma unroll
        for (int ks = 0; ks < 4; ks++) {
            uint32_t ah[4][4], al[4][4];
            #pragma unroll
            for (int ms = 0; ms < 4; ms++) {
                uint32_t off = SW128((arow + ms * 16) * 128 + ks * 32 + acb);
                ldsm_x4(ah[ms], tA + off);
                if constexpr (TERMS == 3) ldsm_x4(al[ms], tAl + off);
            }
            #pragma unroll
            for (int ng4 = 0; ng4 < NG4; ng4++) {
                uint32_t bh4[4], bl4[4];
                uint32_t off = SW128((brow4 + ng4 * 16) * 128 + ks * 32 + bcb4);
                ldsm_x4(bh4, tB + off);
                if constexpr (TERMS == 3) ldsm_x4(bl4, tBl + off);
                #pragma unroll
                for (int ms = 0; ms < 4; ms++) {
                    mma_f16(acc[ms][2*ng4], ah[ms], bh4);
                    if constexpr (TERMS == 3) {
                        mma_f16(acc[ms][2*ng4], ah[ms], bl4);
                        mma_f16(acc[ms][2*ng4], al[ms], bh4);
                    }
                    mma_f16(acc[ms][2*ng4+1], ah[ms], bh4 + 2);
                    if constexpr (TERMS == 3) {
                        mma_f16(acc[ms][2*ng4+1], ah[ms], bl4 + 2);
                        mma_f16(acc[ms][2*ng4+1], al[ms], bh4 + 2);
                    }
                }
            }
        }
        __syncthreads();
    }

    const int gid = lane >> 2, tc = lane & 3;
    #pragma unroll
    for (int ms = 0; ms < 4; ms++) {
        #pragma unroll
        for (int ns = 0; ns < NS; ns++) {
            int gr0 = bm + wm + ms * 16 + gid;
            int gc  = bn + wn + ns * 8 + tc * 2;
            if (gc < N) {
                float2 v0;
                v0.x = alpha * acc[ms][ns][0];
                v0.y = alpha * acc[ms][ns][1];
                if (R) { v0.x += R[(size_t)gr0 * ldr + gc]; v0.y += R[(size_t)gr0 * ldr + gc + 1]; }
                *(float2*)&C[(size_t)gr0 * ldc + gc] = v0;
                int gr1 = gr0 + 8;
                float2 v1;
                v1.x = alpha * acc[ms][ns][2];
                v1.y = alpha * acc[ms][ns][3];
                if (R) { v1.x += R[(size_t)gr1 * ldr + gc]; v1.y += R[(size_t)gr1 * ldr + gc + 1]; }
                *(float2*)&C[(size_t)gr1 * ldc + gc] = v1;
            }
        }
    }
}

// smem sizes per instantiation
#define SM_3_256 (2*(32768+65536))   // 196608
#define SM_3_128 (3*(32768+32768))   // 196608
#define SM_1_256 (4*(16384+32768))   // 196608
#define SM_1_128 (4*(16384+16384))   // 131072

// ------------------------------ host launch ---------------------------------
static void gemm3(const __half* Ah, const __half* Al, int lda, long long sA,
                  const __half* Bh, const __half* Bl, int ldb, long long sB,
                  float* C, int ldc, long long sC,
                  const float* R, int ldr, long long sR,
                  int M, int N, int K, float alpha, int Z, int causal = 0)
{
    if (N % 256 == 0) {
        dim3 grid(N / 256, M / 128, Z);
        gemm_h<3,256><<<grid, 256, SM_3_256>>>(Ah, Al, lda, sA, Bh, Bl, ldb, sB,
                                               C, ldc, sC, R, ldr, sR, M, N, K, alpha, causal);
    } else {
        dim3 grid((N + 127) / 128, M / 128, Z);
        gemm_h<3,128><<<grid, 256, SM_3_128>>>(Ah, Al, lda, sA, Bh, Bl, ldb, sB,
                                               C, ldc, sC, R, ldr, sR, M, N, K, alpha, causal);
    }
}
static void gemm1(const __half* A, int lda, long long sA,
                  const __half* B, int ldb, long long sB,
                  float* C, int ldc, long long sC,
                  const float* R, int ldr, long long sR,
                  int M, int N, int K, float alpha, int Z, int causal = 0)
{
    if (N % 256 == 0) {
        dim3 grid(N / 256, M / 128, Z);
        gemm_h<1,256><<<grid, 256, SM_1_256>>>(A, nullptr, lda, sA, B, nullptr, ldb, sB,
                                               C, ldc, sC, R, ldr, sR, M, N, K, alpha, causal);
    } else {
        dim3 grid((N + 127) / 128, M / 128, Z);
        gemm_h<1,128><<<grid, 256, SM_1_128>>>(A, nullptr, lda, sA, B, nullptr, ldb, sB,
                                               C, ldc, sC, R, ldr, sR, M, N, K, alpha, causal);
    }
}

static void splitp(const float* in, __half* hi, __half* lo, long long n)
{
    long long n4 = n >> 2;
    split_h_k<<<(unsigned)((n4 + 255) / 256), 256>>>(
        (const float4*)in, (__half2*)hi, (__half2*)lo, n4);
}

extern "C" void kernel_launch(void* const* d_in, const int* in_sizes, int n_in,
                              void* d_out, int out_size)
{
    const float* x     = (const float*)d_in[0];
    const float* mask  = (const float*)d_in[1];
    const float* fcos  = (const float*)d_in[2];
    const float* fsin  = (const float*)d_in[3];
    const float* anw   = (const float*)d_in[4];
    const float* wq_a  = (const float*)d_in[5];
    const float* qnw   = (const float*)d_in[6];
    const float* wq_b  = (const float*)d_in[7];
    const float* wkv_a = (const float*)d_in[8];
    const float* kvnw  = (const float*)d_in[9];
    const float* wkv_b = (const float*)d_in[10];
    const float* wo    = (const float*)d_in[11];
    const float* fnw   = (const float*)d_in[12];
    const float* w1    = (const float*)d_in[13];
    const float* w2    = (const float*)d_in[14];
    const float* w3    = (const float*)d_in[15];
    float* out = (float*)d_out;

    cudaFuncSetAttribute(gemm_h<3,256>, cudaFuncAttributeMaxDynamicSharedMemorySize, SM_3_256);
    cudaFuncSetAttribute(gemm_h<3,128>, cudaFuncAttributeMaxDynamicSharedMemorySize, SM_3_128);
    cudaFuncSetAttribute(gemm_h<1,256>, cudaFuncAttributeMaxDynamicSharedMemorySize, SM_1_256);
    cudaFuncSetAttribute(gemm_h<1,128>, cudaFuncAttributeMaxDynamicSharedMemorySize, SM_1_128);

    float *p_qa, *p_q, *p_kva, *p_kv, *p_sc, *p_y, *p_x2, *p_gate, *p_up;
    cudaGetSymbolAddress((void**)&p_qa,  g_qa);
    cudaGetSymbolAddress((void**)&p_q,   g_q);
    cudaGetSymbolAddress((void**)&p_kva, g_kva);
    cudaGetSymbolAddress((void**)&p_kv,  g_kv);
    cudaGetSymbolAddress((void**)&p_sc,  g_sc);
    cudaGetSymbolAddress((void**)&p_y,   g_y);
    cudaGetSymbolAddress((void**)&p_x2,  g_x2);
    cudaGetSymbolAddress((void**)&p_gate,g_gate);
    cudaGetSymbolAddress((void**)&p_up,  g_up);

    __half *hH,*hL,*qaH,*qaL,*kvnH,*kvnL,*qfH,*qfL,*kfH,*kfL,*vT,*at,*y2,*h2,*gs,
           *wqaH,*wqaL,*wqbH,*wqbL,*wkaH,*wkaL,*wkbH,*wkbL,*woh,*w1h,*w2h,*w3h;
    cudaGetSymbolAddress((void**)&hH,  f_hH);  cudaGetSymbolAddress((void**)&hL,  f_hL);
    cudaGetSymbolAddress((void**)&qaH, f_qaH); cudaGetSymbolAddress((void**)&qaL, f_qaL);
    cudaGetSymbolAddress((void**)&kvnH,f_kvnH);cudaGetSymbolAddress((void**)&kvnL,f_kvnL);
    cudaGetSymbolAddress((void**)&qfH, f_qfH); cudaGetSymbolAddress((void**)&qfL, f_qfL);
    cudaGetSymbolAddress((void**)&kfH, f_kfH); cudaGetSymbolAddress((void**)&kfL, f_kfL);
    cudaGetSymbolAddress((void**)&vT,  f_vT);  cudaGetSymbolAddress((void**)&at,  f_at);
    cudaGetSymbolAddress((void**)&y2,  f_y2);  cudaGetSymbolAddress((void**)&h2,  f_h2);
    cudaGetSymbolAddress((void**)&gs,  f_gs);
    cudaGetSymbolAddress((void**)&wqaH,f_wqaH);cudaGetSymbolAddress((void**)&wqaL,f_wqaL);
    cudaGetSymbolAddress((void**)&wqbH,f_wqbH);cudaGetSymbolAddress((void**)&wqbL,f_wqbL);
    cudaGetSymbolAddress((void**)&wkaH,f_wkaH);cudaGetSymbolAddress((void**)&wkaL,f_wkaL);
    cudaGetSymbolAddress((void**)&wkbH,f_wkbH);cudaGetSymbolAddress((void**)&wkbL,f_wkbL);
    cudaGetSymbolAddress((void**)&woh, f_wo);
    cudaGetSymbolAddress((void**)&w1h, f_w1);  cudaGetSymbolAddress((void**)&w2h, f_w2);
    cudaGetSymbolAddress((void**)&w3h, f_w3);

    // ---- attention path (q/k path 3-term) ----
    // 1) h = rmsnorm(x) -> fp16 pair
    rmsnorm_split_h_k<<<CM, 256>>>(x, CD, anw, hH, hL, CD);
    splitp(wq_a, wqaH, wqaL, (long long)CQLORA*CD);
    // 2) qa = h @ wq_a^T
    gemm3(hH, hL, CD, 0, wqaH, wqaL, CD, 0, p_qa, CQLORA, 0,
          nullptr, 0, 0, CM, CQLORA, CD, 1.f, 1);
    // 3) qa_norm -> pair
    rmsnorm_split_h_k<<<CM, 256>>>(p_qa, CQLORA, qnw, qaH, qaL, CQLORA);
    splitp(wq_b, wqbH, wqbL, (long long)CH*CQKD*CQLORA);
    // 4) q = qa_norm @ wq_b^T      <-- ncu -s 5 lands here
    gemm3(qaH, qaL, CQLORA, 0, wqbH, wqbL, CQLORA, 0, p_q, CH*CQKD, 0,
          nullptr, 0, 0, CM, CH*CQKD, CQLORA, 1.f, 1);
    splitp(wkv_a, wkaH, wkaL, (long long)(CKVLORA+CROPE)*CD);
    // 5) kva = h @ wkv_a^T  (N=576 -> 128-wide kernel)
    gemm3(hH, hL, CD, 0, wkaH, wkaL, CD, 0, p_kva, CKVLORA+CROPE, 0,
          nullptr, 0, 0, CM, CKVLORA+CROPE, CD, 1.f, 1);
    // 6) kv_norm -> pair
    rmsnorm_split_h_k<<<CM, 256>>>(p_kva, CKVLORA+CROPE, kvnw, kvnH, kvnL, CKVLORA);
    splitp(wkv_b, wkbH, wkbL, (long long)CH*256*CKVLORA);
    // 7) kv = kv_norm @ wkv_b^T
    gemm3(kvnH, kvnL, CKVLORA, 0, wkbH, wkbL, CKVLORA, 0, p_kv, CH*256, 0,
          nullptr, 0, 0, CM, CH*256, CKVLORA, 1.f, 1);
    // 8) rope + pack (qf/kf pairs, vT single)
    rope_pack_h_k<<<dim3(CT, CB), 256>>>(p_q, p_kv, p_kva, fcos, fsin,
                                         qfH, qfL, kfH, kfL, vT);
    // 9) scores = -96 * qf @ kf^T + mask (skip fully-masked tiles)
    gemm3(qfH, qfL, CQKD, (long long)CT*CQKD,
          kfH, kfL, CQKD, (long long)CT*CQKD,
          p_sc, CT, (long long)CT*CT,
          mask, CT, 0, CT, CT, CQKD, -96.f, CB*CH, 1);
    // 10) softmax -> attn single fp16
    softmax_h_k<<<CB*CH*CT, 256>>>(p_sc, at);
    // 11) y = attn @ vT  (1-term, truncate K at diagonal)
    gemm1(at, CT, (long long)CT*CT,
          vT, CT, (long long)CVHD*CT,
          p_y, CVHD, (long long)CT*CVHD,
          nullptr, 0, 0, CT, CVHD, CT, 1.f, CB*CH, 2);
    // 12) permute -> y2 single fp16
    permute_h_k<<<dim3(CT, CB), 256>>>(p_y, y2);
    {
        long long n4 = ((long long)CD * CD) >> 2;
        conv_h_k<<<(unsigned)((n4 + 255) / 256), 256>>>((const float4*)wo, (__half2*)woh, n4);
    }
    // 13) x2 = x + y2 @ wo^T  (1-term)
    gemm1(y2, CH*CVHD, 0, woh, CH*CVHD, 0, p_x2, CD, 0,
          x, CD, 0, CM, CD, CH*CVHD, 1.f, 1);

    // ---- FFN path (1-term fp16) ----
    {
        long long n4 = ((long long)CINTER * CD) >> 2;
        dim3 grid((unsigned)((n4 + 255) / 256), 3);
        conv3_h_k<<<grid, 256>>>((const float4*)w1, (const float4*)w2, (const float4*)w3,
                                 (__half2*)w1h, (__half2*)w2h, (__half2*)w3h, n4);
    }
    // 14) h2 = rmsnorm(x2) -> single fp16
    rmsnorm_h_k<<<CM, 256>>>(p_x2, CD, fnw, h2, CD);
    // 15/16) gate = h2 @ w1^T ; up = h2 @ w3^T
    gemm1(h2, CD, 0, w1h, CD, 0, p_gate, CINTER, 0,
          nullptr, 0, 0, CM, CINTER, CD, 1.f, 1);
    gemm1(h2, CD, 0, w3h, CD, 0, p_up, CINTER, 0,
          nullptr, 0, 0, CM, CINTER, CD, 1.f, 1);
    // 17) gs = silu(gate)*up -> single fp16
    {
        long long n4 = ((long long)CM * CINTER) >> 2;
        silu_mul_h_k<<<(unsigned)((n4 + 255) / 256), 256>>>(
            (const float4*)p_gate, (const float4*)p_up, (__half2*)gs, n4);
    }
    // 18) out = x2 + gs @ w2^T
    gemm1(gs, CINTER, 0, w2h, CINTER, 0, out, CD, 0,
          p_x2, CD, 0, CM, CD, CINTER, 1.f, 1);
}

// round 7
// speedup vs baseline: 5.4809x; 1.0961x over previous
#include <cuda_runtime.h>
#include <cuda_fp16.h>
#include <cstdint>

// ---------------------------------------------------------------------------
// DeepSeek MLA block on GB300 — mma.sync fp16 GEMMs, v5.
// q/k path: fp16-pair 3-term split. Additive paths: 1-term fp16.
// v5: single-sync mainloop, batched gate/up, merged qa/kva, causal softmax,
//     fp16 attn@V output.
// ---------------------------------------------------------------------------

#define CB 2
#define CT 1024
#define CD 2048
#define CH 16
#define CNOPE 128
#define CROPE 64
#define CQKD 192
#define CQLORA 1536
#define CKVLORA 512
#define CVHD 128
#define CINTER 8192
#define CM (CB*CT)
#define NQKVA (CQLORA + CKVLORA + CROPE)   // 2112

// ------------------------------- PTX helpers -------------------------------
__device__ __forceinline__ uint32_t smem_u32(const void* p) {
    uint32_t a;
    asm("{ .reg .u64 t; cvta.to.shared.u64 t, %1; cvt.u32.u64 %0, t; }" : "=r"(a) : "l"(p));
    return a;
}
#define SW128(o) ((o) ^ (((o) >> 3) & 0x70))

__device__ __forceinline__ void cpa16(uint32_t s, const void* g, int sz) {
    asm volatile("cp.async.cg.shared.global [%0], [%1], 16, %2;"
                 :: "r"(s), "l"(g), "r"(sz));
}
__device__ __forceinline__ void cp_commit() {
    asm volatile("cp.async.commit_group;" ::: "memory");
}
template <int N> __device__ __forceinline__ void cp_wait() {
    asm volatile("cp.async.wait_group %0;" :: "n"(N) : "memory");
}
__device__ __forceinline__ void ldsm_x4(uint32_t* r, uint32_t a) {
    asm volatile("ldmatrix.sync.aligned.m8n8.x4.shared.b16 {%0,%1,%2,%3}, [%4];"
        : "=r"(r[0]), "=r"(r[1]), "=r"(r[2]), "=r"(r[3]) : "r"(a));
}
__device__ __forceinline__ void mma_f16(float* d, const uint32_t* a, const uint32_t* b) {
    asm volatile(
        "mma.sync.aligned.m16n8k16.row.col.f32.f16.f16.f32 "
        "{%0,%1,%2,%3}, {%4,%5,%6,%7}, {%8,%9}, {%0,%1,%2,%3};"
        : "+f"(d[0]), "+f"(d[1]), "+f"(d[2]), "+f"(d[3])
        : "r"(a[0]), "r"(a[1]), "r"(a[2]), "r"(a[3]), "r"(b[0]), "r"(b[1]));
}

// ------------------------- scratch (device globals) ------------------------
__device__ float g_qkva[(long long)CM*NQKVA];
__device__ float g_q   [(long long)CM*CH*CQKD];
__device__ float g_kv  [(long long)CM*CH*(CNOPE+CVHD)];
__device__ float g_sc  [(long long)CB*CH*CT*CT];
__device__ float g_x2  [(long long)CM*CD];
__device__ float g_gu  [(long long)2*CM*CINTER];   // [0]=gate, [1]=up

// fp16 operand buffers
__device__ __half f_hH [(long long)CM*CD],        f_hL [(long long)CM*CD];
__device__ __half f_qaH[(long long)CM*CQLORA],    f_qaL[(long long)CM*CQLORA];
__device__ __half f_kvnH[(long long)CM*CKVLORA],  f_kvnL[(long long)CM*CKVLORA];
__device__ __half f_qfH[(long long)CB*CH*CT*CQKD], f_qfL[(long long)CB*CH*CT*CQKD];
__device__ __half f_kfH[(long long)CB*CH*CT*CQKD], f_kfL[(long long)CB*CH*CT*CQKD];
__device__ __half f_vT [(long long)CB*CH*CVHD*CT];
__device__ __half f_at [(long long)CB*CH*CT*CT];
__device__ __half f_y  [(long long)CB*CH*CT*CVHD];
__device__ __half f_y2 [(long long)CM*CD];
__device__ __half f_h2 [(long long)CM*CD];
__device__ __half f_gs [(long long)CM*CINTER];
// weights
__device__ __half f_wqkaH[(long long)NQKVA*CD],   f_wqkaL[(long long)NQKVA*CD];
__device__ __half f_wqbH[(long long)CH*CQKD*CQLORA], f_wqbL[(long long)CH*CQKD*CQLORA];
__device__ __half f_wkbH[(long long)CH*256*CKVLORA], f_wkbL[(long long)CH*256*CKVLORA];
__device__ __half f_wo [(long long)CD*CD];
__device__ __half f_w13[(long long)2*CINTER*CD];   // [0]=w1, [1]=w3
__device__ __half f_w2 [(long long)CD*CINTER];

// ------------------------------- split helpers -----------------------------
__device__ __forceinline__ void split1h(float v, __half& h, __half& l) {
    h = __float2half_rn(v);
    l = __float2half_rn(v - __half2float(h));
}

__global__ __launch_bounds__(256) void split_h_k(
    const float4* __restrict__ in, __half2* __restrict__ hi,
    __half2* __restrict__ lo, long long n4)
{
    long long i = (long long)blockIdx.x * 256 + threadIdx.x;
    if (i >= n4) return;
    float4 v = in[i];
    __half h0,h1,h2,h3,l0,l1,l2,l3;
    split1h(v.x,h0,l0); split1h(v.y,h1,l1); split1h(v.z,h2,l2); split1h(v.w,h3,l3);
    hi[2*i]   = __halves2half2(h0,h1);
    hi[2*i+1] = __halves2half2(h2,h3);
    lo[2*i]   = __halves2half2(l0,l1);
    lo[2*i+1] = __halves2half2(l2,l3);
}

__global__ __launch_bounds__(256) void conv_h_k(
    const float4* __restrict__ in, __half2* __restrict__ out, long long n4)
{
    long long i = (long long)blockIdx.x * 256 + threadIdx.x;
    if (i >= n4) return;
    float4 v = in[i];
    out[2*i]   = __floats2half2_rn(v.x, v.y);
    out[2*i+1] = __floats2half2_rn(v.z, v.w);
}

// fused fp16 conversion of w1, w2, w3
__global__ __launch_bounds__(256) void conv3_h_k(
    const float4* __restrict__ s0, const float4* __restrict__ s1,
    const float4* __restrict__ s2,
    __half2* __restrict__ d0, __half2* __restrict__ d1, __half2* __restrict__ d2,
    long long n4)
{
    long long i = (long long)blockIdx.x * 256 + threadIdx.x;
    if (i >= n4) return;
    const float4* s = (blockIdx.y == 0) ? s0 : (blockIdx.y == 1) ? s1 : s2;
    __half2* d = (blockIdx.y == 0) ? d0 : (blockIdx.y == 1) ? d1 : d2;
    float4 v = s[i];
    d[2*i]   = __floats2half2_rn(v.x, v.y);
    d[2*i+1] = __floats2half2_rn(v.z, v.w);
}

// ------------------------------ RMSNorm variants ----------------------------
__device__ __forceinline__ float rms_scale(const float* ip, int K, int tid) {
    float s = 0.f;
    for (int i = tid; i < K; i += 256) { float v = ip[i]; s += v * v; }
    __shared__ float red[32];
    #pragma unroll
    for (int o = 16; o > 0; o >>= 1) s += __shfl_xor_sync(0xffffffffu, s, o);
    int warp = tid >> 5, lane = tid & 31;
    if (lane == 0) red[warp] = s;
    __syncthreads();
    if (warp == 0) {
        float s2 = (lane < 8) ? red[lane] : 0.f;
        #pragma unroll
        for (int o = 4; o > 0; o >>= 1) s2 += __shfl_xor_sync(0xffffffffu, s2, o);
        if (lane == 0) red[0] = s2;
    }
    __syncthreads();
    return rsqrtf(red[0] / (float)K + 1e-6f);
}

__global__ __launch_bounds__(256) void rmsnorm_split_h_k(
    const float* __restrict__ in, int ldin, const float* __restrict__ w,
    __half* __restrict__ hi, __half* __restrict__ lo, int K)
{
    long long row = blockIdx.x;
    const float* ip = in + row * ldin;
    float scale = rms_scale(ip, K, threadIdx.x);
    for (int i = threadIdx.x; i < K; i += 256) {
        float v = ip[i] * scale * w[i];
        __half h, l; split1h(v, h, l);
        hi[row * (long long)K + i] = h;
        lo[row * (long long)K + i] = l;
    }
}

__global__ __launch_bounds__(256) void rmsnorm_h_k(
    const float* __restrict__ in, int ldin, const float* __restrict__ w,
    __half* __restrict__ out, int K)
{
    long long row = blockIdx.x;
    const float* ip = in + row * ldin;
    float scale = rms_scale(ip, K, threadIdx.x);
    for (int i = threadIdx.x; i < K; i += 256)
        out[row * (long long)K + i] = __float2half_rn(ip[i] * scale * w[i]);
}

// ------------------- RoPE + head packing (qf/kf pairs, vT single) -----------
// qkva: [CM, 2112]; k_pe raw at cols 2048..2111.
__global__ __launch_bounds__(256) void rope_pack_h_k(
    const float* __restrict__ q, const float* __restrict__ kv,
    const float* __restrict__ qkva,
    const float* __restrict__ fcos, const float* __restrict__ fsin,
    __half* __restrict__ qfH, __half* __restrict__ qfL,
    __half* __restrict__ kfH, __half* __restrict__ kfL,
    __half* __restrict__ vT)
{
    int t = blockIdx.x, b = blockIdx.y;
    long long m = (long long)b * CT + t;
    __shared__ float kpe[CROPE], cs[32], sn[32];
    int tid = threadIdx.x;
    if (tid < 32) { cs[tid] = fcos[t*32 + tid]; sn[tid] = fsin[t*32 + tid]; }
    __syncthreads();
    if (tid < 32) {
        float x0 = qkva[m*NQKVA + 2048 + 2*tid];
        float x1 = qkva[m*NQKVA + 2048 + 2*tid + 1];
        kpe[2*tid]   = x0*cs[tid] - x1*sn[tid];
        kpe[2*tid+1] = x0*sn[tid] + x1*cs[tid];
    }
    __syncthreads();
    for (int idx = tid; idx < CH*CQKD; idx += 256) {
        int h = idx / CQKD, d = idx % CQKD;
        long long o = (((long long)b*CH + h)*CT + t)*CQKD + d;
        float qv, kvv;
        if (d < CNOPE) {
            qv  = q [m*(CH*CQKD) + h*CQKD + d];
            kvv = kv[m*(CH*256)  + h*256  + d];
        } else {
            int j = d - CNOPE, i2 = j >> 1;
            float x0 = q[m*(CH*CQKD) + h*CQKD + CNOPE + 2*i2];
            float x1 = q[m*(CH*CQKD) + h*CQKD + CNOPE + 2*i2 + 1];
            qv  = (j & 1) ? (x0*sn[i2] + x1*cs[i2]) : (x0*cs[i2] - x1*sn[i2]);
            kvv = kpe[j];
        }
        __half hh, ll;
        split1h(qv, hh, ll);  qfH[o] = hh; qfL[o] = ll;
        split1h(kvv, hh, ll); kfH[o] = hh; kfL[o] = ll;
    }
    for (int idx = tid; idx < CH*CVHD; idx += 256) {
        int h = idx >> 7, d = idx & 127;
        vT[(((long long)b*CH + h)*CVHD + d)*CT + t] =
            __float2half_rn(kv[m*(CH*256) + h*256 + CNOPE + d]);
    }
}

// ------------------- causal softmax (fp16 out, skip masked reads) -----------
__global__ __launch_bounds__(256) void softmax_causal_h_k(
    const float* __restrict__ s, __half* __restrict__ at)
{
    long long row = blockIdx.x;
    int sIdx = (int)(row & (CT - 1));      // position within sequence
    const float4* p = (const float4*)(s + row * (long long)CT);
    int tid = threadIdx.x, warp = tid >> 5, lane = tid & 31;
    __shared__ float red[32];

    bool act = (4 * tid <= sIdx);
    float4 v = act ? p[tid] : make_float4(-1e30f, -1e30f, -1e30f, -1e30f);
    float mx = fmaxf(fmaxf(v.x, v.y), fmaxf(v.z, v.w));
    #pragma unroll
    for (int o = 16; o > 0; o >>= 1) mx = fmaxf(mx, __shfl_xor_sync(0xffffffffu, mx, o));
    if (lane == 0) red[warp] = mx;
    __syncthreads();
    if (warp == 0) {
        float m2 = (lane < 8) ? red[lane] : -1e30f;
        #pragma unroll
        for (int o = 4; o > 0; o >>= 1) m2 = fmaxf(m2, __shfl_xor_sync(0xffffffffu, m2, o));
        if (lane == 0) red[0] = m2;
    }
    __syncthreads();
    mx = red[0];
    __syncthreads();

    float sum = 0.f;
    if (act) {
        v.x = __expf(v.x - mx); v.y = __expf(v.y - mx);
        v.z = __expf(v.z - mx); v.w = __expf(v.w - mx);
        sum = v.x + v.y + v.z + v.w;
    }
    #pragma unroll
    for (int o = 16; o > 0; o >>= 1) sum += __shfl_xor_sync(0xffffffffu, sum, o);
    if (lane == 0) red[warp] = sum;
    __syncthreads();
    if (warp == 0) {
        float s2 = (lane < 8) ? red[lane] : 0.f;
        #pragma unroll
        for (int o = 4; o > 0; o >>= 1) s2 += __shfl_xor_sync(0xffffffffu, s2, o);
        if (lane == 0) red[0] = s2;
    }
    __syncthreads();
    float inv = 1.f / red[0];
    __half2* H = (__half2*)(at + row * (long long)CT);
    if (act) {
        H[2*tid]   = __floats2half2_rn(v.x * inv, v.y * inv);
        H[2*tid+1] = __floats2half2_rn(v.z * inv, v.w * inv);
    } else {
        H[2*tid]   = __halves2half2(__float2half_rn(0.f), __float2half_rn(0.f));
        H[2*tid+1] = H[2*tid];
    }
}

// ------------------- permute y [B,H,T,VHD] (fp16) -> [B*T, H*VHD] -----------
__global__ __launch_bounds__(256) void permute_hh_k(
    const __half* __restrict__ y, __half* __restrict__ y2)
{
    int t = blockIdx.x, b = blockIdx.y;
    for (int idx = threadIdx.x; idx < CH*CVHD; idx += 256) {
        int h = idx >> 7, d = idx & 127;
        y2[((long long)b*CT + t)*(CH*CVHD) + idx] =
            y[(((long long)b*CH + h)*CT + t)*CVHD + d];
    }
}

// --------------------------- SiLU(gate)*up (fp16 out) ------------------------
__global__ __launch_bounds__(256) void silu_mul_h_k(
    const float4* __restrict__ g, const float4* __restrict__ u,
    __half2* __restrict__ gs, long long n4)
{
    long long i = (long long)blockIdx.x * 256 + threadIdx.x;
    if (i >= n4) return;
    float4 gv = g[i], uv = u[i];
    float r0 = gv.x / (1.f + __expf(-gv.x)) * uv.x;
    float r1 = gv.y / (1.f + __expf(-gv.y)) * uv.y;
    float r2 = gv.z / (1.f + __expf(-gv.z)) * uv.z;
    float r3 = gv.w / (1.f + __expf(-gv.w)) * uv.w;
    gs[2*i]   = __floats2half2_rn(r0, r1);
    gs[2*i+1] = __floats2half2_rn(r2, r3);
}

// ======================= templated fp16 HMMA GEMM ===========================
// TERMS=3: C = alpha*(Ah@Bh + Ah@Bl + Al@Bh) [+R];  TERMS=1: C = alpha*Ah@Bh [+R]
// HOUT=0: C float (R/alpha);  HOUT=1: C __half (alpha, no R).
// causal: 1 = skip (no writes) when bn > bm+127;  2 = truncate K at bm+128.
template<int TERMS, int BN>
__device__ __forceinline__ void issue_h(
    uint32_t sbase, const __half* Ah, const __half* Al,
    const __half* Bh, const __half* Bl,
    int lda, int ldb, int bm, int bn, int M, int N, int k0, int tid)
{
    constexpr int OPS = (TERMS == 3) ? 2 : 1;
    constexpr int ABYTES = 16384 * OPS;
    constexpr int NBT = BN / 128;
    #pragma unroll
    for (int it = 0; it < 4; it++) {
        int e = it * 256 + tid;
        int r = e >> 3, g = e & 7;
        uint32_t so = SW128(r * 128 + g * 16);
        int ra = bm + r; int pa = (ra < M) ? 16 : 0; if (!pa) ra = 0;
        cpa16(sbase + so, Ah + (size_t)ra * lda + k0 + g * 8, pa);
        if constexpr (TERMS == 3)
            cpa16(sbase + 16384 + so, Al + (size_t)ra * lda + k0 + g * 8, pa);
    }
    #pragma unroll
    for (int it = 0; it < 4 * NBT; it++) {
        int e = it * 256 + tid;
        int r = e >> 3, g = e & 7;
        uint32_t so = SW128(r * 128 + g * 16);
        int rb = bn + r; int pb = (rb < N) ? 16 : 0; if (!pb) rb = 0;
        cpa16(sbase + ABYTES + so, Bh + (size_t)rb * ldb + k0 + g * 8, pb);
        if constexpr (TERMS == 3)
            cpa16(sbase + ABYTES + NBT * 16384 + so, Bl + (size_t)rb * ldb + k0 + g * 8, pb);
    }
    cp_commit();
}

template<int TERMS, int BN, int HOUT>
__global__ __launch_bounds__(256, 1) void gemm_h(
    const __half* __restrict__ Ah, const __half* __restrict__ Al,
    int lda, long long sA,
    const __half* __restrict__ Bh, const __half* __restrict__ Bl,
    int ldb, long long sB,
    void* __restrict__ Cv, int ldc, long long sC,
    const float* __restrict__ R, int ldr, long long sR,
    int M, int N, int K, float alpha, int causal)
{
    constexpr int OPS = (TERMS == 3) ? 2 : 1;
    constexpr int ABYTES = 16384 * OPS;
    constexpr int NBT = BN / 128;
    constexpr int STAGE = ABYTES + NBT * 16384 * OPS;
    constexpr int NST = (TERMS == 1) ? 4 : ((BN == 128) ? 3 : 2);
    constexpr int NG4 = BN / 64;
    constexpr int NS  = BN / 32;

    extern __shared__ __align__(1024) char smem[];
    const uint32_t sb0 = smem_u32(smem);
    const int tid = threadIdx.x;
    const int wid = tid >> 5, lane = tid & 31;
    long long z = blockIdx.z;
    Ah += z * sA;
    if constexpr (TERMS == 3) Al += z * sA;
    Bh += z * sB;
    if constexpr (TERMS == 3) Bl += z * sB;
    if (R) R += z * sR;
    const int bm = blockIdx.y * 128, bn = blockIdx.x * BN;
    const int wm = (wid >> 2) * 64, wn = (wid & 3) * (BN / 4);

    if (causal == 1 && bn > bm + 127) return;   // fully masked: softmax fills zeros

    float acc[4][NS][4];
    #pragma unroll
    for (int i = 0; i < 4; i++)
        #pragma unroll
        for (int j = 0; j < NS; j++)
            #pragma unroll
            for (int r = 0; r < 4; r++) acc[i][j][r] = 0.f;

    int nc = K >> 6;
    if (causal == 2) { int lim = (bm + 191) >> 6; if (lim < nc) nc = lim; }

    #pragma unroll
    for (int s = 0; s < NST - 1; s++) {
        if (s < nc)
            issue_h<TERMS, BN>(sb0 + s * STAGE, Ah, Al, Bh, Bl, lda, ldb, bm, bn, M, N, s << 6, tid);
        else
            cp_commit();
    }

    const int arow = wm + (lane & 15);
    const int acb  = (lane >> 4) << 4;
    const int brow4 = wn + ((lane >> 4) << 3) + (lane & 7);
    const int bcb4  = ((lane >> 3) & 1) << 4;

    for (int c = 0; c < nc; c++) {
        cp_wait<NST - 2>();
        __syncthreads();
        {
            int nx = c + NST - 1;
            if (nx < nc)
                issue_h<TERMS, BN>(sb0 + (nx % NST) * STAGE, Ah, Al, Bh, Bl,
                                   lda, ldb, bm, bn, M, N, nx << 6, tid);
            else
                cp_commit();
        }

        uint32_t tA  = sb0 + (c % NST) * STAGE;
        uint32_t tAl = tA + 16384;
        uint32_t tB  = tA + ABYTES;
        uint32_t tBl = tB + NBT * 16384;

        #pragma unroll
        for (int ks = 0; ks < 4; ks++) {
            uint32_t ah[4][4], al[4][4];
            #pragma unroll
            for (int ms = 0; ms < 4; ms++) {
                uint32_t off = SW128((arow + ms * 16) * 128 + ks * 32 + acb);
                ldsm_x4(ah[ms], tA + off);
                if constexpr (TERMS == 3) ldsm_x4(al[ms], tAl + off);
            }
            #pragma unroll
            for (int ng4 = 0; ng4 < NG4; ng4++) {
                uint32_t bh4[4], bl4[4];
                uint32_t off = SW128((brow4 + ng4 * 16) * 128 + ks * 32 + bcb4);
                ldsm_x4(bh4, tB + off);
                if constexpr (TERMS == 3) ldsm_x4(bl4, tBl + off);
                #pragma unroll
                for (int ms = 0; ms < 4; ms++) {
                    mma_f16(acc[ms][2*ng4], ah[ms], bh4);
                    if constexpr (TERMS == 3) {
                        mma_f16(acc[ms][2*ng4], ah[ms], bl4);
                        mma_f16(acc[ms][2*ng4], al[ms], bh4);
                    }
                    mma_f16(acc[ms][2*ng4+1], ah[ms], bh4 + 2);
                    if constexpr (TERMS == 3) {
                        mma_f16(acc[ms][2*ng4+1], ah[ms], bl4 + 2);
                        mma_f16(acc[ms][2*ng4+1], al[ms], bh4 + 2);
                    }
                }
            }
        }
    }

    const int gid = lane >> 2, tc = lane & 3;
    if constexpr (HOUT == 1) {
        __half* C = (__half*)Cv + z * sC;
        #pragma unroll
        for (int ms = 0; ms < 4; ms++)
            #pragma unroll
            for (int ns = 0; ns < NS; ns++) {
                int gr0 = bm + wm + ms * 16 + gid;
                int gc  = bn + wn + ns * 8 + tc * 2;
                if (gc < N) {
                    *(__half2*)&C[(size_t)gr0 * ldc + gc] =
                        __floats2half2_rn(alpha * acc[ms][ns][0], alpha * acc[ms][ns][1]);
                    *(__half2*)&C[(size_t)(gr0 + 8) * ldc + gc] =
                        __floats2half2_rn(alpha * acc[ms][ns][2], alpha * acc[ms][ns][3]);
                }
            }
    } else {
        float* C = (float*)Cv + z * sC;
        #pragma unroll
        for (int ms = 0; ms < 4; ms++)
            #pragma unroll
            for (int ns = 0; ns < NS; ns++) {
                int gr0 = bm + wm + ms * 16 + gid;
                int gc  = bn + wn + ns * 8 + tc * 2;
                if (gc < N) {
                    float2 v0;
                    v0.x = alpha * acc[ms][ns][0];
                    v0.y = alpha * acc[ms][ns][1];
                    if (R) { v0.x += R[(size_t)gr0 * ldr + gc]; v0.y += R[(size_t)gr0 * ldr + gc + 1]; }
                    *(float2*)&C[(size_t)gr0 * ldc + gc] = v0;
                    int gr1 = gr0 + 8;
                    float2 v1;
                    v1.x = alpha * acc[ms][ns][2];
                    v1.y = alpha * acc[ms][ns][3];
                    if (R) { v1.x += R[(size_t)gr1 * ldr + gc]; v1.y += R[(size_t)gr1 * ldr + gc + 1]; }
                    *(float2*)&C[(size_t)gr1 * ldc + gc] = v1;
                }
            }
    }
}

#define SM_3_256 (2*(32768+65536))
#define SM_3_128 (3*(32768+32768))
#define SM_1_256 (4*(16384+32768))
#define SM_1_128 (4*(16384+16384))

// ------------------------------ host launch ---------------------------------
static void gemm3(const __half* Ah, const __half* Al, int lda, long long sA,
                  const __half* Bh, const __half* Bl, int ldb, long long sB,
                  float* C, int ldc, long long sC,
                  const float* R, int ldr, long long sR,
                  int M, int N, int K, float alpha, int Z, int causal = 0)
{
    if (N % 256 == 0) {
        dim3 grid(N / 256, M / 128, Z);
        gemm_h<3,256,0><<<grid, 256, SM_3_256>>>(Ah, Al, lda, sA, Bh, Bl, ldb, sB,
                                                 C, ldc, sC, R, ldr, sR, M, N, K, alpha, causal);
    } else {
        dim3 grid((N + 127) / 128, M / 128, Z);
        gemm_h<3,128,0><<<grid, 256, SM_3_128>>>(Ah, Al, lda, sA, Bh, Bl, ldb, sB,
                                                 C, ldc, sC, R, ldr, sR, M, N, K, alpha, causal);
    }
}
static void gemm1f(const __half* A, int lda, long long sA,
                   const __half* B, int ldb, long long sB,
                   float* C, int ldc, long long sC,
                   const float* R, int ldr, long long sR,
                   int M, int N, int K, float alpha, int Z, int causal = 0)
{
    if (N % 256 == 0) {
        dim3 grid(N / 256, M / 128, Z);
        gemm_h<1,256,0><<<grid, 256, SM_1_256>>>(A, nullptr, lda, sA, B, nullptr, ldb, sB,
                                                 C, ldc, sC, R, ldr, sR, M, N, K, alpha, causal);
    } else {
        dim3 grid((N + 127) / 128, M / 128, Z);
        gemm_h<1,128,0><<<grid, 256, SM_1_128>>>(A, nullptr, lda, sA, B, nullptr, ldb, sB,
                                                 C, ldc, sC, R, ldr, sR, M, N, K, alpha, causal);
    }
}
static void gemm1h(const __half* A, int lda, long long sA,
                   const __half* B, int ldb, long long sB,
                   __half* C, int ldc, long long sC,
                   int M, int N, int K, float alpha, int Z, int causal = 0)
{
    if (N % 256 == 0) {
        dim3 grid(N / 256, M / 128, Z);
        gemm_h<1,256,1><<<grid, 256, SM_1_256>>>(A, nullptr, lda, sA, B, nullptr, ldb, sB,
                                                 C, ldc, sC, nullptr, 0, 0, M, N, K, alpha, causal);
    } else {
        dim3 grid((N + 127) / 128, M / 128, Z);
        gemm_h<1,128,1><<<grid, 256, SM_1_128>>>(A, nullptr, lda, sA, B, nullptr, ldb, sB,
                                                 C, ldc, sC, nullptr, 0, 0, M, N, K, alpha, causal);
    }
}

static void splitp(const float* in, __half* hi, __half* lo, long long n)
{
    long long n4 = n >> 2;
    split_h_k<<<(unsigned)((n4 + 255) / 256), 256>>>(
        (const float4*)in, (__half2*)hi, (__half2*)lo, n4);
}

extern "C" void kernel_launch(void* const* d_in, const int* in_sizes, int n_in,
                              void* d_out, int out_size)
{
    const float* x     = (const float*)d_in[0];
    const float* mask  = (const float*)d_in[1];
    const float* fcos  = (const float*)d_in[2];
    const float* fsin  = (const float*)d_in[3];
    const float* anw   = (const float*)d_in[4];
    const float* wq_a  = (const float*)d_in[5];
    const float* qnw   = (const float*)d_in[6];
    const float* wq_b  = (const float*)d_in[7];
    const float* wkv_a = (const float*)d_in[8];
    const float* kvnw  = (const float*)d_in[9];
    const float* wkv_b = (const float*)d_in[10];
    const float* wo    = (const float*)d_in[11];
    const float* fnw   = (const float*)d_in[12];
    const float* w1    = (const float*)d_in[13];
    const float* w2    = (const float*)d_in[14];
    const float* w3    = (const float*)d_in[15];
    float* out = (float*)d_out;

    cudaFuncSetAttribute(gemm_h<3,256,0>, cudaFuncAttributeMaxDynamicSharedMemorySize, SM_3_256);
    cudaFuncSetAttribute(gemm_h<3,128,0>, cudaFuncAttributeMaxDynamicSharedMemorySize, SM_3_128);
    cudaFuncSetAttribute(gemm_h<1,256,0>, cudaFuncAttributeMaxDynamicSharedMemorySize, SM_1_256);
    cudaFuncSetAttribute(gemm_h<1,128,0>, cudaFuncAttributeMaxDynamicSharedMemorySize, SM_1_128);
    cudaFuncSetAttribute(gemm_h<1,256,1>, cudaFuncAttributeMaxDynamicSharedMemorySize, SM_1_256);
    cudaFuncSetAttribute(gemm_h<1,128,1>, cudaFuncAttributeMaxDynamicSharedMemorySize, SM_1_128);

    float *p_qkva, *p_q, *p_kv, *p_sc, *p_x2, *p_gu;
    cudaGetSymbolAddress((void**)&p_qkva, g_qkva);
    cudaGetSymbolAddress((void**)&p_q,    g_q);
    cudaGetSymbolAddress((void**)&p_kv,   g_kv);
    cudaGetSymbolAddress((void**)&p_sc,   g_sc);
    cudaGetSymbolAddress((void**)&p_x2,   g_x2);
    cudaGetSymbolAddress((void**)&p_gu,   g_gu);

    __half *hH,*hL,*qaH,*qaL,*kvnH,*kvnL,*qfH,*qfL,*kfH,*kfL,*vT,*at,*y,*y2,*h2,*gs,
           *wqkaH,*wqkaL,*wqbH,*wqbL,*wkbH,*wkbL,*woh,*w13h,*w2h;
    cudaGetSymbolAddress((void**)&hH,   f_hH);  cudaGetSymbolAddress((void**)&hL,   f_hL);
    cudaGetSymbolAddress((void**)&qaH,  f_qaH); cudaGetSymbolAddress((void**)&qaL,  f_qaL);
    cudaGetSymbolAddress((void**)&kvnH, f_kvnH);cudaGetSymbolAddress((void**)&kvnL, f_kvnL);
    cudaGetSymbolAddress((void**)&qfH,  f_qfH); cudaGetSymbolAddress((void**)&qfL,  f_qfL);
    cudaGetSymbolAddress((void**)&kfH,  f_kfH); cudaGetSymbolAddress((void**)&kfL,  f_kfL);
    cudaGetSymbolAddress((void**)&vT,   f_vT);  cudaGetSymbolAddress((void**)&at,   f_at);
    cudaGetSymbolAddress((void**)&y,    f_y);   cudaGetSymbolAddress((void**)&y2,   f_y2);
    cudaGetSymbolAddress((void**)&h2,   f_h2);  cudaGetSymbolAddress((void**)&gs,   f_gs);
    cudaGetSymbolAddress((void**)&wqkaH,f_wqkaH);cudaGetSymbolAddress((void**)&wqkaL,f_wqkaL);
    cudaGetSymbolAddress((void**)&wqbH, f_wqbH);cudaGetSymbolAddress((void**)&wqbL, f_wqbL);
    cudaGetSymbolAddress((void**)&wkbH, f_wkbH);cudaGetSymbolAddress((void**)&wkbL, f_wkbL);
    cudaGetSymbolAddress((void**)&woh,  f_wo);
    cudaGetSymbolAddress((void**)&w13h, f_w13); cudaGetSymbolAddress((void**)&w2h,  f_w2);

    // ---- attention path ----
    // 1) h = rmsnorm(x) -> fp16 pair
    rmsnorm_split_h_k<<<CM, 256>>>(x, CD, anw, hH, hL, CD);
    // merged wq_a || wkv_a -> [2112, 2048] fp16 pair
    splitp(wq_a,  wqkaH, wqkaL, (long long)CQLORA*CD);
    splitp(wkv_a, wqkaH + (long long)CQLORA*CD, wqkaL + (long long)CQLORA*CD,
           (long long)(CKVLORA+CROPE)*CD);
    // 2+5) qkva = h @ [wq_a; wkv_a]^T   (N=2112)
    gemm3(hH, hL, CD, 0, wqkaH, wqkaL, CD, 0, p_qkva, NQKVA, 0,
          nullptr, 0, 0, CM, NQKVA, CD, 1.f, 1);
    // 3) qa_norm (cols 0..1535)
    rmsnorm_split_h_k<<<CM, 256>>>(p_qkva, NQKVA, qnw, qaH, qaL, CQLORA);
    splitp(wq_b, wqbH, wqbL, (long long)CH*CQKD*CQLORA);
    // 4) q = qa_norm @ wq_b^T
    gemm3(qaH, qaL, CQLORA, 0, wqbH, wqbL, CQLORA, 0, p_q, CH*CQKD, 0,
          nullptr, 0, 0, CM, CH*CQKD, CQLORA, 1.f, 1);
    // 6) kv_norm (cols 1536..2047)
    rmsnorm_split_h_k<<<CM, 256>>>(p_qkva + CQLORA, NQKVA, kvnw, kvnH, kvnL, CKVLORA);
    splitp(wkv_b, wkbH, wkbL, (long long)CH*256*CKVLORA);
    // 7) kv = kv_norm @ wkv_b^T
    gemm3(kvnH, kvnL, CKVLORA, 0, wkbH, wkbL, CKVLORA, 0, p_kv, CH*256, 0,
          nullptr, 0, 0, CM, CH*256, CKVLORA, 1.f, 1);
    // 8) rope + pack
    rope_pack_h_k<<<dim3(CT, CB), 256>>>(p_q, p_kv, p_qkva, fcos, fsin,
                                         qfH, qfL, kfH, kfL, vT);
    // 9) scores = -96 * qf @ kf^T + mask  (fully-masked tiles skipped entirely)
    gemm3(qfH, qfL, CQKD, (long long)CT*CQKD,
          kfH, kfL, CQKD, (long long)CT*CQKD,
          p_sc, CT, (long long)CT*CT,
          mask, CT, 0, CT, CT, CQKD, -96.f, CB*CH, 1);
    // 10) causal softmax -> fp16 attn (zeros beyond diagonal)
    softmax_causal_h_k<<<CB*CH*CT, 256>>>(p_sc, at);
    // 11) y = attn @ vT  (fp16 out, truncate K at diagonal)
    gemm1h(at, CT, (long long)CT*CT,
           vT, CT, (long long)CVHD*CT,
           y, CVHD, (long long)CT*CVHD,
           CT, CVHD, CT, 1.f, CB*CH, 2);
    // 12) permute (half -> half)
    permute_hh_k<<<dim3(CT, CB), 256>>>(y, y2);
    {
        long long n4 = ((long long)CD * CD) >> 2;
        conv_h_k<<<(unsigned)((n4 + 255) / 256), 256>>>((const float4*)wo, (__half2*)woh, n4);
    }
    // 13) x2 = x + y2 @ wo^T
    gemm1f(y2, CH*CVHD, 0, woh, CH*CVHD, 0, p_x2, CD, 0,
           x, CD, 0, CM, CD, CH*CVHD, 1.f, 1);

    // ---- FFN path ----
    {
        long long n4 = ((long long)CINTER * CD) >> 2;
        dim3 grid((unsigned)((n4 + 255) / 256), 3);
        conv3_h_k<<<grid, 256>>>((const float4*)w1, (const float4*)w2, (const float4*)w3,
                                 (__half2*)w13h, (__half2*)w2h,
                                 (__half2*)(w13h + (long long)CINTER*CD), n4);
    }
    // 14) h2 = rmsnorm(x2) -> single fp16
    rmsnorm_h_k<<<CM, 256>>>(p_x2, CD, fnw, h2, CD);
    // 15/16) [gate; up] = h2 @ [w1; w3]^T in ONE batched launch (Z=2, shared A)
    gemm1f(h2, CD, 0, w13h, CD, (long long)CINTER*CD,
           p_gu, CINTER, (long long)CM*CINTER,
           nullptr, 0, 0, CM, CINTER, CD, 1.f, 2);
    // 17) gs = silu(gate)*up -> fp16
    {
        long long n4 = ((long long)CM * CINTER) >> 2;
        silu_mul_h_k<<<(unsigned)((n4 + 255) / 256), 256>>>(
            (const float4*)p_gu, (const float4*)(p_gu + (long long)CM*CINTER),
            (__half2*)gs, n4);
    }
    // 18) out = x2 + gs @ w2^T
    gemm1f(gs, CINTER, 0, w2h, CINTER, 0, out, CD, 0,
           p_x2, CD, 0, CM, CD, CINTER, 1.f, 1);
}

// round 8
// speedup vs baseline: 5.5486x; 1.0124x over previous
#include <cuda_runtime.h>
#include <cuda_fp16.h>
#include <cstdint>

// ---------------------------------------------------------------------------
// DeepSeek MLA block on GB300 — mma.sync fp16 GEMMs, v6.
// q/k path: fp16-pair 3-term split. Additive paths: 1-term fp16.
// v6: gate/up/silu fused in one GEMM epilogue, permute fused into attn@V,
//     one weight-convert kernel, interleaved MMA term order.
// ---------------------------------------------------------------------------

#define CB 2
#define CT 1024
#define CD 2048
#define CH 16
#define CNOPE 128
#define CROPE 64
#define CQKD 192
#define CQLORA 1536
#define CKVLORA 512
#define CVHD 128
#define CINTER 8192
#define CM (CB*CT)
#define NQKVA (CQLORA + CKVLORA + CROPE)   // 2112

// ------------------------------- PTX helpers -------------------------------
__device__ __forceinline__ uint32_t smem_u32(const void* p) {
    uint32_t a;
    asm("{ .reg .u64 t; cvta.to.shared.u64 t, %1; cvt.u32.u64 %0, t; }" : "=r"(a) : "l"(p));
    return a;
}
#define SW128(o) ((o) ^ (((o) >> 3) & 0x70))

__device__ __forceinline__ void cpa16(uint32_t s, const void* g, int sz) {
    asm volatile("cp.async.cg.shared.global [%0], [%1], 16, %2;"
                 :: "r"(s), "l"(g), "r"(sz));
}
__device__ __forceinline__ void cp_commit() {
    asm volatile("cp.async.commit_group;" ::: "memory");
}
template <int N> __device__ __forceinline__ void cp_wait() {
    asm volatile("cp.async.wait_group %0;" :: "n"(N) : "memory");
}
__device__ __forceinline__ void ldsm_x4(uint32_t* r, uint32_t a) {
    asm volatile("ldmatrix.sync.aligned.m8n8.x4.shared.b16 {%0,%1,%2,%3}, [%4];"
        : "=r"(r[0]), "=r"(r[1]), "=r"(r[2]), "=r"(r[3]) : "r"(a));
}
__device__ __forceinline__ void mma_f16(float* d, const uint32_t* a, const uint32_t* b) {
    asm volatile(
        "mma.sync.aligned.m16n8k16.row.col.f32.f16.f16.f32 "
        "{%0,%1,%2,%3}, {%4,%5,%6,%7}, {%8,%9}, {%0,%1,%2,%3};"
        : "+f"(d[0]), "+f"(d[1]), "+f"(d[2]), "+f"(d[3])
        : "r"(a[0]), "r"(a[1]), "r"(a[2]), "r"(a[3]), "r"(b[0]), "r"(b[1]));
}

// ------------------------- scratch (device globals) ------------------------
__device__ float g_qkva[(long long)CM*NQKVA];
__device__ float g_q   [(long long)CM*CH*CQKD];
__device__ float g_kv  [(long long)CM*CH*(CNOPE+CVHD)];
__device__ float g_sc  [(long long)CB*CH*CT*CT];
__device__ float g_x2  [(long long)CM*CD];

// fp16 operand buffers
__device__ __half f_hH [(long long)CM*CD],        f_hL [(long long)CM*CD];
__device__ __half f_qaH[(long long)CM*CQLORA],    f_qaL[(long long)CM*CQLORA];
__device__ __half f_kvnH[(long long)CM*CKVLORA],  f_kvnL[(long long)CM*CKVLORA];
__device__ __half f_qfH[(long long)CB*CH*CT*CQKD], f_qfL[(long long)CB*CH*CT*CQKD];
__device__ __half f_kfH[(long long)CB*CH*CT*CQKD], f_kfL[(long long)CB*CH*CT*CQKD];
__device__ __half f_vT [(long long)CB*CH*CVHD*CT];
__device__ __half f_at [(long long)CB*CH*CT*CT];
__device__ __half f_y2 [(long long)CM*CD];
__device__ __half f_h2 [(long long)CM*CD];
__device__ __half f_gs [(long long)CM*CINTER];
// weights
__device__ __half f_wqkaH[(long long)NQKVA*CD],   f_wqkaL[(long long)NQKVA*CD];
__device__ __half f_wqbH[(long long)CH*CQKD*CQLORA], f_wqbL[(long long)CH*CQKD*CQLORA];
__device__ __half f_wkbH[(long long)CH*256*CKVLORA], f_wkbL[(long long)CH*256*CKVLORA];
__device__ __half f_wo [(long long)CD*CD];
__device__ __half f_w13[(long long)2*CINTER*CD];   // interleaved: row 2j=w1_j, 2j+1=w3_j
__device__ __half f_w2 [(long long)CD*CINTER];

// ------------------------------- split helpers -----------------------------
__device__ __forceinline__ void split1h(float v, __half& h, __half& l) {
    h = __float2half_rn(v);
    l = __float2half_rn(v - __half2float(h));
}

__global__ __launch_bounds__(256) void split_h_k(
    const float4* __restrict__ in, __half2* __restrict__ hi,
    __half2* __restrict__ lo, long long n4)
{
    long long i = (long long)blockIdx.x * 256 + threadIdx.x;
    if (i >= n4) return;
    float4 v = in[i];
    __half h0,h1,h2,h3,l0,l1,l2,l3;
    split1h(v.x,h0,l0); split1h(v.y,h1,l1); split1h(v.z,h2,l2); split1h(v.w,h3,l3);
    hi[2*i]   = __halves2half2(h0,h1);
    hi[2*i+1] = __halves2half2(h2,h3);
    lo[2*i]   = __halves2half2(l0,l1);
    lo[2*i+1] = __halves2half2(l2,l3);
}

// convert w1 (interleave even rows), w3 (odd rows), w2 (straight), wo (straight)
__global__ __launch_bounds__(256) void conv4_h_k(
    const float4* __restrict__ w1, const float4* __restrict__ w3,
    const float4* __restrict__ w2, const float4* __restrict__ wo,
    __half2* __restrict__ w13, __half2* __restrict__ w2h, __half2* __restrict__ woh,
    long long n4big, long long n4wo)
{
    long long i = (long long)blockIdx.x * 256 + threadIdx.x;
    int which = blockIdx.y;
    if (which <= 1) {
        if (i >= n4big) return;
        const float4* s = which ? w3 : w1;
        float4 v = s[i];
        long long row = i / (CD/4), off = i % (CD/4);
        long long orow = 2*row + which;
        __half2* d = w13 + orow * (CD/2) + off*2;
        d[0] = __floats2half2_rn(v.x, v.y);
        d[1] = __floats2half2_rn(v.z, v.w);
    } else if (which == 2) {
        if (i >= n4big) return;
        float4 v = w2[i];
        w2h[2*i]   = __floats2half2_rn(v.x, v.y);
        w2h[2*i+1] = __floats2half2_rn(v.z, v.w);
    } else {
        if (i >= n4wo) return;
        float4 v = wo[i];
        woh[2*i]   = __floats2half2_rn(v.x, v.y);
        woh[2*i+1] = __floats2half2_rn(v.z, v.w);
    }
}

// ------------------------------ RMSNorm variants ----------------------------
__device__ __forceinline__ float rms_scale(const float* ip, int K, int tid) {
    float s = 0.f;
    for (int i = tid; i < K; i += 256) { float v = ip[i]; s += v * v; }
    __shared__ float red[32];
    #pragma unroll
    for (int o = 16; o > 0; o >>= 1) s += __shfl_xor_sync(0xffffffffu, s, o);
    int warp = tid >> 5, lane = tid & 31;
    if (lane == 0) red[warp] = s;
    __syncthreads();
    if (warp == 0) {
        float s2 = (lane < 8) ? red[lane] : 0.f;
        #pragma unroll
        for (int o = 4; o > 0; o >>= 1) s2 += __shfl_xor_sync(0xffffffffu, s2, o);
        if (lane == 0) red[0] = s2;
    }
    __syncthreads();
    return rsqrtf(red[0] / (float)K + 1e-6f);
}

__global__ __launch_bounds__(256) void rmsnorm_split_h_k(
    const float* __restrict__ in, int ldin, const float* __restrict__ w,
    __half* __restrict__ hi, __half* __restrict__ lo, int K)
{
    long long row = blockIdx.x;
    const float* ip = in + row * ldin;
    float scale = rms_scale(ip, K, threadIdx.x);
    for (int i = threadIdx.x; i < K; i += 256) {
        float v = ip[i] * scale * w[i];
        __half h, l; split1h(v, h, l);
        hi[row * (long long)K + i] = h;
        lo[row * (long long)K + i] = l;
    }
}

__global__ __launch_bounds__(256) void rmsnorm_h_k(
    const float* __restrict__ in, int ldin, const float* __restrict__ w,
    __half* __restrict__ out, int K)
{
    long long row = blockIdx.x;
    const float* ip = in + row * ldin;
    float scale = rms_scale(ip, K, threadIdx.x);
    for (int i = threadIdx.x; i < K; i += 256)
        out[row * (long long)K + i] = __float2half_rn(ip[i] * scale * w[i]);
}

// ------------------- RoPE + head packing (qf/kf pairs, vT single) -----------
__global__ __launch_bounds__(256) void rope_pack_h_k(
    const float* __restrict__ q, const float* __restrict__ kv,
    const float* __restrict__ qkva,
    const float* __restrict__ fcos, const float* __restrict__ fsin,
    __half* __restrict__ qfH, __half* __restrict__ qfL,
    __half* __restrict__ kfH, __half* __restrict__ kfL,
    __half* __restrict__ vT)
{
    int t = blockIdx.x, b = blockIdx.y;
    long long m = (long long)b * CT + t;
    __shared__ float kpe[CROPE], cs[32], sn[32];
    int tid = threadIdx.x;
    if (tid < 32) { cs[tid] = fcos[t*32 + tid]; sn[tid] = fsin[t*32 + tid]; }
    __syncthreads();
    if (tid < 32) {
        float x0 = qkva[m*NQKVA + 2048 + 2*tid];
        float x1 = qkva[m*NQKVA + 2048 + 2*tid + 1];
        kpe[2*tid]   = x0*cs[tid] - x1*sn[tid];
        kpe[2*tid+1] = x0*sn[tid] + x1*cs[tid];
    }
    __syncthreads();
    for (int idx = tid; idx < CH*CQKD; idx += 256) {
        int h = idx / CQKD, d = idx % CQKD;
        long long o = (((long long)b*CH + h)*CT + t)*CQKD + d;
        float qv, kvv;
        if (d < CNOPE) {
            qv  = q [m*(CH*CQKD) + h*CQKD + d];
            kvv = kv[m*(CH*256)  + h*256  + d];
        } else {
            int j = d - CNOPE, i2 = j >> 1;
            float x0 = q[m*(CH*CQKD) + h*CQKD + CNOPE + 2*i2];
            float x1 = q[m*(CH*CQKD) + h*CQKD + CNOPE + 2*i2 + 1];
            qv  = (j & 1) ? (x0*sn[i2] + x1*cs[i2]) : (x0*cs[i2] - x1*sn[i2]);
            kvv = kpe[j];
        }
        __half hh, ll;
        split1h(qv, hh, ll);  qfH[o] = hh; qfL[o] = ll;
        split1h(kvv, hh, ll); kfH[o] = hh; kfL[o] = ll;
    }
    for (int idx = tid; idx < CH*CVHD; idx += 256) {
        int h = idx >> 7, d = idx & 127;
        vT[(((long long)b*CH + h)*CVHD + d)*CT + t] =
            __float2half_rn(kv[m*(CH*256) + h*256 + CNOPE + d]);
    }
}

// ------------------- causal softmax (fp16 out, skip masked reads) -----------
__global__ __launch_bounds__(256) void softmax_causal_h_k(
    const float* __restrict__ s, __half* __restrict__ at)
{
    long long row = blockIdx.x;
    int sIdx = (int)(row & (CT - 1));
    const float4* p = (const float4*)(s + row * (long long)CT);
    int tid = threadIdx.x, warp = tid >> 5, lane = tid & 31;
    __shared__ float red[32];

    bool act = (4 * tid <= sIdx);
    float4 v = act ? p[tid] : make_float4(-1e30f, -1e30f, -1e30f, -1e30f);
    float mx = fmaxf(fmaxf(v.x, v.y), fmaxf(v.z, v.w));
    #pragma unroll
    for (int o = 16; o > 0; o >>= 1) mx = fmaxf(mx, __shfl_xor_sync(0xffffffffu, mx, o));
    if (lane == 0) red[warp] = mx;
    __syncthreads();
    if (warp == 0) {
        float m2 = (lane < 8) ? red[lane] : -1e30f;
        #pragma unroll
        for (int o = 4; o > 0; o >>= 1) m2 = fmaxf(m2, __shfl_xor_sync(0xffffffffu, m2, o));
        if (lane == 0) red[0] = m2;
    }
    __syncthreads();
    mx = red[0];
    __syncthreads();

    float sum = 0.f;
    if (act) {
        v.x = __expf(v.x - mx); v.y = __expf(v.y - mx);
        v.z = __expf(v.z - mx); v.w = __expf(v.w - mx);
        sum = v.x + v.y + v.z + v.w;
    }
    #pragma unroll
    for (int o = 16; o > 0; o >>= 1) sum += __shfl_xor_sync(0xffffffffu, sum, o);
    if (lane == 0) red[warp] = sum;
    __syncthreads();
    if (warp == 0) {
        float s2 = (lane < 8) ? red[lane] : 0.f;
        #pragma unroll
        for (int o = 4; o > 0; o >>= 1) s2 += __shfl_xor_sync(0xffffffffu, s2, o);
        if (lane == 0) red[0] = s2;
    }
    __syncthreads();
    float inv = 1.f / red[0];
    __half2* H = (__half2*)(at + row * (long long)CT);
    if (act) {
        H[2*tid]   = __floats2half2_rn(v.x * inv, v.y * inv);
        H[2*tid+1] = __floats2half2_rn(v.z * inv, v.w * inv);
    } else {
        H[2*tid]   = __halves2half2(__float2half_rn(0.f), __float2half_rn(0.f));
        H[2*tid+1] = H[2*tid];
    }
}

// ======================= templated fp16 HMMA GEMM ===========================
// TERMS=3: C = alpha*(Ah@Bh + Ah@Bl + Al@Bh) [+R];  TERMS=1: C = alpha*Ah@Bh [+R]
// HOUT: 0=float(+R), 1=half, 2=gu-fused (silu(even col)*odd col -> half, ld=ldc)
// C offset per z: (z/zdiv)*sC + (z%zdiv)*sC2
// causal: 1 = skip when bn > bm+127;  2 = truncate K at bm+128.
template<int TERMS, int BN>
__device__ __forceinline__ void issue_h(
    uint32_t sbase, const __half* Ah, const __half* Al,
    const __half* Bh, const __half* Bl,
    int lda, int ldb, int bm, int bn, int M, int N, int k0, int tid)
{
    constexpr int OPS = (TERMS == 3) ? 2 : 1;
    constexpr int ABYTES = 16384 * OPS;
    constexpr int NBT = BN / 128;
    #pragma unroll
    for (int it = 0; it < 4; it++) {
        int e = it * 256 + tid;
        int r = e >> 3, g = e & 7;
        uint32_t so = SW128(r * 128 + g * 16);
        int ra = bm + r; int pa = (ra < M) ? 16 : 0; if (!pa) ra = 0;
        cpa16(sbase + so, Ah + (size_t)ra * lda + k0 + g * 8, pa);
        if constexpr (TERMS == 3)
            cpa16(sbase + 16384 + so, Al + (size_t)ra * lda + k0 + g * 8, pa);
    }
    #pragma unroll
    for (int it = 0; it < 4 * NBT; it++) {
        int e = it * 256 + tid;
        int r = e >> 3, g = e & 7;
        uint32_t so = SW128(r * 128 + g * 16);
        int rb = bn + r; int pb = (rb < N) ? 16 : 0; if (!pb) rb = 0;
        cpa16(sbase + ABYTES + so, Bh + (size_t)rb * ldb + k0 + g * 8, pb);
        if constexpr (TERMS == 3)
            cpa16(sbase + ABYTES + NBT * 16384 + so, Bl + (size_t)rb * ldb + k0 + g * 8, pb);
    }
    cp_commit();
}

template<int TERMS, int BN, int HOUT>
__global__ __launch_bounds__(256, 1) void gemm_h(
    const __half* __restrict__ Ah, const __half* __restrict__ Al,
    int lda, long long sA,
    const __half* __restrict__ Bh, const __half* __restrict__ Bl,
    int ldb, long long sB,
    void* __restrict__ Cv, int ldc, long long sC, int zdiv, long long sC2,
    const float* __restrict__ R, int ldr, long long sR,
    int M, int N, int K, float alpha, int causal)
{
    constexpr int OPS = (TERMS == 3) ? 2 : 1;
    constexpr int ABYTES = 16384 * OPS;
    constexpr int NBT = BN / 128;
    constexpr int STAGE = ABYTES + NBT * 16384 * OPS;
    constexpr int NST = (TERMS == 1) ? 4 : ((BN == 128) ? 3 : 2);
    constexpr int NG4 = BN / 64;
    constexpr int NS  = BN / 32;

    extern __shared__ __align__(1024) char smem[];
    const uint32_t sb0 = smem_u32(smem);
    const int tid = threadIdx.x;
    const int wid = tid >> 5, lane = tid & 31;
    long long z = blockIdx.z;
    Ah += z * sA;
    if constexpr (TERMS == 3) Al += z * sA;
    Bh += z * sB;
    if constexpr (TERMS == 3) Bl += z * sB;
    if (R) R += z * sR;
    const long long zo = (z / zdiv) * sC + (z % zdiv) * sC2;
    const int bm = blockIdx.y * 128, bn = blockIdx.x * BN;
    const int wm = (wid >> 2) * 64, wn = (wid & 3) * (BN / 4);

    if (causal == 1 && bn > bm + 127) return;

    float acc[4][NS][4];
    #pragma unroll
    for (int i = 0; i < 4; i++)
        #pragma unroll
        for (int j = 0; j < NS; j++)
            #pragma unroll
            for (int r = 0; r < 4; r++) acc[i][j][r] = 0.f;

    int nc = K >> 6;
    if (causal == 2) { int lim = (bm + 191) >> 6; if (lim < nc) nc = lim; }

    #pragma unroll
    for (int s = 0; s < NST - 1; s++) {
        if (s < nc)
            issue_h<TERMS, BN>(sb0 + s * STAGE, Ah, Al, Bh, Bl, lda, ldb, bm, bn, M, N, s << 6, tid);
        else
            cp_commit();
    }

    const int arow = wm + (lane & 15);
    const int acb  = (lane >> 4) << 4;
    const int brow4 = wn + ((lane >> 4) << 3) + (lane & 7);
    const int bcb4  = ((lane >> 3) & 1) << 4;

    for (int c = 0; c < nc; c++) {
        cp_wait<NST - 2>();
        __syncthreads();
        {
            int nx = c + NST - 1;
            if (nx < nc)
                issue_h<TERMS, BN>(sb0 + (nx % NST) * STAGE, Ah, Al, Bh, Bl,
                                   lda, ldb, bm, bn, M, N, nx << 6, tid);
            else
                cp_commit();
        }

        uint32_t tA  = sb0 + (c % NST) * STAGE;
        uint32_t tAl = tA + 16384;
        uint32_t tB  = tA + ABYTES;
        uint32_t tBl = tB + NBT * 16384;

        #pragma unroll
        for (int ks = 0; ks < 4; ks++) {
            uint32_t ah[4][4], al[4][4];
            #pragma unroll
            for (int ms = 0; ms < 4; ms++) {
                uint32_t off = SW128((arow + ms * 16) * 128 + ks * 32 + acb);
                ldsm_x4(ah[ms], tA + off);
                if constexpr (TERMS == 3) ldsm_x4(al[ms], tAl + off);
            }
            #pragma unroll
            for (int ng4 = 0; ng4 < NG4; ng4++) {
                uint32_t bh4[4], bl4[4];
                uint32_t off = SW128((brow4 + ng4 * 16) * 128 + ks * 32 + bcb4);
                ldsm_x4(bh4, tB + off);
                if constexpr (TERMS == 3) ldsm_x4(bl4, tBl + off);
                #pragma unroll
                for (int ms = 0; ms < 4; ms++) {
                    // interleaved term order: alternate the two acc chains
                    mma_f16(acc[ms][2*ng4],   ah[ms], bh4);
                    mma_f16(acc[ms][2*ng4+1], ah[ms], bh4 + 2);
                    if constexpr (TERMS == 3) {
                        mma_f16(acc[ms][2*ng4],   ah[ms], bl4);
                        mma_f16(acc[ms][2*ng4+1], ah[ms], bl4 + 2);
                        mma_f16(acc[ms][2*ng4],   al[ms], bh4);
                        mma_f16(acc[ms][2*ng4+1], al[ms], bh4 + 2);
                    }
                }
            }
        }
    }

    const int gid = lane >> 2, tc = lane & 3;
    if constexpr (HOUT == 2) {
        // gate/up fused: even col = gate, odd col = up; write silu(g)*u
        __half* C = (__half*)Cv + zo;
        #pragma unroll
        for (int ms = 0; ms < 4; ms++)
            #pragma unroll
            for (int ns = 0; ns < NS; ns++) {
                int gr0 = bm + wm + ms * 16 + gid;
                int gc  = bn + wn + ns * 8 + tc * 2;
                float g0 = acc[ms][ns][0], u0 = acc[ms][ns][1];
                float g1 = acc[ms][ns][2], u1 = acc[ms][ns][3];
                float r0 = g0 / (1.f + __expf(-g0)) * u0;
                float r1 = g1 / (1.f + __expf(-g1)) * u1;
                C[(size_t)gr0 * ldc + (gc >> 1)]       = __float2half_rn(r0);
                C[(size_t)(gr0 + 8) * ldc + (gc >> 1)] = __float2half_rn(r1);
            }
    } else if constexpr (HOUT == 1) {
        __half* C = (__half*)Cv + zo;
        #pragma unroll
        for (int ms = 0; ms < 4; ms++)
            #pragma unroll
            for (int ns = 0; ns < NS; ns++) {
                int gr0 = bm + wm + ms * 16 + gid;
                int gc  = bn + wn + ns * 8 + tc * 2;
                if (gc < N) {
                    *(__half2*)&C[(size_t)gr0 * ldc + gc] =
                        __floats2half2_rn(alpha * acc[ms][ns][0], alpha * acc[ms][ns][1]);
                    *(__half2*)&C[(size_t)(gr0 + 8) * ldc + gc] =
                        __floats2half2_rn(alpha * acc[ms][ns][2], alpha * acc[ms][ns][3]);
                }
            }
    } else {
        float* C = (float*)Cv + zo;
        #pragma unroll
        for (int ms = 0; ms < 4; ms++)
            #pragma unroll
            for (int ns = 0; ns < NS; ns++) {
                int gr0 = bm + wm + ms * 16 + gid;
                int gc  = bn + wn + ns * 8 + tc * 2;
                if (gc < N) {
                    float2 v0;
                    v0.x = alpha * acc[ms][ns][0];
                    v0.y = alpha * acc[ms][ns][1];
                    if (R) { v0.x += R[(size_t)gr0 * ldr + gc]; v0.y += R[(size_t)gr0 * ldr + gc + 1]; }
                    *(float2*)&C[(size_t)gr0 * ldc + gc] = v0;
                    int gr1 = gr0 + 8;
                    float2 v1;
                    v1.x = alpha * acc[ms][ns][2];
                    v1.y = alpha * acc[ms][ns][3];
                    if (R) { v1.x += R[(size_t)gr1 * ldr + gc]; v1.y += R[(size_t)gr1 * ldr + gc + 1]; }
                    *(float2*)&C[(size_t)gr1 * ldc + gc] = v1;
                }
            }
    }
}

#define SM_3_256 (2*(32768+65536))
#define SM_3_128 (3*(32768+32768))
#define SM_1_256 (4*(16384+32768))
#define SM_1_128 (4*(16384+16384))

// ------------------------------ host launch ---------------------------------
static void gemm3(const __half* Ah, const __half* Al, int lda, long long sA,
                  const __half* Bh, const __half* Bl, int ldb, long long sB,
                  float* C, int ldc, long long sC,
                  const float* R, int ldr, long long sR,
                  int M, int N, int K, float alpha, int Z, int causal = 0)
{
    if (N % 256 == 0) {
        dim3 grid(N / 256, M / 128, Z);
        gemm_h<3,256,0><<<grid, 256, SM_3_256>>>(Ah, Al, lda, sA, Bh, Bl, ldb, sB,
                                                 C, ldc, sC, 1, 0, R, ldr, sR, M, N, K, alpha, causal);
    } else {
        dim3 grid((N + 127) / 128, M / 128, Z);
        gemm_h<3,128,0><<<grid, 256, SM_3_128>>>(Ah, Al, lda, sA, Bh, Bl, ldb, sB,
                                                 C, ldc, sC, 1, 0, R, ldr, sR, M, N, K, alpha, causal);
    }
}
static void gemm1f(const __half* A, int lda, long long sA,
                   const __half* B, int ldb, long long sB,
                   float* C, int ldc, long long sC,
                   const float* R, int ldr, long long sR,
                   int M, int N, int K, float alpha, int Z, int causal = 0)
{
    if (N % 256 == 0) {
        dim3 grid(N / 256, M / 128, Z);
        gemm_h<1,256,0><<<grid, 256, SM_1_256>>>(A, nullptr, lda, sA, B, nullptr, ldb, sB,
                                                 C, ldc, sC, 1, 0, R, ldr, sR, M, N, K, alpha, causal);
    } else {
        dim3 grid((N + 127) / 128, M / 128, Z);
        gemm_h<1,128,0><<<grid, 256, SM_1_128>>>(A, nullptr, lda, sA, B, nullptr, ldb, sB,
                                                 C, ldc, sC, 1, 0, R, ldr, sR, M, N, K, alpha, causal);
    }
}

static void splitp(const float* in, __half* hi, __half* lo, long long n)
{
    long long n4 = n >> 2;
    split_h_k<<<(unsigned)((n4 + 255) / 256), 256>>>(
        (const float4*)in, (__half2*)hi, (__half2*)lo, n4);
}

extern "C" void kernel_launch(void* const* d_in, const int* in_sizes, int n_in,
                              void* d_out, int out_size)
{
    const float* x     = (const float*)d_in[0];
    const float* mask  = (const float*)d_in[1];
    const float* fcos  = (const float*)d_in[2];
    const float* fsin  = (const float*)d_in[3];
    const float* anw   = (const float*)d_in[4];
    const float* wq_a  = (const float*)d_in[5];
    const float* qnw   = (const float*)d_in[6];
    const float* wq_b  = (const float*)d_in[7];
    const float* wkv_a = (const float*)d_in[8];
    const float* kvnw  = (const float*)d_in[9];
    const float* wkv_b = (const float*)d_in[10];
    const float* wo    = (const float*)d_in[11];
    const float* fnw   = (const float*)d_in[12];
    const float* w1    = (const float*)d_in[13];
    const float* w2    = (const float*)d_in[14];
    const float* w3    = (const float*)d_in[15];
    float* out = (float*)d_out;

    cudaFuncSetAttribute(gemm_h<3,256,0>, cudaFuncAttributeMaxDynamicSharedMemorySize, SM_3_256);
    cudaFuncSetAttribute(gemm_h<3,128,0>, cudaFuncAttributeMaxDynamicSharedMemorySize, SM_3_128);
    cudaFuncSetAttribute(gemm_h<1,256,0>, cudaFuncAttributeMaxDynamicSharedMemorySize, SM_1_256);
    cudaFuncSetAttribute(gemm_h<1,128,0>, cudaFuncAttributeMaxDynamicSharedMemorySize, SM_1_128);
    cudaFuncSetAttribute(gemm_h<1,128,1>, cudaFuncAttributeMaxDynamicSharedMemorySize, SM_1_128);
    cudaFuncSetAttribute(gemm_h<1,256,2>, cudaFuncAttributeMaxDynamicSharedMemorySize, SM_1_256);

    float *p_qkva, *p_q, *p_kv, *p_sc, *p_x2;
    cudaGetSymbolAddress((void**)&p_qkva, g_qkva);
    cudaGetSymbolAddress((void**)&p_q,    g_q);
    cudaGetSymbolAddress((void**)&p_kv,   g_kv);
    cudaGetSymbolAddress((void**)&p_sc,   g_sc);
    cudaGetSymbolAddress((void**)&p_x2,   g_x2);

    __half *hH,*hL,*qaH,*qaL,*kvnH,*kvnL,*qfH,*qfL,*kfH,*kfL,*vT,*at,*y2,*h2,*gs,
           *wqkaH,*wqkaL,*wqbH,*wqbL,*wkbH,*wkbL,*woh,*w13h,*w2h;
    cudaGetSymbolAddress((void**)&hH,   f_hH);  cudaGetSymbolAddress((void**)&hL,   f_hL);
    cudaGetSymbolAddress((void**)&qaH,  f_qaH); cudaGetSymbolAddress((void**)&qaL,  f_qaL);
    cudaGetSymbolAddress((void**)&kvnH, f_kvnH);cudaGetSymbolAddress((void**)&kvnL, f_kvnL);
    cudaGetSymbolAddress((void**)&qfH,  f_qfH); cudaGetSymbolAddress((void**)&qfL,  f_qfL);
    cudaGetSymbolAddress((void**)&kfH,  f_kfH); cudaGetSymbolAddress((void**)&kfL,  f_kfL);
    cudaGetSymbolAddress((void**)&vT,   f_vT);  cudaGetSymbolAddress((void**)&at,   f_at);
    cudaGetSymbolAddress((void**)&y2,   f_y2);
    cudaGetSymbolAddress((void**)&h2,   f_h2);  cudaGetSymbolAddress((void**)&gs,   f_gs);
    cudaGetSymbolAddress((void**)&wqkaH,f_wqkaH);cudaGetSymbolAddress((void**)&wqkaL,f_wqkaL);
    cudaGetSymbolAddress((void**)&wqbH, f_wqbH);cudaGetSymbolAddress((void**)&wqbL, f_wqbL);
    cudaGetSymbolAddress((void**)&wkbH, f_wkbH);cudaGetSymbolAddress((void**)&wkbL, f_wkbL);
    cudaGetSymbolAddress((void**)&woh,  f_wo);
    cudaGetSymbolAddress((void**)&w13h, f_w13); cudaGetSymbolAddress((void**)&w2h,  f_w2);

    // weight conversions (independent; issue early)
    {
        long long n4big = ((long long)CINTER * CD) >> 2;
        long long n4wo  = ((long long)CD * CD) >> 2;
        dim3 grid((unsigned)((n4big + 255) / 256), 4);
        conv4_h_k<<<grid, 256>>>((const float4*)w1, (const float4*)w3,
                                 (const float4*)w2, (const float4*)wo,
                                 (__half2*)w13h, (__half2*)w2h, (__half2*)woh,
                                 n4big, n4wo);
    }

    // ---- attention path ----
    rmsnorm_split_h_k<<<CM, 256>>>(x, CD, anw, hH, hL, CD);
    splitp(wq_a,  wqkaH, wqkaL, (long long)CQLORA*CD);
    splitp(wkv_a, wqkaH + (long long)CQLORA*CD, wqkaL + (long long)CQLORA*CD,
           (long long)(CKVLORA+CROPE)*CD);
    // qkva = h @ [wq_a; wkv_a]^T
    gemm3(hH, hL, CD, 0, wqkaH, wqkaL, CD, 0, p_qkva, NQKVA, 0,
          nullptr, 0, 0, CM, NQKVA, CD, 1.f, 1);
    rmsnorm_split_h_k<<<CM, 256>>>(p_qkva, NQKVA, qnw, qaH, qaL, CQLORA);
    splitp(wq_b, wqbH, wqbL, (long long)CH*CQKD*CQLORA);
    // q = qa_norm @ wq_b^T
    gemm3(qaH, qaL, CQLORA, 0, wqbH, wqbL, CQLORA, 0, p_q, CH*CQKD, 0,
          nullptr, 0, 0, CM, CH*CQKD, CQLORA, 1.f, 1);
    rmsnorm_split_h_k<<<CM, 256>>>(p_qkva + CQLORA, NQKVA, kvnw, kvnH, kvnL, CKVLORA);
    splitp(wkv_b, wkbH, wkbL, (long long)CH*256*CKVLORA);
    // kv = kv_norm @ wkv_b^T
    gemm3(kvnH, kvnL, CKVLORA, 0, wkbH, wkbL, CKVLORA, 0, p_kv, CH*256, 0,
          nullptr, 0, 0, CM, CH*256, CKVLORA, 1.f, 1);
    rope_pack_h_k<<<dim3(CT, CB), 256>>>(p_q, p_kv, p_qkva, fcos, fsin,
                                         qfH, qfL, kfH, kfL, vT);
    // scores = -96 * qf @ kf^T + mask (masked tiles skipped; softmax fills zeros)
    gemm3(qfH, qfL, CQKD, (long long)CT*CQKD,
          kfH, kfL, CQKD, (long long)CT*CQKD,
          p_sc, CT, (long long)CT*CT,
          mask, CT, 0, CT, CT, CQKD, -96.f, CB*CH, 1);
    softmax_causal_h_k<<<CB*CH*CT, 256>>>(p_sc, at);
    // y2 = attn @ vT with fused [B,H,T,d] -> [B*T, H*d] permute in epilogue
    {
        dim3 grid(1, CT / 128, CB*CH);
        gemm_h<1,128,1><<<grid, 256, SM_1_128>>>(
            at, nullptr, CT, (long long)CT*CT,
            vT, nullptr, CT, (long long)CVHD*CT,
            y2, CD, (long long)CT*CD, CH, (long long)CVHD,
            nullptr, 0, 0, CT, CVHD, CT, 1.f, 2);
    }
    // x2 = x + y2 @ wo^T
    gemm1f(y2, CH*CVHD, 0, woh, CH*CVHD, 0, p_x2, CD, 0,
           x, CD, 0, CM, CD, CH*CVHD, 1.f, 1);

    // ---- FFN path ----
    rmsnorm_h_k<<<CM, 256>>>(p_x2, CD, fnw, h2, CD);
    // gs = silu(h2@w1^T) * (h2@w3^T) in ONE GEMM (w13 interleaved, fused epilogue)
    {
        dim3 grid((2*CINTER) / 256, CM / 128, 1);
        gemm_h<1,256,2><<<grid, 256, SM_1_256>>>(
            h2, nullptr, CD, 0,
            w13h, nullptr, CD, 0,
            gs, CINTER, 0, 1, 0,
            nullptr, 0, 0, CM, 2*CINTER, CD, 1.f, 0);
    }
    // out = x2 + gs @ w2^T
    gemm1f(gs, CINTER, 0, w2h, CINTER, 0, out, CD, 0,
           p_x2, CD, 0, CM, CD, CINTER, 1.f, 1);
}

// round 9
// speedup vs baseline: 5.6123x; 1.0115x over previous
#include <cuda_runtime.h>
#include <cuda_fp16.h>
#include <cstdint>

// ---------------------------------------------------------------------------
// DeepSeek MLA block on GB300 — mma.sync fp16 GEMMs, v7.
// q/k path: fp16-pair 3-term split. Additive paths: 1-term fp16.
// v7: fragment loads batched per ks-step + cross-ks double buffering
//     (volatile-asm ordering made the old ldsm->mma interleave serialize).
// ---------------------------------------------------------------------------

#define CB 2
#define CT 1024
#define CD 2048
#define CH 16
#define CNOPE 128
#define CROPE 64
#define CQKD 192
#define CQLORA 1536
#define CKVLORA 512
#define CVHD 128
#define CINTER 8192
#define CM (CB*CT)
#define NQKVA (CQLORA + CKVLORA + CROPE)   // 2112

// ------------------------------- PTX helpers -------------------------------
__device__ __forceinline__ uint32_t smem_u32(const void* p) {
    uint32_t a;
    asm("{ .reg .u64 t; cvta.to.shared.u64 t, %1; cvt.u32.u64 %0, t; }" : "=r"(a) : "l"(p));
    return a;
}
#define SW128(o) ((o) ^ (((o) >> 3) & 0x70))

__device__ __forceinline__ void cpa16(uint32_t s, const void* g, int sz) {
    asm volatile("cp.async.cg.shared.global [%0], [%1], 16, %2;"
                 :: "r"(s), "l"(g), "r"(sz));
}
__device__ __forceinline__ void cp_commit() {
    asm volatile("cp.async.commit_group;" ::: "memory");
}
template <int N> __device__ __forceinline__ void cp_wait() {
    asm volatile("cp.async.wait_group %0;" :: "n"(N) : "memory");
}
__device__ __forceinline__ void ldsm_x4(uint32_t* r, uint32_t a) {
    asm volatile("ldmatrix.sync.aligned.m8n8.x4.shared.b16 {%0,%1,%2,%3}, [%4];"
        : "=r"(r[0]), "=r"(r[1]), "=r"(r[2]), "=r"(r[3]) : "r"(a));
}
__device__ __forceinline__ void mma_f16(float* d, const uint32_t* a, const uint32_t* b) {
    asm volatile(
        "mma.sync.aligned.m16n8k16.row.col.f32.f16.f16.f32 "
        "{%0,%1,%2,%3}, {%4,%5,%6,%7}, {%8,%9}, {%0,%1,%2,%3};"
        : "+f"(d[0]), "+f"(d[1]), "+f"(d[2]), "+f"(d[3])
        : "r"(a[0]), "r"(a[1]), "r"(a[2]), "r"(a[3]), "r"(b[0]), "r"(b[1]));
}

// ------------------------- scratch (device globals) ------------------------
__device__ float g_qkva[(long long)CM*NQKVA];
__device__ float g_q   [(long long)CM*CH*CQKD];
__device__ float g_kv  [(long long)CM*CH*(CNOPE+CVHD)];
__device__ float g_sc  [(long long)CB*CH*CT*CT];
__device__ float g_x2  [(long long)CM*CD];

// fp16 operand buffers
__device__ __half f_hH [(long long)CM*CD],        f_hL [(long long)CM*CD];
__device__ __half f_qaH[(long long)CM*CQLORA],    f_qaL[(long long)CM*CQLORA];
__device__ __half f_kvnH[(long long)CM*CKVLORA],  f_kvnL[(long long)CM*CKVLORA];
__device__ __half f_qfH[(long long)CB*CH*CT*CQKD], f_qfL[(long long)CB*CH*CT*CQKD];
__device__ __half f_kfH[(long long)CB*CH*CT*CQKD], f_kfL[(long long)CB*CH*CT*CQKD];
__device__ __half f_vT [(long long)CB*CH*CVHD*CT];
__device__ __half f_at [(long long)CB*CH*CT*CT];
__device__ __half f_y2 [(long long)CM*CD];
__device__ __half f_h2 [(long long)CM*CD];
__device__ __half f_gs [(long long)CM*CINTER];
// weights
__device__ __half f_wqkaH[(long long)NQKVA*CD],   f_wqkaL[(long long)NQKVA*CD];
__device__ __half f_wqbH[(long long)CH*CQKD*CQLORA], f_wqbL[(long long)CH*CQKD*CQLORA];
__device__ __half f_wkbH[(long long)CH*256*CKVLORA], f_wkbL[(long long)CH*256*CKVLORA];
__device__ __half f_wo [(long long)CD*CD];
__device__ __half f_w13[(long long)2*CINTER*CD];   // interleaved: row 2j=w1_j, 2j+1=w3_j
__device__ __half f_w2 [(long long)CD*CINTER];

// ------------------------------- split helpers -----------------------------
__device__ __forceinline__ void split1h(float v, __half& h, __half& l) {
    h = __float2half_rn(v);
    l = __float2half_rn(v - __half2float(h));
}

__global__ __launch_bounds__(256) void split_h_k(
    const float4* __restrict__ in, __half2* __restrict__ hi,
    __half2* __restrict__ lo, long long n4)
{
    long long i = (long long)blockIdx.x * 256 + threadIdx.x;
    if (i >= n4) return;
    float4 v = in[i];
    __half h0,h1,h2,h3,l0,l1,l2,l3;
    split1h(v.x,h0,l0); split1h(v.y,h1,l1); split1h(v.z,h2,l2); split1h(v.w,h3,l3);
    hi[2*i]   = __halves2half2(h0,h1);
    hi[2*i+1] = __halves2half2(h2,h3);
    lo[2*i]   = __halves2half2(l0,l1);
    lo[2*i+1] = __halves2half2(l2,l3);
}

// convert w1 (interleave even rows), w3 (odd rows), w2 (straight), wo (straight)
__global__ __launch_bounds__(256) void conv4_h_k(
    const float4* __restrict__ w1, const float4* __restrict__ w3,
    const float4* __restrict__ w2, const float4* __restrict__ wo,
    __half2* __restrict__ w13, __half2* __restrict__ w2h, __half2* __restrict__ woh,
    long long n4big, long long n4wo)
{
    long long i = (long long)blockIdx.x * 256 + threadIdx.x;
    int which = blockIdx.y;
    if (which <= 1) {
        if (i >= n4big) return;
        const float4* s = which ? w3 : w1;
        float4 v = s[i];
        long long row = i / (CD/4), off = i % (CD/4);
        long long orow = 2*row + which;
        __half2* d = w13 + orow * (CD/2) + off*2;
        d[0] = __floats2half2_rn(v.x, v.y);
        d[1] = __floats2half2_rn(v.z, v.w);
    } else if (which == 2) {
        if (i >= n4big) return;
        float4 v = w2[i];
        w2h[2*i]   = __floats2half2_rn(v.x, v.y);
        w2h[2*i+1] = __floats2half2_rn(v.z, v.w);
    } else {
        if (i >= n4wo) return;
        float4 v = wo[i];
        woh[2*i]   = __floats2half2_rn(v.x, v.y);
        woh[2*i+1] = __floats2half2_rn(v.z, v.w);
    }
}

// ------------------------------ RMSNorm variants ----------------------------
__device__ __forceinline__ float rms_scale(const float* ip, int K, int tid) {
    float s = 0.f;
    for (int i = tid; i < K; i += 256) { float v = ip[i]; s += v * v; }
    __shared__ float red[32];
    #pragma unroll
    for (int o = 16; o > 0; o >>= 1) s += __shfl_xor_sync(0xffffffffu, s, o);
    int warp = tid >> 5, lane = tid & 31;
    if (lane == 0) red[warp] = s;
    __syncthreads();
    if (warp == 0) {
        float s2 = (lane < 8) ? red[lane] : 0.f;
        #pragma unroll
        for (int o = 4; o > 0; o >>= 1) s2 += __shfl_xor_sync(0xffffffffu, s2, o);
        if (lane == 0) red[0] = s2;
    }
    __syncthreads();
    return rsqrtf(red[0] / (float)K + 1e-6f);
}

__global__ __launch_bounds__(256) void rmsnorm_split_h_k(
    const float* __restrict__ in, int ldin, const float* __restrict__ w,
    __half* __restrict__ hi, __half* __restrict__ lo, int K)
{
    long long row = blockIdx.x;
    const float* ip = in + row * ldin;
    float scale = rms_scale(ip, K, threadIdx.x);
    for (int i = threadIdx.x; i < K; i += 256) {
        float v = ip[i] * scale * w[i];
        __half h, l; split1h(v, h, l);
        hi[row * (long long)K + i] = h;
        lo[row * (long long)K + i] = l;
    }
}

__global__ __launch_bounds__(256) void rmsnorm_h_k(
    const float* __restrict__ in, int ldin, const float* __restrict__ w,
    __half* __restrict__ out, int K)
{
    long long row = blockIdx.x;
    const float* ip = in + row * ldin;
    float scale = rms_scale(ip, K, threadIdx.x);
    for (int i = threadIdx.x; i < K; i += 256)
        out[row * (long long)K + i] = __float2half_rn(ip[i] * scale * w[i]);
}

// ------------------- RoPE + head packing (qf/kf pairs, vT single) -----------
__global__ __launch_bounds__(256) void rope_pack_h_k(
    const float* __restrict__ q, const float* __restrict__ kv,
    const float* __restrict__ qkva,
    const float* __restrict__ fcos, const float* __restrict__ fsin,
    __half* __restrict__ qfH, __half* __restrict__ qfL,
    __half* __restrict__ kfH, __half* __restrict__ kfL,
    __half* __restrict__ vT)
{
    int t = blockIdx.x, b = blockIdx.y;
    long long m = (long long)b * CT + t;
    __shared__ float kpe[CROPE], cs[32], sn[32];
    int tid = threadIdx.x;
    if (tid < 32) { cs[tid] = fcos[t*32 + tid]; sn[tid] = fsin[t*32 + tid]; }
    __syncthreads();
    if (tid < 32) {
        float x0 = qkva[m*NQKVA + 2048 + 2*tid];
        float x1 = qkva[m*NQKVA + 2048 + 2*tid + 1];
        kpe[2*tid]   = x0*cs[tid] - x1*sn[tid];
        kpe[2*tid+1] = x0*sn[tid] + x1*cs[tid];
    }
    __syncthreads();
    for (int idx = tid; idx < CH*CQKD; idx += 256) {
        int h = idx / CQKD, d = idx % CQKD;
        long long o = (((long long)b*CH + h)*CT + t)*CQKD + d;
        float qv, kvv;
        if (d < CNOPE) {
            qv  = q [m*(CH*CQKD) + h*CQKD + d];
            kvv = kv[m*(CH*256)  + h*256  + d];
        } else {
            int j = d - CNOPE, i2 = j >> 1;
            float x0 = q[m*(CH*CQKD) + h*CQKD + CNOPE + 2*i2];
            float x1 = q[m*(CH*CQKD) + h*CQKD + CNOPE + 2*i2 + 1];
            qv  = (j & 1) ? (x0*sn[i2] + x1*cs[i2]) : (x0*cs[i2] - x1*sn[i2]);
            kvv = kpe[j];
        }
        __half hh, ll;
        split1h(qv, hh, ll);  qfH[o] = hh; qfL[o] = ll;
        split1h(kvv, hh, ll); kfH[o] = hh; kfL[o] = ll;
    }
    for (int idx = tid; idx < CH*CVHD; idx += 256) {
        int h = idx >> 7, d = idx & 127;
        vT[(((long long)b*CH + h)*CVHD + d)*CT + t] =
            __float2half_rn(kv[m*(CH*256) + h*256 + CNOPE + d]);
    }
}

// ------------------- causal softmax (fp16 out, skip masked reads) -----------
__global__ __launch_bounds__(256) void softmax_causal_h_k(
    const float* __restrict__ s, __half* __restrict__ at)
{
    long long row = blockIdx.x;
    int sIdx = (int)(row & (CT - 1));
    const float4* p = (const float4*)(s + row * (long long)CT);
    int tid = threadIdx.x, warp = tid >> 5, lane = tid & 31;
    __shared__ float red[32];

    bool act = (4 * tid <= sIdx);
    float4 v = act ? p[tid] : make_float4(-1e30f, -1e30f, -1e30f, -1e30f);
    float mx = fmaxf(fmaxf(v.x, v.y), fmaxf(v.z, v.w));
    #pragma unroll
    for (int o = 16; o > 0; o >>= 1) mx = fmaxf(mx, __shfl_xor_sync(0xffffffffu, mx, o));
    if (lane == 0) red[warp] = mx;
    __syncthreads();
    if (warp == 0) {
        float m2 = (lane < 8) ? red[lane] : -1e30f;
        #pragma unroll
        for (int o = 4; o > 0; o >>= 1) m2 = fmaxf(m2, __shfl_xor_sync(0xffffffffu, m2, o));
        if (lane == 0) red[0] = m2;
    }
    __syncthreads();
    mx = red[0];
    __syncthreads();

    float sum = 0.f;
    if (act) {
        v.x = __expf(v.x - mx); v.y = __expf(v.y - mx);
        v.z = __expf(v.z - mx); v.w = __expf(v.w - mx);
        sum = v.x + v.y + v.z + v.w;
    }
    #pragma unroll
    for (int o = 16; o > 0; o >>= 1) sum += __shfl_xor_sync(0xffffffffu, sum, o);
    if (lane == 0) red[warp] = sum;
    __syncthreads();
    if (warp == 0) {
        float s2 = (lane < 8) ? red[lane] : 0.f;
        #pragma unroll
        for (int o = 4; o > 0; o >>= 1) s2 += __shfl_xor_sync(0xffffffffu, s2, o);
        if (lane == 0) red[0] = s2;
    }
    __syncthreads();
    float inv = 1.f / red[0];
    __half2* H = (__half2*)(at + row * (long long)CT);
    if (act) {
        H[2*tid]   = __floats2half2_rn(v.x * inv, v.y * inv);
        H[2*tid+1] = __floats2half2_rn(v.z * inv, v.w * inv);
    } else {
        H[2*tid]   = __halves2half2(__float2half_rn(0.f), __float2half_rn(0.f));
        H[2*tid+1] = H[2*tid];
    }
}

// ======================= templated fp16 HMMA GEMM ===========================
// TERMS=3: C = alpha*(Ah@Bh + Ah@Bl + Al@Bh) [+R];  TERMS=1: C = alpha*Ah@Bh [+R]
// HOUT: 0=float(+R), 1=half, 2=gu-fused (silu(even col)*odd col -> half)
// C offset per z: (z/zdiv)*sC + (z%zdiv)*sC2
// causal: 1 = skip when bn > bm+127;  2 = truncate K at bm+128.
template<int TERMS, int BN>
__device__ __forceinline__ void issue_h(
    uint32_t sbase, const __half* Ah, const __half* Al,
    const __half* Bh, const __half* Bl,
    int lda, int ldb, int bm, int bn, int M, int N, int k0, int tid)
{
    constexpr int OPS = (TERMS == 3) ? 2 : 1;
    constexpr int ABYTES = 16384 * OPS;
    constexpr int NBT = BN / 128;
    #pragma unroll
    for (int it = 0; it < 4; it++) {
        int e = it * 256 + tid;
        int r = e >> 3, g = e & 7;
        uint32_t so = SW128(r * 128 + g * 16);
        int ra = bm + r; int pa = (ra < M) ? 16 : 0; if (!pa) ra = 0;
        cpa16(sbase + so, Ah + (size_t)ra * lda + k0 + g * 8, pa);
        if constexpr (TERMS == 3)
            cpa16(sbase + 16384 + so, Al + (size_t)ra * lda + k0 + g * 8, pa);
    }
    #pragma unroll
    for (int it = 0; it < 4 * NBT; it++) {
        int e = it * 256 + tid;
        int r = e >> 3, g = e & 7;
        uint32_t so = SW128(r * 128 + g * 16);
        int rb = bn + r; int pb = (rb < N) ? 16 : 0; if (!pb) rb = 0;
        cpa16(sbase + ABYTES + so, Bh + (size_t)rb * ldb + k0 + g * 8, pb);
        if constexpr (TERMS == 3)
            cpa16(sbase + ABYTES + NBT * 16384 + so, Bl + (size_t)rb * ldb + k0 + g * 8, pb);
    }
    cp_commit();
}

template<int TERMS, int BN, int HOUT>
__global__ __launch_bounds__(256, 1) void gemm_h(
    const __half* __restrict__ Ah, const __half* __restrict__ Al,
    int lda, long long sA,
    const __half* __restrict__ Bh, const __half* __restrict__ Bl,
    int ldb, long long sB,
    void* __restrict__ Cv, int ldc, long long sC, int zdiv, long long sC2,
    const float* __restrict__ R, int ldr, long long sR,
    int M, int N, int K, float alpha, int causal)
{
    constexpr int OPS = (TERMS == 3) ? 2 : 1;
    constexpr int ABYTES = 16384 * OPS;
    constexpr int NBT = BN / 128;
    constexpr int STAGE = ABYTES + NBT * 16384 * OPS;
    constexpr int NST = (TERMS == 1) ? 4 : ((BN == 128) ? 3 : 2);
    constexpr int NG4 = BN / 64;
    constexpr int NS  = BN / 32;
    // cross-ks double buffering where registers allow
    constexpr int NBUF = (TERMS == 1 || BN == 128) ? 2 : 1;

    extern __shared__ __align__(1024) char smem[];
    const uint32_t sb0 = smem_u32(smem);
    const int tid = threadIdx.x;
    const int wid = tid >> 5, lane = tid & 31;
    long long z = blockIdx.z;
    Ah += z * sA;
    if constexpr (TERMS == 3) Al += z * sA;
    Bh += z * sB;
    if constexpr (TERMS == 3) Bl += z * sB;
    if (R) R += z * sR;
    const long long zo = (z / zdiv) * sC + (z % zdiv) * sC2;
    const int bm = blockIdx.y * 128, bn = blockIdx.x * BN;
    const int wm = (wid >> 2) * 64, wn = (wid & 3) * (BN / 4);

    if (causal == 1 && bn > bm + 127) return;

    float acc[4][NS][4];
    #pragma unroll
    for (int i = 0; i < 4; i++)
        #pragma unroll
        for (int j = 0; j < NS; j++)
            #pragma unroll
            for (int r = 0; r < 4; r++) acc[i][j][r] = 0.f;

    int nc = K >> 6;
    if (causal == 2) { int lim = (bm + 191) >> 6; if (lim < nc) nc = lim; }

    #pragma unroll
    for (int s = 0; s < NST - 1; s++) {
        if (s < nc)
            issue_h<TERMS, BN>(sb0 + s * STAGE, Ah, Al, Bh, Bl, lda, ldb, bm, bn, M, N, s << 6, tid);
        else
            cp_commit();
    }

    const int arow = wm + (lane & 15);
    const int acb  = (lane >> 4) << 4;
    const int brow4 = wn + ((lane >> 4) << 3) + (lane & 7);
    const int bcb4  = ((lane >> 3) & 1) << 4;

    // fragment register buffers
    uint32_t ahf[NBUF][4][4], alf[NBUF][4][4];
    uint32_t bhf[NBUF][NG4][4], blf[NBUF][NG4][4];
    (void)alf; (void)blf;

    for (int c = 0; c < nc; c++) {
        cp_wait<NST - 2>();
        __syncthreads();
        {
            int nx = c + NST - 1;
            if (nx < nc)
                issue_h<TERMS, BN>(sb0 + (nx % NST) * STAGE, Ah, Al, Bh, Bl,
                                   lda, ldb, bm, bn, M, N, nx << 6, tid);
            else
                cp_commit();
        }

        uint32_t tA  = sb0 + (c % NST) * STAGE;
        uint32_t tAl = tA + 16384;
        uint32_t tB  = tA + ABYTES;
        uint32_t tBl = tB + NBT * 16384;

        // batched fragment load for one ks into buffer b (all LDSM back-to-back)
        #define LOAD_FRAGS(ksv, b) do {                                          \
            _Pragma("unroll")                                                    \
            for (int ms = 0; ms < 4; ms++) {                                     \
                uint32_t off = SW128((arow + ms * 16) * 128 + (ksv) * 32 + acb); \
                ldsm_x4(ahf[b][ms], tA + off);                                   \
                if constexpr (TERMS == 3) ldsm_x4(alf[b][ms], tAl + off);        \
            }                                                                    \
            _Pragma("unroll")                                                    \
            for (int ng4 = 0; ng4 < NG4; ng4++) {                                \
                uint32_t off = SW128((brow4 + ng4 * 16) * 128 + (ksv) * 32 + bcb4); \
                ldsm_x4(bhf[b][ng4], tB + off);                                  \
                if constexpr (TERMS == 3) ldsm_x4(blf[b][ng4], tBl + off);       \
            }                                                                    \
        } while (0)

        #define DO_MMAS(b) do {                                                  \
            _Pragma("unroll")                                                    \
            for (int ng4 = 0; ng4 < NG4; ng4++)                                  \
                _Pragma("unroll")                                                \
                for (int ms = 0; ms < 4; ms++) {                                 \
                    mma_f16(acc[ms][2*ng4],   ahf[b][ms], bhf[b][ng4]);          \
                    mma_f16(acc[ms][2*ng4+1], ahf[b][ms], bhf[b][ng4] + 2);      \
                    if constexpr (TERMS == 3) {                                  \
                        mma_f16(acc[ms][2*ng4],   ahf[b][ms], blf[b][ng4]);      \
                        mma_f16(acc[ms][2*ng4+1], ahf[b][ms], blf[b][ng4] + 2);  \
                        mma_f16(acc[ms][2*ng4],   alf[b][ms], bhf[b][ng4]);      \
                        mma_f16(acc[ms][2*ng4+1], alf[b][ms], bhf[b][ng4] + 2);  \
                    }                                                            \
                }                                                                \
        } while (0)

        if constexpr (NBUF == 2) {
            LOAD_FRAGS(0, 0);
            #pragma unroll
            for (int ks = 0; ks < 4; ks++) {
                if (ks < 3) LOAD_FRAGS(ks + 1, (ks + 1) & 1);
                DO_MMAS(ks & 1);
            }
        } else {
            #pragma unroll
            for (int ks = 0; ks < 4; ks++) {
                LOAD_FRAGS(ks, 0);
                DO_MMAS(0);
            }
        }
        #undef LOAD_FRAGS
        #undef DO_MMAS
    }

    const int gid = lane >> 2, tc = lane & 3;
    if constexpr (HOUT == 2) {
        __half* C = (__half*)Cv + zo;
        #pragma unroll
        for (int ms = 0; ms < 4; ms++)
            #pragma unroll
            for (int ns = 0; ns < NS; ns++) {
                int gr0 = bm + wm + ms * 16 + gid;
                int gc  = bn + wn + ns * 8 + tc * 2;
                float g0 = acc[ms][ns][0], u0 = acc[ms][ns][1];
                float g1 = acc[ms][ns][2], u1 = acc[ms][ns][3];
                float r0 = g0 / (1.f + __expf(-g0)) * u0;
                float r1 = g1 / (1.f + __expf(-g1)) * u1;
                C[(size_t)gr0 * ldc + (gc >> 1)]       = __float2half_rn(r0);
                C[(size_t)(gr0 + 8) * ldc + (gc >> 1)] = __float2half_rn(r1);
            }
    } else if constexpr (HOUT == 1) {
        __half* C = (__half*)Cv + zo;
        #pragma unroll
        for (int ms = 0; ms < 4; ms++)
            #pragma unroll
            for (int ns = 0; ns < NS; ns++) {
                int gr0 = bm + wm + ms * 16 + gid;
                int gc  = bn + wn + ns * 8 + tc * 2;
                if (gc < N) {
                    *(__half2*)&C[(size_t)gr0 * ldc + gc] =
                        __floats2half2_rn(alpha * acc[ms][ns][0], alpha * acc[ms][ns][1]);
                    *(__half2*)&C[(size_t)(gr0 + 8) * ldc + gc] =
                        __floats2half2_rn(alpha * acc[ms][ns][2], alpha * acc[ms][ns][3]);
                }
            }
    } else {
        float* C = (float*)Cv + zo;
        #pragma unroll
        for (int ms = 0; ms < 4; ms++)
            #pragma unroll
            for (int ns = 0; ns < NS; ns++) {
                int gr0 = bm + wm + ms * 16 + gid;
                int gc  = bn + wn + ns * 8 + tc * 2;
                if (gc < N) {
                    float2 v0;
                    v0.x = alpha * acc[ms][ns][0];
                    v0.y = alpha * acc[ms][ns][1];
                    if (R) { v0.x += R[(size_t)gr0 * ldr + gc]; v0.y += R[(size_t)gr0 * ldr + gc + 1]; }
                    *(float2*)&C[(size_t)gr0 * ldc + gc] = v0;
                    int gr1 = gr0 + 8;
                    float2 v1;
                    v1.x = alpha * acc[ms][ns][2];
                    v1.y = alpha * acc[ms][ns][3];
                    if (R) { v1.x += R[(size_t)gr1 * ldr + gc]; v1.y += R[(size_t)gr1 * ldr + gc + 1]; }
                    *(float2*)&C[(size_t)gr1 * ldc + gc] = v1;
                }
            }
    }
}

#define SM_3_256 (2*(32768+65536))
#define SM_3_128 (3*(32768+32768))
#define SM_1_256 (4*(16384+32768))
#define SM_1_128 (4*(16384+16384))

// ------------------------------ host launch ---------------------------------
static void gemm3(const __half* Ah, const __half* Al, int lda, long long sA,
                  const __half* Bh, const __half* Bl, int ldb, long long sB,
                  float* C, int ldc, long long sC,
                  const float* R, int ldr, long long sR,
                  int M, int N, int K, float alpha, int Z, int causal = 0)
{
    if (N % 256 == 0) {
        dim3 grid(N / 256, M / 128, Z);
        gemm_h<3,256,0><<<grid, 256, SM_3_256>>>(Ah, Al, lda, sA, Bh, Bl, ldb, sB,
                                                 C, ldc, sC, 1, 0, R, ldr, sR, M, N, K, alpha, causal);
    } else {
        dim3 grid((N + 127) / 128, M / 128, Z);
        gemm_h<3,128,0><<<grid, 256, SM_3_128>>>(Ah, Al, lda, sA, Bh, Bl, ldb, sB,
                                                 C, ldc, sC, 1, 0, R, ldr, sR, M, N, K, alpha, causal);
    }
}
static void gemm1f(const __half* A, int lda, long long sA,
                   const __half* B, int ldb, long long sB,
                   float* C, int ldc, long long sC,
                   const float* R, int ldr, long long sR,
                   int M, int N, int K, float alpha, int Z, int causal = 0)
{
    if (N % 256 == 0) {
        dim3 grid(N / 256, M / 128, Z);
        gemm_h<1,256,0><<<grid, 256, SM_1_256>>>(A, nullptr, lda, sA, B, nullptr, ldb, sB,
                                                 C, ldc, sC, 1, 0, R, ldr, sR, M, N, K, alpha, causal);
    } else {
        dim3 grid((N + 127) / 128, M / 128, Z);
        gemm_h<1,128,0><<<grid, 256, SM_1_128>>>(A, nullptr, lda, sA, B, nullptr, ldb, sB,
                                                 C, ldc, sC, 1, 0, R, ldr, sR, M, N, K, alpha, causal);
    }
}

static void splitp(const float* in, __half* hi, __half* lo, long long n)
{
    long long n4 = n >> 2;
    split_h_k<<<(unsigned)((n4 + 255) / 256), 256>>>(
        (const float4*)in, (__half2*)hi, (__half2*)lo, n4);
}

extern "C" void kernel_launch(void* const* d_in, const int* in_sizes, int n_in,
                              void* d_out, int out_size)
{
    const float* x     = (const float*)d_in[0];
    const float* mask  = (const float*)d_in[1];
    const float* fcos  = (const float*)d_in[2];
    const float* fsin  = (const float*)d_in[3];
    const float* anw   = (const float*)d_in[4];
    const float* wq_a  = (const float*)d_in[5];
    const float* qnw   = (const float*)d_in[6];
    const float* wq_b  = (const float*)d_in[7];
    const float* wkv_a = (const float*)d_in[8];
    const float* kvnw  = (const float*)d_in[9];
    const float* wkv_b = (const float*)d_in[10];
    const float* wo    = (const float*)d_in[11];
    const float* fnw   = (const float*)d_in[12];
    const float* w1    = (const float*)d_in[13];
    const float* w2    = (const float*)d_in[14];
    const float* w3    = (const float*)d_in[15];
    float* out = (float*)d_out;

    cudaFuncSetAttribute(gemm_h<3,256,0>, cudaFuncAttributeMaxDynamicSharedMemorySize, SM_3_256);
    cudaFuncSetAttribute(gemm_h<3,128,0>, cudaFuncAttributeMaxDynamicSharedMemorySize, SM_3_128);
    cudaFuncSetAttribute(gemm_h<1,256,0>, cudaFuncAttributeMaxDynamicSharedMemorySize, SM_1_256);
    cudaFuncSetAttribute(gemm_h<1,128,0>, cudaFuncAttributeMaxDynamicSharedMemorySize, SM_1_128);
    cudaFuncSetAttribute(gemm_h<1,128,1>, cudaFuncAttributeMaxDynamicSharedMemorySize, SM_1_128);
    cudaFuncSetAttribute(gemm_h<1,256,2>, cudaFuncAttributeMaxDynamicSharedMemorySize, SM_1_256);

    float *p_qkva, *p_q, *p_kv, *p_sc, *p_x2;
    cudaGetSymbolAddress((void**)&p_qkva, g_qkva);
    cudaGetSymbolAddress((void**)&p_q,    g_q);
    cudaGetSymbolAddress((void**)&p_kv,   g_kv);
    cudaGetSymbolAddress((void**)&p_sc,   g_sc);
    cudaGetSymbolAddress((void**)&p_x2,   g_x2);

    __half *hH,*hL,*qaH,*qaL,*kvnH,*kvnL,*qfH,*qfL,*kfH,*kfL,*vT,*at,*y2,*h2,*gs,
           *wqkaH,*wqkaL,*wqbH,*wqbL,*wkbH,*wkbL,*woh,*w13h,*w2h;
    cudaGetSymbolAddress((void**)&hH,   f_hH);  cudaGetSymbolAddress((void**)&hL,   f_hL);
    cudaGetSymbolAddress((void**)&qaH,  f_qaH); cudaGetSymbolAddress((void**)&qaL,  f_qaL);
    cudaGetSymbolAddress((void**)&kvnH, f_kvnH);cudaGetSymbolAddress((void**)&kvnL, f_kvnL);
    cudaGetSymbolAddress((void**)&qfH,  f_qfH); cudaGetSymbolAddress((void**)&qfL,  f_qfL);
    cudaGetSymbolAddress((void**)&kfH,  f_kfH); cudaGetSymbolAddress((void**)&kfL,  f_kfL);
    cudaGetSymbolAddress((void**)&vT,   f_vT);  cudaGetSymbolAddress((void**)&at,   f_at);
    cudaGetSymbolAddress((void**)&y2,   f_y2);
    cudaGetSymbolAddress((void**)&h2,   f_h2);  cudaGetSymbolAddress((void**)&gs,   f_gs);
    cudaGetSymbolAddress((void**)&wqkaH,f_wqkaH);cudaGetSymbolAddress((void**)&wqkaL,f_wqkaL);
    cudaGetSymbolAddress((void**)&wqbH, f_wqbH);cudaGetSymbolAddress((void**)&wqbL, f_wqbL);
    cudaGetSymbolAddress((void**)&wkbH, f_wkbH);cudaGetSymbolAddress((void**)&wkbL, f_wkbL);
    cudaGetSymbolAddress((void**)&woh,  f_wo);
    cudaGetSymbolAddress((void**)&w13h, f_w13); cudaGetSymbolAddress((void**)&w2h,  f_w2);

    // weight conversions (independent; issue early)
    {
        long long n4big = ((long long)CINTER * CD) >> 2;
        long long n4wo  = ((long long)CD * CD) >> 2;
        dim3 grid((unsigned)((n4big + 255) / 256), 4);
        conv4_h_k<<<grid, 256>>>((const float4*)w1, (const float4*)w3,
                                 (const float4*)w2, (const float4*)wo,
                                 (__half2*)w13h, (__half2*)w2h, (__half2*)woh,
                                 n4big, n4wo);
    }

    // ---- attention path ----
    rmsnorm_split_h_k<<<CM, 256>>>(x, CD, anw, hH, hL, CD);
    splitp(wq_a,  wqkaH, wqkaL, (long long)CQLORA*CD);
    splitp(wkv_a, wqkaH + (long long)CQLORA*CD, wqkaL + (long long)CQLORA*CD,
           (long long)(CKVLORA+CROPE)*CD);
    // qkva = h @ [wq_a; wkv_a]^T
    gemm3(hH, hL, CD, 0, wqkaH, wqkaL, CD, 0, p_qkva, NQKVA, 0,
          nullptr, 0, 0, CM, NQKVA, CD, 1.f, 1);
    rmsnorm_split_h_k<<<CM, 256>>>(p_qkva, NQKVA, qnw, qaH, qaL, CQLORA);
    splitp(wq_b, wqbH, wqbL, (long long)CH*CQKD*CQLORA);
    // q = qa_norm @ wq_b^T
    gemm3(qaH, qaL, CQLORA, 0, wqbH, wqbL, CQLORA, 0, p_q, CH*CQKD, 0,
          nullptr, 0, 0, CM, CH*CQKD, CQLORA, 1.f, 1);
    rmsnorm_split_h_k<<<CM, 256>>>(p_qkva + CQLORA, NQKVA, kvnw, kvnH, kvnL, CKVLORA);
    splitp(wkv_b, wkbH, wkbL, (long long)CH*256*CKVLORA);
    // kv = kv_norm @ wkv_b^T
    gemm3(kvnH, kvnL, CKVLORA, 0, wkbH, wkbL, CKVLORA, 0, p_kv, CH*256, 0,
          nullptr, 0, 0, CM, CH*256, CKVLORA, 1.f, 1);
    rope_pack_h_k<<<dim3(CT, CB), 256>>>(p_q, p_kv, p_qkva, fcos, fsin,
                                         qfH, qfL, kfH, kfL, vT);
    // scores = -96 * qf @ kf^T + mask (masked tiles skipped; softmax fills zeros)
    gemm3(qfH, qfL, CQKD, (long long)CT*CQKD,
          kfH, kfL, CQKD, (long long)CT*CQKD,
          p_sc, CT, (long long)CT*CT,
          mask, CT, 0, CT, CT, CQKD, -96.f, CB*CH, 1);
    softmax_causal_h_k<<<CB*CH*CT, 256>>>(p_sc, at);
    // y2 = attn @ vT with fused [B,H,T,d] -> [B*T, H*d] permute in epilogue
    {
        dim3 grid(1, CT / 128, CB*CH);
        gemm_h<1,128,1><<<grid, 256, SM_1_128>>>(
            at, nullptr, CT, (long long)CT*CT,
            vT, nullptr, CT, (long long)CVHD*CT,
            y2, CD, (long long)CT*CD, CH, (long long)CVHD,
            nullptr, 0, 0, CT, CVHD, CT, 1.f, 2);
    }
    // x2 = x + y2 @ wo^T
    gemm1f(y2, CH*CVHD, 0, woh, CH*CVHD, 0, p_x2, CD, 0,
           x, CD, 0, CM, CD, CH*CVHD, 1.f, 1);

    // ---- FFN path ----
    rmsnorm_h_k<<<CM, 256>>>(p_x2, CD, fnw, h2, CD);
    // gs = silu(h2@w1^T) * (h2@w3^T) in ONE GEMM (w13 interleaved, fused epilogue)
    {
        dim3 grid((2*CINTER) / 256, CM / 128, 1);
        gemm_h<1,256,2><<<grid, 256, SM_1_256>>>(
            h2, nullptr, CD, 0,
            w13h, nullptr, CD, 0,
            gs, CINTER, 0, 1, 0,
            nullptr, 0, 0, CM, 2*CINTER, CD, 1.f, 0);
    }
    // out = x2 + gs @ w2^T
    gemm1f(gs, CINTER, 0, w2h, CINTER, 0, out, CD, 0,
           p_x2, CD, 0, CM, CD, CINTER, 1.f, 1);
}

// round 10
// speedup vs baseline: 5.7927x; 1.0322x over previous
#include <cuda_runtime.h>
#include <cuda_fp16.h>
#include <cstdint>

// ---------------------------------------------------------------------------
// DeepSeek MLA block on GB300 — mma.sync fp16 GEMMs, v8.
// q/k path: fp16-pair 3-term split. Additive paths: 1-term fp16.
// v8: 512-thread GEMM CTAs (16 warps = 4/SMSP) with half-size warp tiles,
//     to fill the HMMA issue cadence (rt_SMSP~8cyc). 3-term via BN=128 only.
// ---------------------------------------------------------------------------

#define CB 2
#define CT 1024
#define CD 2048
#define CH 16
#define CNOPE 128
#define CROPE 64
#define CQKD 192
#define CQLORA 1536
#define CKVLORA 512
#define CVHD 128
#define CINTER 8192
#define CM (CB*CT)
#define NQKVA (CQLORA + CKVLORA + CROPE)   // 2112

// ------------------------------- PTX helpers -------------------------------
__device__ __forceinline__ uint32_t smem_u32(const void* p) {
    uint32_t a;
    asm("{ .reg .u64 t; cvta.to.shared.u64 t, %1; cvt.u32.u64 %0, t; }" : "=r"(a) : "l"(p));
    return a;
}
#define SW128(o) ((o) ^ (((o) >> 3) & 0x70))

__device__ __forceinline__ void cpa16(uint32_t s, const void* g, int sz) {
    asm volatile("cp.async.cg.shared.global [%0], [%1], 16, %2;"
                 :: "r"(s), "l"(g), "r"(sz));
}
__device__ __forceinline__ void cp_commit() {
    asm volatile("cp.async.commit_group;" ::: "memory");
}
template <int N> __device__ __forceinline__ void cp_wait() {
    asm volatile("cp.async.wait_group %0;" :: "n"(N) : "memory");
}
__device__ __forceinline__ void ldsm_x4(uint32_t* r, uint32_t a) {
    asm volatile("ldmatrix.sync.aligned.m8n8.x4.shared.b16 {%0,%1,%2,%3}, [%4];"
        : "=r"(r[0]), "=r"(r[1]), "=r"(r[2]), "=r"(r[3]) : "r"(a));
}
__device__ __forceinline__ void mma_f16(float* d, const uint32_t* a, const uint32_t* b) {
    asm volatile(
        "mma.sync.aligned.m16n8k16.row.col.f32.f16.f16.f32 "
        "{%0,%1,%2,%3}, {%4,%5,%6,%7}, {%8,%9}, {%0,%1,%2,%3};"
        : "+f"(d[0]), "+f"(d[1]), "+f"(d[2]), "+f"(d[3])
        : "r"(a[0]), "r"(a[1]), "r"(a[2]), "r"(a[3]), "r"(b[0]), "r"(b[1]));
}

// ------------------------- scratch (device globals) ------------------------
__device__ float g_qkva[(long long)CM*NQKVA];
__device__ float g_q   [(long long)CM*CH*CQKD];
__device__ float g_kv  [(long long)CM*CH*(CNOPE+CVHD)];
__device__ float g_sc  [(long long)CB*CH*CT*CT];
__device__ float g_x2  [(long long)CM*CD];

// fp16 operand buffers
__device__ __half f_hH [(long long)CM*CD],        f_hL [(long long)CM*CD];
__device__ __half f_qaH[(long long)CM*CQLORA],    f_qaL[(long long)CM*CQLORA];
__device__ __half f_kvnH[(long long)CM*CKVLORA],  f_kvnL[(long long)CM*CKVLORA];
__device__ __half f_qfH[(long long)CB*CH*CT*CQKD], f_qfL[(long long)CB*CH*CT*CQKD];
__device__ __half f_kfH[(long long)CB*CH*CT*CQKD], f_kfL[(long long)CB*CH*CT*CQKD];
__device__ __half f_vT [(long long)CB*CH*CVHD*CT];
__device__ __half f_at [(long long)CB*CH*CT*CT];
__device__ __half f_y2 [(long long)CM*CD];
__device__ __half f_h2 [(long long)CM*CD];
__device__ __half f_gs [(long long)CM*CINTER];
// weights
__device__ __half f_wqkaH[(long long)NQKVA*CD],   f_wqkaL[(long long)NQKVA*CD];
__device__ __half f_wqbH[(long long)CH*CQKD*CQLORA], f_wqbL[(long long)CH*CQKD*CQLORA];
__device__ __half f_wkbH[(long long)CH*256*CKVLORA], f_wkbL[(long long)CH*256*CKVLORA];
__device__ __half f_wo [(long long)CD*CD];
__device__ __half f_w13[(long long)2*CINTER*CD];   // interleaved: row 2j=w1_j, 2j+1=w3_j
__device__ __half f_w2 [(long long)CD*CINTER];

// ------------------------------- split helpers -----------------------------
__device__ __forceinline__ void split1h(float v, __half& h, __half& l) {
    h = __float2half_rn(v);
    l = __float2half_rn(v - __half2float(h));
}

__global__ __launch_bounds__(256) void split_h_k(
    const float4* __restrict__ in, __half2* __restrict__ hi,
    __half2* __restrict__ lo, long long n4)
{
    long long i = (long long)blockIdx.x * 256 + threadIdx.x;
    if (i >= n4) return;
    float4 v = in[i];
    __half h0,h1,h2,h3,l0,l1,l2,l3;
    split1h(v.x,h0,l0); split1h(v.y,h1,l1); split1h(v.z,h2,l2); split1h(v.w,h3,l3);
    hi[2*i]   = __halves2half2(h0,h1);
    hi[2*i+1] = __halves2half2(h2,h3);
    lo[2*i]   = __halves2half2(l0,l1);
    lo[2*i+1] = __halves2half2(l2,l3);
}

// convert w1 (interleave even rows), w3 (odd rows), w2 (straight), wo (straight)
__global__ __launch_bounds__(256) void conv4_h_k(
    const float4* __restrict__ w1, const float4* __restrict__ w3,
    const float4* __restrict__ w2, const float4* __restrict__ wo,
    __half2* __restrict__ w13, __half2* __restrict__ w2h, __half2* __restrict__ woh,
    long long n4big, long long n4wo)
{
    long long i = (long long)blockIdx.x * 256 + threadIdx.x;
    int which = blockIdx.y;
    if (which <= 1) {
        if (i >= n4big) return;
        const float4* s = which ? w3 : w1;
        float4 v = s[i];
        long long row = i / (CD/4), off = i % (CD/4);
        long long orow = 2*row + which;
        __half2* d = w13 + orow * (CD/2) + off*2;
        d[0] = __floats2half2_rn(v.x, v.y);
        d[1] = __floats2half2_rn(v.z, v.w);
    } else if (which == 2) {
        if (i >= n4big) return;
        float4 v = w2[i];
        w2h[2*i]   = __floats2half2_rn(v.x, v.y);
        w2h[2*i+1] = __floats2half2_rn(v.z, v.w);
    } else {
        if (i >= n4wo) return;
        float4 v = wo[i];
        woh[2*i]   = __floats2half2_rn(v.x, v.y);
        woh[2*i+1] = __floats2half2_rn(v.z, v.w);
    }
}

// ------------------------------ RMSNorm variants ----------------------------
__device__ __forceinline__ float rms_scale(const float* ip, int K, int tid) {
    float s = 0.f;
    for (int i = tid; i < K; i += 256) { float v = ip[i]; s += v * v; }
    __shared__ float red[32];
    #pragma unroll
    for (int o = 16; o > 0; o >>= 1) s += __shfl_xor_sync(0xffffffffu, s, o);
    int warp = tid >> 5, lane = tid & 31;
    if (lane == 0) red[warp] = s;
    __syncthreads();
    if (warp == 0) {
        float s2 = (lane < 8) ? red[lane] : 0.f;
        #pragma unroll
        for (int o = 4; o > 0; o >>= 1) s2 += __shfl_xor_sync(0xffffffffu, s2, o);
        if (lane == 0) red[0] = s2;
    }
    __syncthreads();
    return rsqrtf(red[0] / (float)K + 1e-6f);
}

__global__ __launch_bounds__(256) void rmsnorm_split_h_k(
    const float* __restrict__ in, int ldin, const float* __restrict__ w,
    __half* __restrict__ hi, __half* __restrict__ lo, int K)
{
    long long row = blockIdx.x;
    const float* ip = in + row * ldin;
    float scale = rms_scale(ip, K, threadIdx.x);
    for (int i = threadIdx.x; i < K; i += 256) {
        float v = ip[i] * scale * w[i];
        __half h, l; split1h(v, h, l);
        hi[row * (long long)K + i] = h;
        lo[row * (long long)K + i] = l;
    }
}

__global__ __launch_bounds__(256) void rmsnorm_h_k(
    const float* __restrict__ in, int ldin, const float* __restrict__ w,
    __half* __restrict__ out, int K)
{
    long long row = blockIdx.x;
    const float* ip = in + row * ldin;
    float scale = rms_scale(ip, K, threadIdx.x);
    for (int i = threadIdx.x; i < K; i += 256)
        out[row * (long long)K + i] = __float2half_rn(ip[i] * scale * w[i]);
}

// ------------------- RoPE + head packing (qf/kf pairs, vT single) -----------
__global__ __launch_bounds__(256) void rope_pack_h_k(
    const float* __restrict__ q, const float* __restrict__ kv,
    const float* __restrict__ qkva,
    const float* __restrict__ fcos, const float* __restrict__ fsin,
    __half* __restrict__ qfH, __half* __restrict__ qfL,
    __half* __restrict__ kfH, __half* __restrict__ kfL,
    __half* __restrict__ vT)
{
    int t = blockIdx.x, b = blockIdx.y;
    long long m = (long long)b * CT + t;
    __shared__ float kpe[CROPE], cs[32], sn[32];
    int tid = threadIdx.x;
    if (tid < 32) { cs[tid] = fcos[t*32 + tid]; sn[tid] = fsin[t*32 + tid]; }
    __syncthreads();
    if (tid < 32) {
        float x0 = qkva[m*NQKVA + 2048 + 2*tid];
        float x1 = qkva[m*NQKVA + 2048 + 2*tid + 1];
        kpe[2*tid]   = x0*cs[tid] - x1*sn[tid];
        kpe[2*tid+1] = x0*sn[tid] + x1*cs[tid];
    }
    __syncthreads();
    for (int idx = tid; idx < CH*CQKD; idx += 256) {
        int h = idx / CQKD, d = idx % CQKD;
        long long o = (((long long)b*CH + h)*CT + t)*CQKD + d;
        float qv, kvv;
        if (d < CNOPE) {
            qv  = q [m*(CH*CQKD) + h*CQKD + d];
            kvv = kv[m*(CH*256)  + h*256  + d];
        } else {
            int j = d - CNOPE, i2 = j >> 1;
            float x0 = q[m*(CH*CQKD) + h*CQKD + CNOPE + 2*i2];
            float x1 = q[m*(CH*CQKD) + h*CQKD + CNOPE + 2*i2 + 1];
            qv  = (j & 1) ? (x0*sn[i2] + x1*cs[i2]) : (x0*cs[i2] - x1*sn[i2]);
            kvv = kpe[j];
        }
        __half hh, ll;
        split1h(qv, hh, ll);  qfH[o] = hh; qfL[o] = ll;
        split1h(kvv, hh, ll); kfH[o] = hh; kfL[o] = ll;
    }
    for (int idx = tid; idx < CH*CVHD; idx += 256) {
        int h = idx >> 7, d = idx & 127;
        vT[(((long long)b*CH + h)*CVHD + d)*CT + t] =
            __float2half_rn(kv[m*(CH*256) + h*256 + CNOPE + d]);
    }
}

// ------------------- causal softmax (fp16 out, skip masked reads) -----------
__global__ __launch_bounds__(256) void softmax_causal_h_k(
    const float* __restrict__ s, __half* __restrict__ at)
{
    long long row = blockIdx.x;
    int sIdx = (int)(row & (CT - 1));
    const float4* p = (const float4*)(s + row * (long long)CT);
    int tid = threadIdx.x, warp = tid >> 5, lane = tid & 31;
    __shared__ float red[32];

    bool act = (4 * tid <= sIdx);
    float4 v = act ? p[tid] : make_float4(-1e30f, -1e30f, -1e30f, -1e30f);
    float mx = fmaxf(fmaxf(v.x, v.y), fmaxf(v.z, v.w));
    #pragma unroll
    for (int o = 16; o > 0; o >>= 1) mx = fmaxf(mx, __shfl_xor_sync(0xffffffffu, mx, o));
    if (lane == 0) red[warp] = mx;
    __syncthreads();
    if (warp == 0) {
        float m2 = (lane < 8) ? red[lane] : -1e30f;
        #pragma unroll
        for (int o = 4; o > 0; o >>= 1) m2 = fmaxf(m2, __shfl_xor_sync(0xffffffffu, m2, o));
        if (lane == 0) red[0] = m2;
    }
    __syncthreads();
    mx = red[0];
    __syncthreads();

    float sum = 0.f;
    if (act) {
        v.x = __expf(v.x - mx); v.y = __expf(v.y - mx);
        v.z = __expf(v.z - mx); v.w = __expf(v.w - mx);
        sum = v.x + v.y + v.z + v.w;
    }
    #pragma unroll
    for (int o = 16; o > 0; o >>= 1) sum += __shfl_xor_sync(0xffffffffu, sum, o);
    if (lane == 0) red[warp] = sum;
    __syncthreads();
    if (warp == 0) {
        float s2 = (lane < 8) ? red[lane] : 0.f;
        #pragma unroll
        for (int o = 4; o > 0; o >>= 1) s2 += __shfl_xor_sync(0xffffffffu, s2, o);
        if (lane == 0) red[0] = s2;
    }
    __syncthreads();
    float inv = 1.f / red[0];
    __half2* H = (__half2*)(at + row * (long long)CT);
    if (act) {
        H[2*tid]   = __floats2half2_rn(v.x * inv, v.y * inv);
        H[2*tid+1] = __floats2half2_rn(v.z * inv, v.w * inv);
    } else {
        H[2*tid]   = __halves2half2(__float2half_rn(0.f), __float2half_rn(0.f));
        H[2*tid+1] = H[2*tid];
    }
}

// ======================= templated fp16 HMMA GEMM (512 thr) =================
// TERMS=3: C = alpha*(Ah@Bh + Ah@Bl + Al@Bh) [+R]  (BN=128 only)
// TERMS=1: C = alpha*Ah@Bh [+R]
// HOUT: 0=float(+R), 1=half, 2=gu-fused (silu(even col)*odd col -> half)
// C offset per z: (z/zdiv)*sC + (z%zdiv)*sC2
// causal: 1 = skip when bn > bm+127;  2 = truncate K at bm+128.
template<int TERMS, int BN>
__device__ __forceinline__ void issue_h(
    uint32_t sbase, const __half* Ah, const __half* Al,
    const __half* Bh, const __half* Bl,
    int lda, int ldb, int bm, int bn, int M, int N, int k0, int tid)
{
    constexpr int OPS = (TERMS == 3) ? 2 : 1;
    constexpr int ABYTES = 16384 * OPS;
    constexpr int NBT = BN / 128;
    #pragma unroll
    for (int it = 0; it < 2; it++) {
        int e = it * 512 + tid;
        int r = e >> 3, g = e & 7;
        uint32_t so = SW128(r * 128 + g * 16);
        int ra = bm + r; int pa = (ra < M) ? 16 : 0; if (!pa) ra = 0;
        cpa16(sbase + so, Ah + (size_t)ra * lda + k0 + g * 8, pa);
        if constexpr (TERMS == 3)
            cpa16(sbase + 16384 + so, Al + (size_t)ra * lda + k0 + g * 8, pa);
    }
    #pragma unroll
    for (int it = 0; it < 2 * NBT; it++) {
        int e = it * 512 + tid;
        int r = e >> 3, g = e & 7;
        uint32_t so = SW128(r * 128 + g * 16);
        int rb = bn + r; int pb = (rb < N) ? 16 : 0; if (!pb) rb = 0;
        cpa16(sbase + ABYTES + so, Bh + (size_t)rb * ldb + k0 + g * 8, pb);
        if constexpr (TERMS == 3)
            cpa16(sbase + ABYTES + NBT * 16384 + so, Bl + (size_t)rb * ldb + k0 + g * 8, pb);
    }
    cp_commit();
}

template<int TERMS, int BN, int HOUT>
__global__ __launch_bounds__(512, 1) void gemm_h(
    const __half* __restrict__ Ah, const __half* __restrict__ Al,
    int lda, long long sA,
    const __half* __restrict__ Bh, const __half* __restrict__ Bl,
    int ldb, long long sB,
    void* __restrict__ Cv, int ldc, long long sC, int zdiv, long long sC2,
    const float* __restrict__ R, int ldr, long long sR,
    int M, int N, int K, float alpha, int causal)
{
    constexpr int OPS = (TERMS == 3) ? 2 : 1;
    constexpr int ABYTES = 16384 * OPS;
    constexpr int NBT = BN / 128;
    constexpr int STAGE = ABYTES + NBT * 16384 * OPS;
    constexpr int NST = (TERMS == 1) ? 4 : 3;
    constexpr int NG4 = BN / 64;    // 16-col B groups per warp
    constexpr int NS  = BN / 32;    // 8-col accum groups per warp

    extern __shared__ __align__(1024) char smem[];
    const uint32_t sb0 = smem_u32(smem);
    const int tid = threadIdx.x;
    const int wid = tid >> 5, lane = tid & 31;
    long long z = blockIdx.z;
    Ah += z * sA;
    if constexpr (TERMS == 3) Al += z * sA;
    Bh += z * sB;
    if constexpr (TERMS == 3) Bl += z * sB;
    if (R) R += z * sR;
    const long long zo = (z / zdiv) * sC + (z % zdiv) * sC2;
    const int bm = blockIdx.y * 128, bn = blockIdx.x * BN;
    // 16 warps: 4 (M) x 4 (N); warp tile 32 x (BN/4)
    const int wm = (wid >> 2) * 32, wn = (wid & 3) * (BN / 4);

    if (causal == 1 && bn > bm + 127) return;

    float acc[2][NS][4];
    #pragma unroll
    for (int i = 0; i < 2; i++)
        #pragma unroll
        for (int j = 0; j < NS; j++)
            #pragma unroll
            for (int r = 0; r < 4; r++) acc[i][j][r] = 0.f;

    int nc = K >> 6;
    if (causal == 2) { int lim = (bm + 191) >> 6; if (lim < nc) nc = lim; }

    #pragma unroll
    for (int s = 0; s < NST - 1; s++) {
        if (s < nc)
            issue_h<TERMS, BN>(sb0 + s * STAGE, Ah, Al, Bh, Bl, lda, ldb, bm, bn, M, N, s << 6, tid);
        else
            cp_commit();
    }

    const int arow = wm + (lane & 15);
    const int acb  = (lane >> 4) << 4;
    const int brow4 = wn + ((lane >> 4) << 3) + (lane & 7);
    const int bcb4  = ((lane >> 3) & 1) << 4;

    uint32_t ahf[2][4], alf[2][4];
    uint32_t bhf[NG4][4], blf[NG4][4];
    (void)alf; (void)blf;

    for (int c = 0; c < nc; c++) {
        cp_wait<NST - 2>();
        __syncthreads();
        {
            int nx = c + NST - 1;
            if (nx < nc)
                issue_h<TERMS, BN>(sb0 + (nx % NST) * STAGE, Ah, Al, Bh, Bl,
                                   lda, ldb, bm, bn, M, N, nx << 6, tid);
            else
                cp_commit();
        }

        uint32_t tA  = sb0 + (c % NST) * STAGE;
        uint32_t tAl = tA + 16384;
        uint32_t tB  = tA + ABYTES;
        uint32_t tBl = tB + NBT * 16384;

        #pragma unroll
        for (int ks = 0; ks < 4; ks++) {
            // batched fragment loads (back-to-back LDSM)
            #pragma unroll
            for (int ms = 0; ms < 2; ms++) {
                uint32_t off = SW128((arow + ms * 16) * 128 + ks * 32 + acb);
                ldsm_x4(ahf[ms], tA + off);
                if constexpr (TERMS == 3) ldsm_x4(alf[ms], tAl + off);
            }
            #pragma unroll
            for (int ng4 = 0; ng4 < NG4; ng4++) {
                uint32_t off = SW128((brow4 + ng4 * 16) * 128 + ks * 32 + bcb4);
                ldsm_x4(bhf[ng4], tB + off);
                if constexpr (TERMS == 3) ldsm_x4(blf[ng4], tBl + off);
            }
            // back-to-back MMAs
            #pragma unroll
            for (int ng4 = 0; ng4 < NG4; ng4++)
                #pragma unroll
                for (int ms = 0; ms < 2; ms++) {
                    mma_f16(acc[ms][2*ng4],   ahf[ms], bhf[ng4]);
                    mma_f16(acc[ms][2*ng4+1], ahf[ms], bhf[ng4] + 2);
                    if constexpr (TERMS == 3) {
                        mma_f16(acc[ms][2*ng4],   ahf[ms], blf[ng4]);
                        mma_f16(acc[ms][2*ng4+1], ahf[ms], blf[ng4] + 2);
                        mma_f16(acc[ms][2*ng4],   alf[ms], bhf[ng4]);
                        mma_f16(acc[ms][2*ng4+1], alf[ms], bhf[ng4] + 2);
                    }
                }
        }
    }

    const int gid = lane >> 2, tc = lane & 3;
    if constexpr (HOUT == 2) {
        __half* C = (__half*)Cv + zo;
        #pragma unroll
        for (int ms = 0; ms < 2; ms++)
            #pragma unroll
            for (int ns = 0; ns < NS; ns++) {
                int gr0 = bm + wm + ms * 16 + gid;
                int gc  = bn + wn + ns * 8 + tc * 2;
                float g0 = acc[ms][ns][0], u0 = acc[ms][ns][1];
                float g1 = acc[ms][ns][2], u1 = acc[ms][ns][3];
                float r0 = g0 / (1.f + __expf(-g0)) * u0;
                float r1 = g1 / (1.f + __expf(-g1)) * u1;
                C[(size_t)gr0 * ldc + (gc >> 1)]       = __float2half_rn(r0);
                C[(size_t)(gr0 + 8) * ldc + (gc >> 1)] = __float2half_rn(r1);
            }
    } else if constexpr (HOUT == 1) {
        __half* C = (__half*)Cv + zo;
        #pragma unroll
        for (int ms = 0; ms < 2; ms++)
            #pragma unroll
            for (int ns = 0; ns < NS; ns++) {
                int gr0 = bm + wm + ms * 16 + gid;
                int gc  = bn + wn + ns * 8 + tc * 2;
                if (gc < N) {
                    *(__half2*)&C[(size_t)gr0 * ldc + gc] =
                        __floats2half2_rn(alpha * acc[ms][ns][0], alpha * acc[ms][ns][1]);
                    *(__half2*)&C[(size_t)(gr0 + 8) * ldc + gc] =
                        __floats2half2_rn(alpha * acc[ms][ns][2], alpha * acc[ms][ns][3]);
                }
            }
    } else {
        float* C = (float*)Cv + zo;
        #pragma unroll
        for (int ms = 0; ms < 2; ms++)
            #pragma unroll
            for (int ns = 0; ns < NS; ns++) {
                int gr0 = bm + wm + ms * 16 + gid;
                int gc  = bn + wn + ns * 8 + tc * 2;
                if (gc < N) {
                    float2 v0;
                    v0.x = alpha * acc[ms][ns][0];
                    v0.y = alpha * acc[ms][ns][1];
                    if (R) { v0.x += R[(size_t)gr0 * ldr + gc]; v0.y += R[(size_t)gr0 * ldr + gc + 1]; }
                    *(float2*)&C[(size_t)gr0 * ldc + gc] = v0;
                    int gr1 = gr0 + 8;
                    float2 v1;
                    v1.x = alpha * acc[ms][ns][2];
                    v1.y = alpha * acc[ms][ns][3];
                    if (R) { v1.x += R[(size_t)gr1 * ldr + gc]; v1.y += R[(size_t)gr1 * ldr + gc + 1]; }
                    *(float2*)&C[(size_t)gr1 * ldc + gc] = v1;
                }
            }
    }
}

#define SM_3_128 (3*(32768+32768))   // 192KB, NST=3
#define SM_1_256 (4*(16384+32768))   // 192KB, NST=4
#define SM_1_128 (4*(16384+16384))   // 128KB, NST=4

// ------------------------------ host launch ---------------------------------
static void gemm3(const __half* Ah, const __half* Al, int lda, long long sA,
                  const __half* Bh, const __half* Bl, int ldb, long long sB,
                  float* C, int ldc, long long sC,
                  const float* R, int ldr, long long sR,
                  int M, int N, int K, float alpha, int Z, int causal = 0)
{
    dim3 grid((N + 127) / 128, M / 128, Z);
    gemm_h<3,128,0><<<grid, 512, SM_3_128>>>(Ah, Al, lda, sA, Bh, Bl, ldb, sB,
                                             C, ldc, sC, 1, 0, R, ldr, sR, M, N, K, alpha, causal);
}
static void gemm1f(const __half* A, int lda, long long sA,
                   const __half* B, int ldb, long long sB,
                   float* C, int ldc, long long sC,
                   const float* R, int ldr, long long sR,
                   int M, int N, int K, float alpha, int Z, int causal = 0)
{
    if (N % 256 == 0) {
        dim3 grid(N / 256, M / 128, Z);
        gemm_h<1,256,0><<<grid, 512, SM_1_256>>>(A, nullptr, lda, sA, B, nullptr, ldb, sB,
                                                 C, ldc, sC, 1, 0, R, ldr, sR, M, N, K, alpha, causal);
    } else {
        dim3 grid((N + 127) / 128, M / 128, Z);
        gemm_h<1,128,0><<<grid, 512, SM_1_128>>>(A, nullptr, lda, sA, B, nullptr, ldb, sB,
                                                 C, ldc, sC, 1, 0, R, ldr, sR, M, N, K, alpha, causal);
    }
}

static void splitp(const float* in, __half* hi, __half* lo, long long n)
{
    long long n4 = n >> 2;
    split_h_k<<<(unsigned)((n4 + 255) / 256), 256>>>(
        (const float4*)in, (__half2*)hi, (__half2*)lo, n4);
}

extern "C" void kernel_launch(void* const* d_in, const int* in_sizes, int n_in,
                              void* d_out, int out_size)
{
    const float* x     = (const float*)d_in[0];
    const float* mask  = (const float*)d_in[1];
    const float* fcos  = (const float*)d_in[2];
    const float* fsin  = (const float*)d_in[3];
    const float* anw   = (const float*)d_in[4];
    const float* wq_a  = (const float*)d_in[5];
    const float* qnw   = (const float*)d_in[6];
    const float* wq_b  = (const float*)d_in[7];
    const float* wkv_a = (const float*)d_in[8];
    const float* kvnw  = (const float*)d_in[9];
    const float* wkv_b = (const float*)d_in[10];
    const float* wo    = (const float*)d_in[11];
    const float* fnw   = (const float*)d_in[12];
    const float* w1    = (const float*)d_in[13];
    const float* w2    = (const float*)d_in[14];
    const float* w3    = (const float*)d_in[15];
    float* out = (float*)d_out;

    cudaFuncSetAttribute(gemm_h<3,128,0>, cudaFuncAttributeMaxDynamicSharedMemorySize, SM_3_128);
    cudaFuncSetAttribute(gemm_h<1,256,0>, cudaFuncAttributeMaxDynamicSharedMemorySize, SM_1_256);
    cudaFuncSetAttribute(gemm_h<1,128,0>, cudaFuncAttributeMaxDynamicSharedMemorySize, SM_1_128);
    cudaFuncSetAttribute(gemm_h<1,128,1>, cudaFuncAttributeMaxDynamicSharedMemorySize, SM_1_128);
    cudaFuncSetAttribute(gemm_h<1,256,2>, cudaFuncAttributeMaxDynamicSharedMemorySize, SM_1_256);

    float *p_qkva, *p_q, *p_kv, *p_sc, *p_x2;
    cudaGetSymbolAddress((void**)&p_qkva, g_qkva);
    cudaGetSymbolAddress((void**)&p_q,    g_q);
    cudaGetSymbolAddress((void**)&p_kv,   g_kv);
    cudaGetSymbolAddress((void**)&p_sc,   g_sc);
    cudaGetSymbolAddress((void**)&p_x2,   g_x2);

    __half *hH,*hL,*qaH,*qaL,*kvnH,*kvnL,*qfH,*qfL,*kfH,*kfL,*vT,*at,*y2,*h2,*gs,
           *wqkaH,*wqkaL,*wqbH,*wqbL,*wkbH,*wkbL,*woh,*w13h,*w2h;
    cudaGetSymbolAddress((void**)&hH,   f_hH);  cudaGetSymbolAddress((void**)&hL,   f_hL);
    cudaGetSymbolAddress((void**)&qaH,  f_qaH); cudaGetSymbolAddress((void**)&qaL,  f_qaL);
    cudaGetSymbolAddress((void**)&kvnH, f_kvnH);cudaGetSymbolAddress((void**)&kvnL, f_kvnL);
    cudaGetSymbolAddress((void**)&qfH,  f_qfH); cudaGetSymbolAddress((void**)&qfL,  f_qfL);
    cudaGetSymbolAddress((void**)&kfH,  f_kfH); cudaGetSymbolAddress((void**)&kfL,  f_kfL);
    cudaGetSymbolAddress((void**)&vT,   f_vT);  cudaGetSymbolAddress((void**)&at,   f_at);
    cudaGetSymbolAddress((void**)&y2,   f_y2);
    cudaGetSymbolAddress((void**)&h2,   f_h2);  cudaGetSymbolAddress((void**)&gs,   f_gs);
    cudaGetSymbolAddress((void**)&wqkaH,f_wqkaH);cudaGetSymbolAddress((void**)&wqkaL,f_wqkaL);
    cudaGetSymbolAddress((void**)&wqbH, f_wqbH);cudaGetSymbolAddress((void**)&wqbL, f_wqbL);
    cudaGetSymbolAddress((void**)&wkbH, f_wkbH);cudaGetSymbolAddress((void**)&wkbL, f_wkbL);
    cudaGetSymbolAddress((void**)&woh,  f_wo);
    cudaGetSymbolAddress((void**)&w13h, f_w13); cudaGetSymbolAddress((void**)&w2h,  f_w2);

    // weight conversions (independent; issue early)
    {
        long long n4big = ((long long)CINTER * CD) >> 2;
        long long n4wo  = ((long long)CD * CD) >> 2;
        dim3 grid((unsigned)((n4big + 255) / 256), 4);
        conv4_h_k<<<grid, 256>>>((const float4*)w1, (const float4*)w3,
                                 (const float4*)w2, (const float4*)wo,
                                 (__half2*)w13h, (__half2*)w2h, (__half2*)woh,
                                 n4big, n4wo);
    }

    // ---- attention path ----
    rmsnorm_split_h_k<<<CM, 256>>>(x, CD, anw, hH, hL, CD);
    splitp(wq_a,  wqkaH, wqkaL, (long long)CQLORA*CD);
    splitp(wkv_a, wqkaH + (long long)CQLORA*CD, wqkaL + (long long)CQLORA*CD,
           (long long)(CKVLORA+CROPE)*CD);
    // qkva = h @ [wq_a; wkv_a]^T
    gemm3(hH, hL, CD, 0, wqkaH, wqkaL, CD, 0, p_qkva, NQKVA, 0,
          nullptr, 0, 0, CM, NQKVA, CD, 1.f, 1);
    rmsnorm_split_h_k<<<CM, 256>>>(p_qkva, NQKVA, qnw, qaH, qaL, CQLORA);
    splitp(wq_b, wqbH, wqbL, (long long)CH*CQKD*CQLORA);
    // q = qa_norm @ wq_b^T
    gemm3(qaH, qaL, CQLORA, 0, wqbH, wqbL, CQLORA, 0, p_q, CH*CQKD, 0,
          nullptr, 0, 0, CM, CH*CQKD, CQLORA, 1.f, 1);
    rmsnorm_split_h_k<<<CM, 256>>>(p_qkva + CQLORA, NQKVA, kvnw, kvnH, kvnL, CKVLORA);
    splitp(wkv_b, wkbH, wkbL, (long long)CH*256*CKVLORA);
    // kv = kv_norm @ wkv_b^T
    gemm3(kvnH, kvnL, CKVLORA, 0, wkbH, wkbL, CKVLORA, 0, p_kv, CH*256, 0,
          nullptr, 0, 0, CM, CH*256, CKVLORA, 1.f, 1);
    rope_pack_h_k<<<dim3(CT, CB), 256>>>(p_q, p_kv, p_qkva, fcos, fsin,
                                         qfH, qfL, kfH, kfL, vT);
    // scores = -96 * qf @ kf^T + mask (masked tiles skipped; softmax fills zeros)
    gemm3(qfH, qfL, CQKD, (long long)CT*CQKD,
          kfH, kfL, CQKD, (long long)CT*CQKD,
          p_sc, CT, (long long)CT*CT,
          mask, CT, 0, CT, CT, CQKD, -96.f, CB*CH, 1);
    softmax_causal_h_k<<<CB*CH*CT, 256>>>(p_sc, at);
    // y2 = attn @ vT with fused [B,H,T,d] -> [B*T, H*d] permute in epilogue
    {
        dim3 grid(1, CT / 128, CB*CH);
        gemm_h<1,128,1><<<grid, 512, SM_1_128>>>(
            at, nullptr, CT, (long long)CT*CT,
            vT, nullptr, CT, (long long)CVHD*CT,
            y2, CD, (long long)CT*CD, CH, (long long)CVHD,
            nullptr, 0, 0, CT, CVHD, CT, 1.f, 2);
    }
    // x2 = x + y2 @ wo^T
    gemm1f(y2, CH*CVHD, 0, woh, CH*CVHD, 0, p_x2, CD, 0,
           x, CD, 0, CM, CD, CH*CVHD, 1.f, 1);

    // ---- FFN path ----
    rmsnorm_h_k<<<CM, 256>>>(p_x2, CD, fnw, h2, CD);
    // gs = silu(h2@w1^T) * (h2@w3^T) in ONE GEMM (w13 interleaved, fused epilogue)
    {
        dim3 grid((2*CINTER) / 256, CM / 128, 1);
        gemm_h<1,256,2><<<grid, 512, SM_1_256>>>(
            h2, nullptr, CD, 0,
            w13h, nullptr, CD, 0,
            gs, CINTER, 0, 1, 0,
            nullptr, 0, 0, CM, 2*CINTER, CD, 1.f, 0);
    }
    // out = x2 + gs @ w2^T
    gemm1f(gs, CINTER, 0, w2h, CINTER, 0, out, CD, 0,
           p_x2, CD, 0, CM, CD, CINTER, 1.f, 1);
}

// round 11
// speedup vs baseline: 5.9030x; 1.0190x over previous
#include <cuda_runtime.h>
#include <cuda_fp16.h>
#include <cstdint>

// ---------------------------------------------------------------------------
// DeepSeek MLA block on GB300 — mma.sync fp16 GEMMs, v9.
// q/k path: fp16-pair 3-term split. Additive paths: 1-term fp16.
// v9 = v8 + dual-stream overlap: all weight conversions run on a forked
//      stream (capture-legal event fork/join) under the DRAM-idle GEMMs.
// ---------------------------------------------------------------------------

#define CB 2
#define CT 1024
#define CD 2048
#define CH 16
#define CNOPE 128
#define CROPE 64
#define CQKD 192
#define CQLORA 1536
#define CKVLORA 512
#define CVHD 128
#define CINTER 8192
#define CM (CB*CT)
#define NQKVA (CQLORA + CKVLORA + CROPE)   // 2112

// ------------------------------- PTX helpers -------------------------------
__device__ __forceinline__ uint32_t smem_u32(const void* p) {
    uint32_t a;
    asm("{ .reg .u64 t; cvta.to.shared.u64 t, %1; cvt.u32.u64 %0, t; }" : "=r"(a) : "l"(p));
    return a;
}
#define SW128(o) ((o) ^ (((o) >> 3) & 0x70))

__device__ __forceinline__ void cpa16(uint32_t s, const void* g, int sz) {
    asm volatile("cp.async.cg.shared.global [%0], [%1], 16, %2;"
                 :: "r"(s), "l"(g), "r"(sz));
}
__device__ __forceinline__ void cp_commit() {
    asm volatile("cp.async.commit_group;" ::: "memory");
}
template <int N> __device__ __forceinline__ void cp_wait() {
    asm volatile("cp.async.wait_group %0;" :: "n"(N) : "memory");
}
__device__ __forceinline__ void ldsm_x4(uint32_t* r, uint32_t a) {
    asm volatile("ldmatrix.sync.aligned.m8n8.x4.shared.b16 {%0,%1,%2,%3}, [%4];"
        : "=r"(r[0]), "=r"(r[1]), "=r"(r[2]), "=r"(r[3]) : "r"(a));
}
__device__ __forceinline__ void mma_f16(float* d, const uint32_t* a, const uint32_t* b) {
    asm volatile(
        "mma.sync.aligned.m16n8k16.row.col.f32.f16.f16.f32 "
        "{%0,%1,%2,%3}, {%4,%5,%6,%7}, {%8,%9}, {%0,%1,%2,%3};"
        : "+f"(d[0]), "+f"(d[1]), "+f"(d[2]), "+f"(d[3])
        : "r"(a[0]), "r"(a[1]), "r"(a[2]), "r"(a[3]), "r"(b[0]), "r"(b[1]));
}

// ------------------------- scratch (device globals) ------------------------
__device__ float g_qkva[(long long)CM*NQKVA];
__device__ float g_q   [(long long)CM*CH*CQKD];
__device__ float g_kv  [(long long)CM*CH*(CNOPE+CVHD)];
__device__ float g_sc  [(long long)CB*CH*CT*CT];
__device__ float g_x2  [(long long)CM*CD];

// fp16 operand buffers
__device__ __half f_hH [(long long)CM*CD],        f_hL [(long long)CM*CD];
__device__ __half f_qaH[(long long)CM*CQLORA],    f_qaL[(long long)CM*CQLORA];
__device__ __half f_kvnH[(long long)CM*CKVLORA],  f_kvnL[(long long)CM*CKVLORA];
__device__ __half f_qfH[(long long)CB*CH*CT*CQKD], f_qfL[(long long)CB*CH*CT*CQKD];
__device__ __half f_kfH[(long long)CB*CH*CT*CQKD], f_kfL[(long long)CB*CH*CT*CQKD];
__device__ __half f_vT [(long long)CB*CH*CVHD*CT];
__device__ __half f_at [(long long)CB*CH*CT*CT];
__device__ __half f_y2 [(long long)CM*CD];
__device__ __half f_h2 [(long long)CM*CD];
__device__ __half f_gs [(long long)CM*CINTER];
// weights
__device__ __half f_wqkaH[(long long)NQKVA*CD],   f_wqkaL[(long long)NQKVA*CD];
__device__ __half f_wqbH[(long long)CH*CQKD*CQLORA], f_wqbL[(long long)CH*CQKD*CQLORA];
__device__ __half f_wkbH[(long long)CH*256*CKVLORA], f_wkbL[(long long)CH*256*CKVLORA];
__device__ __half f_wo [(long long)CD*CD];
__device__ __half f_w13[(long long)2*CINTER*CD];   // interleaved: row 2j=w1_j, 2j+1=w3_j
__device__ __half f_w2 [(long long)CD*CINTER];

// ------------------------------- split helpers -----------------------------
__device__ __forceinline__ void split1h(float v, __half& h, __half& l) {
    h = __float2half_rn(v);
    l = __float2half_rn(v - __half2float(h));
}

__global__ __launch_bounds__(256) void split_h_k(
    const float4* __restrict__ in, __half2* __restrict__ hi,
    __half2* __restrict__ lo, long long n4)
{
    long long i = (long long)blockIdx.x * 256 + threadIdx.x;
    if (i >= n4) return;
    float4 v = in[i];
    __half h0,h1,h2,h3,l0,l1,l2,l3;
    split1h(v.x,h0,l0); split1h(v.y,h1,l1); split1h(v.z,h2,l2); split1h(v.w,h3,l3);
    hi[2*i]   = __halves2half2(h0,h1);
    hi[2*i+1] = __halves2half2(h2,h3);
    lo[2*i]   = __halves2half2(l0,l1);
    lo[2*i+1] = __halves2half2(l2,l3);
}

// convert w1 (interleave even rows), w3 (odd rows), w2 (straight), wo (straight)
__global__ __launch_bounds__(256) void conv4_h_k(
    const float4* __restrict__ w1, const float4* __restrict__ w3,
    const float4* __restrict__ w2, const float4* __restrict__ wo,
    __half2* __restrict__ w13, __half2* __restrict__ w2h, __half2* __restrict__ woh,
    long long n4big, long long n4wo)
{
    long long i = (long long)blockIdx.x * 256 + threadIdx.x;
    int which = blockIdx.y;
    if (which <= 1) {
        if (i >= n4big) return;
        const float4* s = which ? w3 : w1;
        float4 v = s[i];
        long long row = i / (CD/4), off = i % (CD/4);
        long long orow = 2*row + which;
        __half2* d = w13 + orow * (CD/2) + off*2;
        d[0] = __floats2half2_rn(v.x, v.y);
        d[1] = __floats2half2_rn(v.z, v.w);
    } else if (which == 2) {
        if (i >= n4big) return;
        float4 v = w2[i];
        w2h[2*i]   = __floats2half2_rn(v.x, v.y);
        w2h[2*i+1] = __floats2half2_rn(v.z, v.w);
    } else {
        if (i >= n4wo) return;
        float4 v = wo[i];
        woh[2*i]   = __floats2half2_rn(v.x, v.y);
        woh[2*i+1] = __floats2half2_rn(v.z, v.w);
    }
}

// ------------------------------ RMSNorm variants ----------------------------
__device__ __forceinline__ float rms_scale(const float* ip, int K, int tid) {
    float s = 0.f;
    for (int i = tid; i < K; i += 256) { float v = ip[i]; s += v * v; }
    __shared__ float red[32];
    #pragma unroll
    for (int o = 16; o > 0; o >>= 1) s += __shfl_xor_sync(0xffffffffu, s, o);
    int warp = tid >> 5, lane = tid & 31;
    if (lane == 0) red[warp] = s;
    __syncthreads();
    if (warp == 0) {
        float s2 = (lane < 8) ? red[lane] : 0.f;
        #pragma unroll
        for (int o = 4; o > 0; o >>= 1) s2 += __shfl_xor_sync(0xffffffffu, s2, o);
        if (lane == 0) red[0] = s2;
    }
    __syncthreads();
    return rsqrtf(red[0] / (float)K + 1e-6f);
}

__global__ __launch_bounds__(256) void rmsnorm_split_h_k(
    const float* __restrict__ in, int ldin, const float* __restrict__ w,
    __half* __restrict__ hi, __half* __restrict__ lo, int K)
{
    long long row = blockIdx.x;
    const float* ip = in + row * ldin;
    float scale = rms_scale(ip, K, threadIdx.x);
    for (int i = threadIdx.x; i < K; i += 256) {
        float v = ip[i] * scale * w[i];
        __half h, l; split1h(v, h, l);
        hi[row * (long long)K + i] = h;
        lo[row * (long long)K + i] = l;
    }
}

__global__ __launch_bounds__(256) void rmsnorm_h_k(
    const float* __restrict__ in, int ldin, const float* __restrict__ w,
    __half* __restrict__ out, int K)
{
    long long row = blockIdx.x;
    const float* ip = in + row * ldin;
    float scale = rms_scale(ip, K, threadIdx.x);
    for (int i = threadIdx.x; i < K; i += 256)
        out[row * (long long)K + i] = __float2half_rn(ip[i] * scale * w[i]);
}

// ------------------- RoPE + head packing (qf/kf pairs, vT single) -----------
__global__ __launch_bounds__(256) void rope_pack_h_k(
    const float* __restrict__ q, const float* __restrict__ kv,
    const float* __restrict__ qkva,
    const float* __restrict__ fcos, const float* __restrict__ fsin,
    __half* __restrict__ qfH, __half* __restrict__ qfL,
    __half* __restrict__ kfH, __half* __restrict__ kfL,
    __half* __restrict__ vT)
{
    int t = blockIdx.x, b = blockIdx.y;
    long long m = (long long)b * CT + t;
    __shared__ float kpe[CROPE], cs[32], sn[32];
    int tid = threadIdx.x;
    if (tid < 32) { cs[tid] = fcos[t*32 + tid]; sn[tid] = fsin[t*32 + tid]; }
    __syncthreads();
    if (tid < 32) {
        float x0 = qkva[m*NQKVA + 2048 + 2*tid];
        float x1 = qkva[m*NQKVA + 2048 + 2*tid + 1];
        kpe[2*tid]   = x0*cs[tid] - x1*sn[tid];
        kpe[2*tid+1] = x0*sn[tid] + x1*cs[tid];
    }
    __syncthreads();
    for (int idx = tid; idx < CH*CQKD; idx += 256) {
        int h = idx / CQKD, d = idx % CQKD;
        long long o = (((long long)b*CH + h)*CT + t)*CQKD + d;
        float qv, kvv;
        if (d < CNOPE) {
            qv  = q [m*(CH*CQKD) + h*CQKD + d];
            kvv = kv[m*(CH*256)  + h*256  + d];
        } else {
            int j = d - CNOPE, i2 = j >> 1;
            float x0 = q[m*(CH*CQKD) + h*CQKD + CNOPE + 2*i2];
            float x1 = q[m*(CH*CQKD) + h*CQKD + CNOPE + 2*i2 + 1];
            qv  = (j & 1) ? (x0*sn[i2] + x1*cs[i2]) : (x0*cs[i2] - x1*sn[i2]);
            kvv = kpe[j];
        }
        __half hh, ll;
        split1h(qv, hh, ll);  qfH[o] = hh; qfL[o] = ll;
        split1h(kvv, hh, ll); kfH[o] = hh; kfL[o] = ll;
    }
    for (int idx = tid; idx < CH*CVHD; idx += 256) {
        int h = idx >> 7, d = idx & 127;
        vT[(((long long)b*CH + h)*CVHD + d)*CT + t] =
            __float2half_rn(kv[m*(CH*256) + h*256 + CNOPE + d]);
    }
}

// ------------------- causal softmax (fp16 out, skip masked reads) -----------
__global__ __launch_bounds__(256) void softmax_causal_h_k(
    const float* __restrict__ s, __half* __restrict__ at)
{
    long long row = blockIdx.x;
    int sIdx = (int)(row & (CT - 1));
    const float4* p = (const float4*)(s + row * (long long)CT);
    int tid = threadIdx.x, warp = tid >> 5, lane = tid & 31;
    __shared__ float red[32];

    bool act = (4 * tid <= sIdx);
    float4 v = act ? p[tid] : make_float4(-1e30f, -1e30f, -1e30f, -1e30f);
    float mx = fmaxf(fmaxf(v.x, v.y), fmaxf(v.z, v.w));
    #pragma unroll
    for (int o = 16; o > 0; o >>= 1) mx = fmaxf(mx, __shfl_xor_sync(0xffffffffu, mx, o));
    if (lane == 0) red[warp] = mx;
    __syncthreads();
    if (warp == 0) {
        float m2 = (lane < 8) ? red[lane] : -1e30f;
        #pragma unroll
        for (int o = 4; o > 0; o >>= 1) m2 = fmaxf(m2, __shfl_xor_sync(0xffffffffu, m2, o));
        if (lane == 0) red[0] = m2;
    }
    __syncthreads();
    mx = red[0];
    __syncthreads();

    float sum = 0.f;
    if (act) {
        v.x = __expf(v.x - mx); v.y = __expf(v.y - mx);
        v.z = __expf(v.z - mx); v.w = __expf(v.w - mx);
        sum = v.x + v.y + v.z + v.w;
    }
    #pragma unroll
    for (int o = 16; o > 0; o >>= 1) sum += __shfl_xor_sync(0xffffffffu, sum, o);
    if (lane == 0) red[warp] = sum;
    __syncthreads();
    if (warp == 0) {
        float s2 = (lane < 8) ? red[lane] : 0.f;
        #pragma unroll
        for (int o = 4; o > 0; o >>= 1) s2 += __shfl_xor_sync(0xffffffffu, s2, o);
        if (lane == 0) red[0] = s2;
    }
    __syncthreads();
    float inv = 1.f / red[0];
    __half2* H = (__half2*)(at + row * (long long)CT);
    if (act) {
        H[2*tid]   = __floats2half2_rn(v.x * inv, v.y * inv);
        H[2*tid+1] = __floats2half2_rn(v.z * inv, v.w * inv);
    } else {
        H[2*tid]   = __halves2half2(__float2half_rn(0.f), __float2half_rn(0.f));
        H[2*tid+1] = H[2*tid];
    }
}

// ======================= templated fp16 HMMA GEMM (512 thr) =================
template<int TERMS, int BN>
__device__ __forceinline__ void issue_h(
    uint32_t sbase, const __half* Ah, const __half* Al,
    const __half* Bh, const __half* Bl,
    int lda, int ldb, int bm, int bn, int M, int N, int k0, int tid)
{
    constexpr int OPS = (TERMS == 3) ? 2 : 1;
    constexpr int ABYTES = 16384 * OPS;
    constexpr int NBT = BN / 128;
    #pragma unroll
    for (int it = 0; it < 2; it++) {
        int e = it * 512 + tid;
        int r = e >> 3, g = e & 7;
        uint32_t so = SW128(r * 128 + g * 16);
        int ra = bm + r; int pa = (ra < M) ? 16 : 0; if (!pa) ra = 0;
        cpa16(sbase + so, Ah + (size_t)ra * lda + k0 + g * 8, pa);
        if constexpr (TERMS == 3)
            cpa16(sbase + 16384 + so, Al + (size_t)ra * lda + k0 + g * 8, pa);
    }
    #pragma unroll
    for (int it = 0; it < 2 * NBT; it++) {
        int e = it * 512 + tid;
        int r = e >> 3, g = e & 7;
        uint32_t so = SW128(r * 128 + g * 16);
        int rb = bn + r; int pb = (rb < N) ? 16 : 0; if (!pb) rb = 0;
        cpa16(sbase + ABYTES + so, Bh + (size_t)rb * ldb + k0 + g * 8, pb);
        if constexpr (TERMS == 3)
            cpa16(sbase + ABYTES + NBT * 16384 + so, Bl + (size_t)rb * ldb + k0 + g * 8, pb);
    }
    cp_commit();
}

template<int TERMS, int BN, int HOUT>
__global__ __launch_bounds__(512, 1) void gemm_h(
    const __half* __restrict__ Ah, const __half* __restrict__ Al,
    int lda, long long sA,
    const __half* __restrict__ Bh, const __half* __restrict__ Bl,
    int ldb, long long sB,
    void* __restrict__ Cv, int ldc, long long sC, int zdiv, long long sC2,
    const float* __restrict__ R, int ldr, long long sR,
    int M, int N, int K, float alpha, int causal)
{
    constexpr int OPS = (TERMS == 3) ? 2 : 1;
    constexpr int ABYTES = 16384 * OPS;
    constexpr int NBT = BN / 128;
    constexpr int STAGE = ABYTES + NBT * 16384 * OPS;
    constexpr int NST = (TERMS == 1) ? 4 : 3;
    constexpr int NG4 = BN / 64;
    constexpr int NS  = BN / 32;

    extern __shared__ __align__(1024) char smem[];
    const uint32_t sb0 = smem_u32(smem);
    const int tid = threadIdx.x;
    const int wid = tid >> 5, lane = tid & 31;
    long long z = blockIdx.z;
    Ah += z * sA;
    if constexpr (TERMS == 3) Al += z * sA;
    Bh += z * sB;
    if constexpr (TERMS == 3) Bl += z * sB;
    if (R) R += z * sR;
    const long long zo = (z / zdiv) * sC + (z % zdiv) * sC2;
    const int bm = blockIdx.y * 128, bn = blockIdx.x * BN;
    const int wm = (wid >> 2) * 32, wn = (wid & 3) * (BN / 4);

    if (causal == 1 && bn > bm + 127) return;

    float acc[2][NS][4];
    #pragma unroll
    for (int i = 0; i < 2; i++)
        #pragma unroll
        for (int j = 0; j < NS; j++)
            #pragma unroll
            for (int r = 0; r < 4; r++) acc[i][j][r] = 0.f;

    int nc = K >> 6;
    if (causal == 2) { int lim = (bm + 191) >> 6; if (lim < nc) nc = lim; }

    #pragma unroll
    for (int s = 0; s < NST - 1; s++) {
        if (s < nc)
            issue_h<TERMS, BN>(sb0 + s * STAGE, Ah, Al, Bh, Bl, lda, ldb, bm, bn, M, N, s << 6, tid);
        else
            cp_commit();
    }

    const int arow = wm + (lane & 15);
    const int acb  = (lane >> 4) << 4;
    const int brow4 = wn + ((lane >> 4) << 3) + (lane & 7);
    const int bcb4  = ((lane >> 3) & 1) << 4;

    uint32_t ahf[2][4], alf[2][4];
    uint32_t bhf[NG4][4], blf[NG4][4];
    (void)alf; (void)blf;

    for (int c = 0; c < nc; c++) {
        cp_wait<NST - 2>();
        __syncthreads();
        {
            int nx = c + NST - 1;
            if (nx < nc)
                issue_h<TERMS, BN>(sb0 + (nx % NST) * STAGE, Ah, Al, Bh, Bl,
                                   lda, ldb, bm, bn, M, N, nx << 6, tid);
            else
                cp_commit();
        }

        uint32_t tA  = sb0 + (c % NST) * STAGE;
        uint32_t tAl = tA + 16384;
        uint32_t tB  = tA + ABYTES;
        uint32_t tBl = tB + NBT * 16384;

        #pragma unroll
        for (int ks = 0; ks < 4; ks++) {
            #pragma unroll
            for (int ms = 0; ms < 2; ms++) {
                uint32_t off = SW128((arow + ms * 16) * 128 + ks * 32 + acb);
                ldsm_x4(ahf[ms], tA + off);
                if constexpr (TERMS == 3) ldsm_x4(alf[ms], tAl + off);
            }
            #pragma unroll
            for (int ng4 = 0; ng4 < NG4; ng4++) {
                uint32_t off = SW128((brow4 + ng4 * 16) * 128 + ks * 32 + bcb4);
                ldsm_x4(bhf[ng4], tB + off);
                if constexpr (TERMS == 3) ldsm_x4(blf[ng4], tBl + off);
            }
            #pragma unroll
            for (int ng4 = 0; ng4 < NG4; ng4++)
                #pragma unroll
                for (int ms = 0; ms < 2; ms++) {
                    mma_f16(acc[ms][2*ng4],   ahf[ms], bhf[ng4]);
                    mma_f16(acc[ms][2*ng4+1], ahf[ms], bhf[ng4] + 2);
                    if constexpr (TERMS == 3) {
                        mma_f16(acc[ms][2*ng4],   ahf[ms], blf[ng4]);
                        mma_f16(acc[ms][2*ng4+1], ahf[ms], blf[ng4] + 2);
                        mma_f16(acc[ms][2*ng4],   alf[ms], bhf[ng4]);
                        mma_f16(acc[ms][2*ng4+1], alf[ms], bhf[ng4] + 2);
                    }
                }
        }
    }

    const int gid = lane >> 2, tc = lane & 3;
    if constexpr (HOUT == 2) {
        __half* C = (__half*)Cv + zo;
        #pragma unroll
        for (int ms = 0; ms < 2; ms++)
            #pragma unroll
            for (int ns = 0; ns < NS; ns++) {
                int gr0 = bm + wm + ms * 16 + gid;
                int gc  = bn + wn + ns * 8 + tc * 2;
                float g0 = acc[ms][ns][0], u0 = acc[ms][ns][1];
                float g1 = acc[ms][ns][2], u1 = acc[ms][ns][3];
                float r0 = g0 / (1.f + __expf(-g0)) * u0;
                float r1 = g1 / (1.f + __expf(-g1)) * u1;
                C[(size_t)gr0 * ldc + (gc >> 1)]       = __float2half_rn(r0);
                C[(size_t)(gr0 + 8) * ldc + (gc >> 1)] = __float2half_rn(r1);
            }
    } else if constexpr (HOUT == 1) {
        __half* C = (__half*)Cv + zo;
        #pragma unroll
        for (int ms = 0; ms < 2; ms++)
            #pragma unroll
            for (int ns = 0; ns < NS; ns++) {
                int gr0 = bm + wm + ms * 16 + gid;
                int gc  = bn + wn + ns * 8 + tc * 2;
                if (gc < N) {
                    *(__half2*)&C[(size_t)gr0 * ldc + gc] =
                        __floats2half2_rn(alpha * acc[ms][ns][0], alpha * acc[ms][ns][1]);
                    *(__half2*)&C[(size_t)(gr0 + 8) * ldc + gc] =
                        __floats2half2_rn(alpha * acc[ms][ns][2], alpha * acc[ms][ns][3]);
                }
            }
    } else {
        float* C = (float*)Cv + zo;
        #pragma unroll
        for (int ms = 0; ms < 2; ms++)
            #pragma unroll
            for (int ns = 0; ns < NS; ns++) {
                int gr0 = bm + wm + ms * 16 + gid;
                int gc  = bn + wn + ns * 8 + tc * 2;
                if (gc < N) {
                    float2 v0;
                    v0.x = alpha * acc[ms][ns][0];
                    v0.y = alpha * acc[ms][ns][1];
                    if (R) { v0.x += R[(size_t)gr0 * ldr + gc]; v0.y += R[(size_t)gr0 * ldr + gc + 1]; }
                    *(float2*)&C[(size_t)gr0 * ldc + gc] = v0;
                    int gr1 = gr0 + 8;
                    float2 v1;
                    v1.x = alpha * acc[ms][ns][2];
                    v1.y = alpha * acc[ms][ns][3];
                    if (R) { v1.x += R[(size_t)gr1 * ldr + gc]; v1.y += R[(size_t)gr1 * ldr + gc + 1]; }
                    *(float2*)&C[(size_t)gr1 * ldc + gc] = v1;
                }
            }
    }
}

#define SM_3_128 (3*(32768+32768))
#define SM_1_256 (4*(16384+32768))
#define SM_1_128 (4*(16384+16384))

// ------------------------------ host launch ---------------------------------
static void gemm3(const __half* Ah, const __half* Al, int lda, long long sA,
                  const __half* Bh, const __half* Bl, int ldb, long long sB,
                  float* C, int ldc, long long sC,
                  const float* R, int ldr, long long sR,
                  int M, int N, int K, float alpha, int Z, int causal = 0)
{
    dim3 grid((N + 127) / 128, M / 128, Z);
    gemm_h<3,128,0><<<grid, 512, SM_3_128>>>(Ah, Al, lda, sA, Bh, Bl, ldb, sB,
                                             C, ldc, sC, 1, 0, R, ldr, sR, M, N, K, alpha, causal);
}
static void gemm1f(const __half* A, int lda, long long sA,
                   const __half* B, int ldb, long long sB,
                   float* C, int ldc, long long sC,
                   const float* R, int ldr, long long sR,
                   int M, int N, int K, float alpha, int Z, int causal = 0)
{
    if (N % 256 == 0) {
        dim3 grid(N / 256, M / 128, Z);
        gemm_h<1,256,0><<<grid, 512, SM_1_256>>>(A, nullptr, lda, sA, B, nullptr, ldb, sB,
                                                 C, ldc, sC, 1, 0, R, ldr, sR, M, N, K, alpha, causal);
    } else {
        dim3 grid((N + 127) / 128, M / 128, Z);
        gemm_h<1,128,0><<<grid, 512, SM_1_128>>>(A, nullptr, lda, sA, B, nullptr, ldb, sB,
                                                 C, ldc, sC, 1, 0, R, ldr, sR, M, N, K, alpha, causal);
    }
}

static void splitp_s(cudaStream_t st, const float* in, __half* hi, __half* lo, long long n)
{
    long long n4 = n >> 2;
    split_h_k<<<(unsigned)((n4 + 255) / 256), 256, 0, st>>>(
        (const float4*)in, (__half2*)hi, (__half2*)lo, n4);
}

extern "C" void kernel_launch(void* const* d_in, const int* in_sizes, int n_in,
                              void* d_out, int out_size)
{
    const float* x     = (const float*)d_in[0];
    const float* mask  = (const float*)d_in[1];
    const float* fcos  = (const float*)d_in[2];
    const float* fsin  = (const float*)d_in[3];
    const float* anw   = (const float*)d_in[4];
    const float* wq_a  = (const float*)d_in[5];
    const float* qnw   = (const float*)d_in[6];
    const float* wq_b  = (const float*)d_in[7];
    const float* wkv_a = (const float*)d_in[8];
    const float* kvnw  = (const float*)d_in[9];
    const float* wkv_b = (const float*)d_in[10];
    const float* wo    = (const float*)d_in[11];
    const float* fnw   = (const float*)d_in[12];
    const float* w1    = (const float*)d_in[13];
    const float* w2    = (const float*)d_in[14];
    const float* w3    = (const float*)d_in[15];
    float* out = (float*)d_out;

    cudaFuncSetAttribute(gemm_h<3,128,0>, cudaFuncAttributeMaxDynamicSharedMemorySize, SM_3_128);
    cudaFuncSetAttribute(gemm_h<1,256,0>, cudaFuncAttributeMaxDynamicSharedMemorySize, SM_1_256);
    cudaFuncSetAttribute(gemm_h<1,128,0>, cudaFuncAttributeMaxDynamicSharedMemorySize, SM_1_128);
    cudaFuncSetAttribute(gemm_h<1,128,1>, cudaFuncAttributeMaxDynamicSharedMemorySize, SM_1_128);
    cudaFuncSetAttribute(gemm_h<1,256,2>, cudaFuncAttributeMaxDynamicSharedMemorySize, SM_1_256);

    float *p_qkva, *p_q, *p_kv, *p_sc, *p_x2;
    cudaGetSymbolAddress((void**)&p_qkva, g_qkva);
    cudaGetSymbolAddress((void**)&p_q,    g_q);
    cudaGetSymbolAddress((void**)&p_kv,   g_kv);
    cudaGetSymbolAddress((void**)&p_sc,   g_sc);
    cudaGetSymbolAddress((void**)&p_x2,   g_x2);

    __half *hH,*hL,*qaH,*qaL,*kvnH,*kvnL,*qfH,*qfL,*kfH,*kfL,*vT,*at,*y2,*h2,*gs,
           *wqkaH,*wqkaL,*wqbH,*wqbL,*wkbH,*wkbL,*woh,*w13h,*w2h;
    cudaGetSymbolAddress((void**)&hH,   f_hH);  cudaGetSymbolAddress((void**)&hL,   f_hL);
    cudaGetSymbolAddress((void**)&qaH,  f_qaH); cudaGetSymbolAddress((void**)&qaL,  f_qaL);
    cudaGetSymbolAddress((void**)&kvnH, f_kvnH);cudaGetSymbolAddress((void**)&kvnL, f_kvnL);
    cudaGetSymbolAddress((void**)&qfH,  f_qfH); cudaGetSymbolAddress((void**)&qfL,  f_qfL);
    cudaGetSymbolAddress((void**)&kfH,  f_kfH); cudaGetSymbolAddress((void**)&kfL,  f_kfL);
    cudaGetSymbolAddress((void**)&vT,   f_vT);  cudaGetSymbolAddress((void**)&at,   f_at);
    cudaGetSymbolAddress((void**)&y2,   f_y2);
    cudaGetSymbolAddress((void**)&h2,   f_h2);  cudaGetSymbolAddress((void**)&gs,   f_gs);
    cudaGetSymbolAddress((void**)&wqkaH,f_wqkaH);cudaGetSymbolAddress((void**)&wqkaL,f_wqkaL);
    cudaGetSymbolAddress((void**)&wqbH, f_wqbH);cudaGetSymbolAddress((void**)&wqbL, f_wqbL);
    cudaGetSymbolAddress((void**)&wkbH, f_wkbH);cudaGetSymbolAddress((void**)&wkbL, f_wkbL);
    cudaGetSymbolAddress((void**)&woh,  f_wo);
    cudaGetSymbolAddress((void**)&w13h, f_w13); cudaGetSymbolAddress((void**)&w2h,  f_w2);

    // ---- forked stream for weight conversions (capture-legal fork/join) ----
    cudaStream_t s1;
    cudaStreamCreateWithFlags(&s1, cudaStreamNonBlocking);
    cudaEvent_t evFork, evQKA, evQB, evKB, evConv;
    cudaEventCreateWithFlags(&evFork, cudaEventDisableTiming);
    cudaEventCreateWithFlags(&evQKA,  cudaEventDisableTiming);
    cudaEventCreateWithFlags(&evQB,   cudaEventDisableTiming);
    cudaEventCreateWithFlags(&evKB,   cudaEventDisableTiming);
    cudaEventCreateWithFlags(&evConv, cudaEventDisableTiming);

    cudaEventRecord(evFork, 0);
    cudaStreamWaitEvent(s1, evFork, 0);

    // s1: all weight conversions, ordered by when main needs them
    splitp_s(s1, wq_a,  wqkaH, wqkaL, (long long)CQLORA*CD);
    splitp_s(s1, wkv_a, wqkaH + (long long)CQLORA*CD, wqkaL + (long long)CQLORA*CD,
             (long long)(CKVLORA+CROPE)*CD);
    cudaEventRecord(evQKA, s1);
    splitp_s(s1, wq_b, wqbH, wqbL, (long long)CH*CQKD*CQLORA);
    cudaEventRecord(evQB, s1);
    splitp_s(s1, wkv_b, wkbH, wkbL, (long long)CH*256*CKVLORA);
    cudaEventRecord(evKB, s1);
    {
        long long n4big = ((long long)CINTER * CD) >> 2;
        long long n4wo  = ((long long)CD * CD) >> 2;
        dim3 grid((unsigned)((n4big + 255) / 256), 4);
        conv4_h_k<<<grid, 256, 0, s1>>>((const float4*)w1, (const float4*)w3,
                                        (const float4*)w2, (const float4*)wo,
                                        (__half2*)w13h, (__half2*)w2h, (__half2*)woh,
                                        n4big, n4wo);
    }
    cudaEventRecord(evConv, s1);

    // ---- main stream: attention path ----
    rmsnorm_split_h_k<<<CM, 256>>>(x, CD, anw, hH, hL, CD);
    cudaStreamWaitEvent(0, evQKA, 0);
    // qkva = h @ [wq_a; wkv_a]^T
    gemm3(hH, hL, CD, 0, wqkaH, wqkaL, CD, 0, p_qkva, NQKVA, 0,
          nullptr, 0, 0, CM, NQKVA, CD, 1.f, 1);
    rmsnorm_split_h_k<<<CM, 256>>>(p_qkva, NQKVA, qnw, qaH, qaL, CQLORA);
    cudaStreamWaitEvent(0, evQB, 0);
    // q = qa_norm @ wq_b^T
    gemm3(qaH, qaL, CQLORA, 0, wqbH, wqbL, CQLORA, 0, p_q, CH*CQKD, 0,
          nullptr, 0, 0, CM, CH*CQKD, CQLORA, 1.f, 1);
    rmsnorm_split_h_k<<<CM, 256>>>(p_qkva + CQLORA, NQKVA, kvnw, kvnH, kvnL, CKVLORA);
    cudaStreamWaitEvent(0, evKB, 0);
    // kv = kv_norm @ wkv_b^T
    gemm3(kvnH, kvnL, CKVLORA, 0, wkbH, wkbL, CKVLORA, 0, p_kv, CH*256, 0,
          nullptr, 0, 0, CM, CH*256, CKVLORA, 1.f, 1);
    rope_pack_h_k<<<dim3(CT, CB), 256>>>(p_q, p_kv, p_qkva, fcos, fsin,
                                         qfH, qfL, kfH, kfL, vT);
    // scores = -96 * qf @ kf^T + mask (masked tiles skipped; softmax fills zeros)
    gemm3(qfH, qfL, CQKD, (long long)CT*CQKD,
          kfH, kfL, CQKD, (long long)CT*CQKD,
          p_sc, CT, (long long)CT*CT,
          mask, CT, 0, CT, CT, CQKD, -96.f, CB*CH, 1);
    softmax_causal_h_k<<<CB*CH*CT, 256>>>(p_sc, at);
    // y2 = attn @ vT with fused [B,H,T,d] -> [B*T, H*d] permute in epilogue
    {
        dim3 grid(1, CT / 128, CB*CH);
        gemm_h<1,128,1><<<grid, 512, SM_1_128>>>(
            at, nullptr, CT, (long long)CT*CT,
            vT, nullptr, CT, (long long)CVHD*CT,
            y2, CD, (long long)CT*CD, CH, (long long)CVHD,
            nullptr, 0, 0, CT, CVHD, CT, 1.f, 2);
    }
    // join conversion stream before first consumer of woh/w13h/w2h
    cudaStreamWaitEvent(0, evConv, 0);
    // x2 = x + y2 @ wo^T
    gemm1f(y2, CH*CVHD, 0, woh, CH*CVHD, 0, p_x2, CD, 0,
           x, CD, 0, CM, CD, CH*CVHD, 1.f, 1);

    // ---- FFN path ----
    rmsnorm_h_k<<<CM, 256>>>(p_x2, CD, fnw, h2, CD);
    // gs = silu(h2@w1^T) * (h2@w3^T) in ONE GEMM (w13 interleaved, fused epilogue)
    {
        dim3 grid((2*CINTER) / 256, CM / 128, 1);
        gemm_h<1,256,2><<<grid, 512, SM_1_256>>>(
            h2, nullptr, CD, 0,
            w13h, nullptr, CD, 0,
            gs, CINTER, 0, 1, 0,
            nullptr, 0, 0, CM, 2*CINTER, CD, 1.f, 0);
    }
    // out = x2 + gs @ w2^T
    gemm1f(gs, CINTER, 0, w2h, CINTER, 0, out, CD, 0,
           p_x2, CD, 0, CM, CD, CINTER, 1.f, 1);
}